// round 7
// baseline (speedup 1.0000x reference)
#include <cuda_runtime.h>
#include <cuda_bf16.h>
#include <math.h>
#include <stdint.h>

#define DIMV 1024
#define NHEADS 16
#define DK 64
#define RFF 128
#define FEAT 256
#define BATCH 2
#define SEQ 8192
#define MROWS 16384
#define BH 32
#define NPAD 96
#define INV_SQRT_R 0.08838834764831845f

typedef __nv_bfloat16 bf16;
typedef __nv_bfloat162 bf162;

// ---------------- scratch (device globals) ----------------
__device__ int8_t g_xq1[MROWS*DIMV], g_xq2[MROWS*DIMV];
__device__ float  g_sx[MROWS];
__device__ int8_t g_wq1[3*DIMV*DIMV], g_wq2[3*DIMV*DIMV];
__device__ float  g_sw[3*DIMV];
__device__ int8_t g_pq1[DIMV*DIMV], g_pq2[DIMV*DIMV];
__device__ float  g_sp[DIMV];
__device__ bf16 g_qh[MROWS*DIMV], g_ql[MROWS*DIMV];
__device__ bf16 g_kh[MROWS*DIMV], g_kl[MROWS*DIMV];
__device__ bf16 g_vth[BH*NPAD*SEQ], g_vtl[BH*NPAD*SEQ];
__device__ bf16 g_wrth[NHEADS*RFF*DK], g_wrtl[NHEADS*RFF*DK];
__device__ bf16 g_qfh[(size_t)BH*SEQ*FEAT], g_qfl[(size_t)BH*SEQ*FEAT];
__device__ bf16 g_kfh[(size_t)BH*FEAT*SEQ], g_kfl[(size_t)BH*FEAT*SEQ];
__device__ float g_kvp[8*BH*FEAT*NPAD];
__device__ bf16 g_dth[BH*NPAD*FEAT], g_dtl[BH*NPAD*FEAT];
__device__ float g_af[MROWS*DIMV];
__device__ int8_t g_aq1[MROWS*DIMV], g_aq2[MROWS*DIMV];
__device__ float  g_sa[MROWS];

// ---------------- helpers ----------------
__device__ __forceinline__ uint32_t smem_u32(const void* p) {
    uint32_t a;
    asm("{ .reg .u64 t; cvta.to.shared.u64 t, %1; cvt.u32.u64 %0, t; }" : "=r"(a) : "l"(p));
    return a;
}
__device__ __forceinline__ void cpa16(uint32_t s, const void* g) {
    asm volatile("cp.async.cg.shared.global [%0], [%1], 16;" :: "r"(s), "l"(g));
}
__device__ __forceinline__ void cpa_commit() { asm volatile("cp.async.commit_group;"); }
__device__ __forceinline__ void ldmx4(uint32_t addr, uint32_t& r0, uint32_t& r1, uint32_t& r2, uint32_t& r3) {
    asm volatile("ldmatrix.sync.aligned.m8n8.x4.shared.b16 {%0,%1,%2,%3}, [%4];"
                 : "=r"(r0), "=r"(r1), "=r"(r2), "=r"(r3) : "r"(addr));
}
__device__ __forceinline__ void mma16816(float* d, const uint32_t* a, const uint32_t* b) {
    asm volatile(
        "mma.sync.aligned.m16n8k16.row.col.f32.bf16.bf16.f32 "
        "{%0,%1,%2,%3}, {%4,%5,%6,%7}, {%8,%9}, {%0,%1,%2,%3};"
        : "+f"(d[0]), "+f"(d[1]), "+f"(d[2]), "+f"(d[3])
        : "r"(a[0]), "r"(a[1]), "r"(a[2]), "r"(a[3]), "r"(b[0]), "r"(b[1]));
}
__device__ __forceinline__ void imma16832(int* d, const uint32_t* a, const uint32_t* b) {
    asm volatile(
        "mma.sync.aligned.m16n8k32.row.col.s32.s8.s8.s32 "
        "{%0,%1,%2,%3}, {%4,%5,%6,%7}, {%8,%9}, {%0,%1,%2,%3};"
        : "+r"(d[0]), "+r"(d[1]), "+r"(d[2]), "+r"(d[3])
        : "r"(a[0]), "r"(a[1]), "r"(a[2]), "r"(a[3]), "r"(b[0]), "r"(b[1]));
}
__device__ __forceinline__ void bsplit(float v, bf16& h, bf16& l) {
    h = __float2bfloat16(v);
    l = __float2bfloat16(v - __bfloat162float(h));
}
__device__ __forceinline__ bf162 mk2(bf16 a, bf16 b) { bf162 t; t.x = a; t.y = b; return t; }

// ---------------- per-row 2-digit int8 quantization ----------------
__global__ __launch_bounds__(256) void quant_rows(
    const float* __restrict__ in, int8_t* __restrict__ q1,
    int8_t* __restrict__ q2, float* __restrict__ sc, int nrows)
{
    int row = blockIdx.x * 8 + (threadIdx.x >> 5);
    if (row >= nrows) return;
    int lid = threadIdx.x & 31;
    const float4* r = (const float4*)(in + (size_t)row * 1024);
    float4 v[8];
    float mx = 0.f;
    #pragma unroll
    for (int i = 0; i < 8; i++) {
        v[i] = r[lid + 32 * i];
        mx = fmaxf(mx, fmaxf(fmaxf(fabsf(v[i].x), fabsf(v[i].y)),
                             fmaxf(fabsf(v[i].z), fabsf(v[i].w))));
    }
    #pragma unroll
    for (int o = 16; o; o >>= 1) mx = fmaxf(mx, __shfl_xor_sync(0xFFFFFFFFu, mx, o));
    mx = fmaxf(mx, 1e-20f);
    float inv = 127.f / mx;
    if (lid == 0) sc[row] = mx / 127.f;
    char4* o1 = (char4*)(q1 + (size_t)row * 1024);
    char4* o2 = (char4*)(q2 + (size_t)row * 1024);
    #pragma unroll
    for (int i = 0; i < 8; i++) {
        float qv[4] = { v[i].x * inv, v[i].y * inv, v[i].z * inv, v[i].w * inv };
        char c1[4], c2[4];
        #pragma unroll
        for (int j = 0; j < 4; j++) {
            float a1 = rintf(qv[j]);
            float r2 = (qv[j] - a1) * 256.f;
            float a2 = fminf(fmaxf(rintf(r2), -127.f), 127.f);
            c1[j] = (char)a1; c2[j] = (char)a2;
        }
        o1[lid + 32 * i] = make_char4(c1[0], c1[1], c1[2], c1[3]);
        o2[lid + 32 * i] = make_char4(c2[0], c2[1], c2[2], c2[3]);
    }
}

// ---------------- WrT prep ----------------
__global__ __launch_bounds__(256) void prep_wrt(const float* __restrict__ Wr)
{
    int h = blockIdx.x;
    for (int e = threadIdx.x; e < RFF * DK; e += 256) {
        int r = e >> 6, j = e & 63;
        float v = Wr[(size_t)h * DK * RFF + j * RFF + r];
        bf16 hi, lo; bsplit(v, hi, lo);
        g_wrth[h * RFF * DK + e] = hi;
        g_wrtl[h * RFF * DK + e] = lo;
    }
}

// ---------------- vT padding rows ----------------
__global__ __launch_bounds__(256) void fill_vt()
{
    int bx = blockIdx.x;
    int bh = bx >> 5, dr = 64 + (bx & 31);
    bf16 v = __float2bfloat16(dr == 64 ? 1.f : 0.f);
    bf16 z = __float2bfloat16(0.f);
    bf162 vv = mk2(v, v), zz = mk2(z, z);
    size_t base = ((size_t)bh * NPAD + dr) * SEQ;
    for (int i = threadIdx.x; i < SEQ / 2; i += 256) {
        *(bf162*)&g_vth[base + 2 * i] = vv;
        *(bf162*)&g_vtl[base + 2 * i] = zz;
    }
}

// ---------------- int8x2 IMMA GEMM, 512 threads / 16 warps (4 warps per SMSP) ----------------
// 128x128 CTA tile, 16 warps as 4x4 (32x32 warp tiles), BK=64 int8, 2-stage cp.async.
// SMEM stage: A1[128x64] A2 B1 B2 (8KB each, 32KB/stage).
#define ISTG 32768
#define IGEMM_SMEM (2 * ISTG)

template<int MODE>
__global__ __launch_bounds__(512, 1) void gemm_i8(
    const int8_t* __restrict__ A1, const int8_t* __restrict__ A2, const float* __restrict__ sA,
    const int8_t* __restrict__ B1, const int8_t* __restrict__ B2, const float* __restrict__ sB,
    const float* __restrict__ bias, float* __restrict__ C)
{
    extern __shared__ __align__(128) char sm[];
    const int tid = threadIdx.x, wid = tid >> 5, lid = tid & 31;
    const int m0 = blockIdx.y * 128, n0 = blockIdx.x * 128;
    const int wm = (wid & 3) * 32;      // 4 m-positions
    const int wn = (wid >> 2) * 32;     // 4 n-positions
    const uint32_t smb = smem_u32(sm);

    int X[2][4][4], Y[2][4][4];
    #pragma unroll
    for (int i = 0; i < 2; i++)
        #pragma unroll
        for (int j = 0; j < 4; j++)
            #pragma unroll
            for (int e = 0; e < 4; e++) { X[i][j][e] = 0; Y[i][j][e] = 0; }

    auto load_stage = [&](int ci, int s) {
        const int k0 = ci * 64;
        const uint32_t sb = smb + s * ISTG;
        int row = tid >> 2, q = tid & 3;     // 512 threads: rows 0..127, q 0..3
        uint32_t soff = row * 64 + ((q ^ ((row >> 1) & 3)) << 4);
        size_t ga = (size_t)(m0 + row) * DIMV + k0 + q * 16;
        size_t gb = (size_t)(n0 + row) * DIMV + k0 + q * 16;
        cpa16(sb + soff,         A1 + ga);
        cpa16(sb + 8192  + soff, A2 + ga);
        cpa16(sb + 16384 + soff, B1 + gb);
        cpa16(sb + 24576 + soff, B2 + gb);
        cpa_commit();
    };

    load_stage(0, 0);

    #pragma unroll 1
    for (int ci = 0; ci < 16; ci++) {
        const int s = ci & 1;
        if (ci < 15) { load_stage(ci + 1, s ^ 1); asm volatile("cp.async.wait_group 1;"); }
        else         asm volatile("cp.async.wait_group 0;");
        __syncthreads();

        const uint32_t sb = smb + s * ISTG;
        #pragma unroll
        for (int ks = 0; ks < 2; ks++) {
            uint32_t a1f[2][4], a2f[2][4], b1f[4][2], b2f[4][2];
            #pragma unroll
            for (int mi = 0; mi < 2; mi++) {
                int row = wm + mi * 16 + (lid & 7) + ((lid >> 3) & 1) * 8;
                int q = ks * 2 + (lid >> 4);
                uint32_t off = row * 64 + ((q ^ ((row >> 1) & 3)) << 4);
                ldmx4(sb + off,        a1f[mi][0], a1f[mi][1], a1f[mi][2], a1f[mi][3]);
                ldmx4(sb + 8192 + off, a2f[mi][0], a2f[mi][1], a2f[mi][2], a2f[mi][3]);
            }
            #pragma unroll
            for (int np = 0; np < 2; np++) {
                int row = wn + np * 16 + (lid >> 4) * 8 + (lid & 7);
                int q = ks * 2 + ((lid >> 3) & 1);
                uint32_t off = row * 64 + ((q ^ ((row >> 1) & 3)) << 4);
                ldmx4(sb + 16384 + off, b1f[2*np][0], b1f[2*np][1], b1f[2*np+1][0], b1f[2*np+1][1]);
                ldmx4(sb + 24576 + off, b2f[2*np][0], b2f[2*np][1], b2f[2*np+1][0], b2f[2*np+1][1]);
            }
            #pragma unroll
            for (int mi = 0; mi < 2; mi++)
                #pragma unroll
                for (int ni = 0; ni < 4; ni++)
                    imma16832(X[mi][ni], a1f[mi], b1f[ni]);
            #pragma unroll
            for (int mi = 0; mi < 2; mi++)
                #pragma unroll
                for (int ni = 0; ni < 4; ni++)
                    imma16832(Y[mi][ni], a1f[mi], b2f[ni]);
            #pragma unroll
            for (int mi = 0; mi < 2; mi++)
                #pragma unroll
                for (int ni = 0; ni < 4; ni++)
                    imma16832(Y[mi][ni], a2f[mi], b1f[ni]);
        }
        __syncthreads();
    }

    const int g = lid >> 2, c2 = (lid & 3) * 2;
    #pragma unroll
    for (int mi = 0; mi < 2; mi++) {
        int row = m0 + wm + mi * 16 + g;
        float sa0 = sA[row], sa1 = sA[row + 8];
        #pragma unroll
        for (int ni = 0; ni < 4; ni++) {
            int col = n0 + wn + ni * 8 + c2;
            float sb0 = sB[col], sb1 = sB[col + 1];
            float r00 = sa0 * sb0 * ((float)X[mi][ni][0] + (float)Y[mi][ni][0] * (1.f/256.f));
            float r01 = sa0 * sb1 * ((float)X[mi][ni][1] + (float)Y[mi][ni][1] * (1.f/256.f));
            float r10 = sa1 * sb0 * ((float)X[mi][ni][2] + (float)Y[mi][ni][2] * (1.f/256.f));
            float r11 = sa1 * sb1 * ((float)X[mi][ni][3] + (float)Y[mi][ni][3] * (1.f/256.f));
            if (MODE == 0) {
                float b0 = bias ? bias[col] : 0.f;
                float b1 = bias ? bias[col + 1] : 0.f;
                float2 o0 = { r00 + b0, r01 + b1 };
                float2 o1 = { r10 + b0, r11 + b1 };
                *(float2*)&C[(size_t)row * DIMV + col]       = o0;
                *(float2*)&C[(size_t)(row + 8) * DIMV + col] = o1;
            } else {
                if (col < 2048) {
                    bf16* Ch = (col < 1024) ? g_qh : g_kh;
                    bf16* Cl = (col < 1024) ? g_ql : g_kl;
                    int cc = col & 1023;
                    bf16 h0, l0, h1, l1;
                    bsplit(r00, h0, l0); bsplit(r01, h1, l1);
                    *(bf162*)&Ch[(size_t)row * DIMV + cc] = mk2(h0, h1);
                    *(bf162*)&Cl[(size_t)row * DIMV + cc] = mk2(l0, l1);
                    bsplit(r10, h0, l0); bsplit(r11, h1, l1);
                    *(bf162*)&Ch[(size_t)(row + 8) * DIMV + cc] = mk2(h0, h1);
                    *(bf162*)&Cl[(size_t)(row + 8) * DIMV + cc] = mk2(l0, l1);
                } else {
                    int cc = col - 2048;
                    int hh = cc >> 6, d0 = cc & 63;
                    int b = row >> 13, n = row & 8191;
                    size_t base = ((size_t)(b * NHEADS + hh) * NPAD) * SEQ;
                    bf16 h0, l0;
                    bsplit(r00, h0, l0);
                    g_vth[base + (size_t)d0 * SEQ + n] = h0;       g_vtl[base + (size_t)d0 * SEQ + n] = l0;
                    bsplit(r01, h0, l0);
                    g_vth[base + (size_t)(d0+1) * SEQ + n] = h0;   g_vtl[base + (size_t)(d0+1) * SEQ + n] = l0;
                    bsplit(r10, h0, l0);
                    g_vth[base + (size_t)d0 * SEQ + n + 8] = h0;   g_vtl[base + (size_t)d0 * SEQ + n + 8] = l0;
                    bsplit(r11, h0, l0);
                    g_vth[base + (size_t)(d0+1) * SEQ + n + 8] = h0; g_vtl[base + (size_t)(d0+1) * SEQ + n + 8] = l0;
                }
            }
        }
    }
}

// ---------------- proj + RFF features ----------------
#define PROJ_SMEM 65536

__global__ __launch_bounds__(256, 1) void proj_feat(const float* __restrict__ brp)
{
    extern __shared__ __align__(128) char sm[];
    const int tid = threadIdx.x, wid = tid >> 5, lid = tid & 31;
    const int m0 = blockIdx.x * 128;
    const int qk = blockIdx.y >> 4, h = blockIdx.y & 15;
    const int wm = (wid & 1) * 64, wn = (wid >> 1) * 32;
    const uint32_t smb = smem_u32(sm);

    const bf16* Ah = (qk ? g_kh : g_qh);
    const bf16* Al = (qk ? g_kl : g_ql);
    const bf16* Bh = g_wrth + h * RFF * DK;
    const bf16* Bl = g_wrtl + h * RFF * DK;

    #pragma unroll
    for (int it = 0; it < 4; it++) {
        int idx = tid + it * 256;
        int row = idx >> 3, q = idx & 7;
        uint32_t soff = row * 128 + ((q ^ (row & 7)) << 4);
        *(uint4*)(sm + soff)         = *(const uint4*)(Ah + (size_t)(m0 + row) * DIMV + h * DK + q * 8);
        *(uint4*)(sm + 16384 + soff) = *(const uint4*)(Al + (size_t)(m0 + row) * DIMV + h * DK + q * 8);
        *(uint4*)(sm + 32768 + soff) = *(const uint4*)(Bh + row * DK + q * 8);
        *(uint4*)(sm + 49152 + soff) = *(const uint4*)(Bl + row * DK + q * 8);
    }
    __syncthreads();

    float acc[4][4][4];
    #pragma unroll
    for (int i = 0; i < 4; i++)
        #pragma unroll
        for (int j = 0; j < 4; j++)
            #pragma unroll
            for (int e = 0; e < 4; e++) acc[i][j][e] = 0.f;

    #pragma unroll
    for (int ks = 0; ks < 4; ks++) {
        uint32_t aH[4][4], aL[4][4], bH[4][2], bL[4][2];
        #pragma unroll
        for (int mi = 0; mi < 4; mi++) {
            int row = wm + mi * 16 + (lid & 7) + ((lid >> 3) & 1) * 8;
            int q = ks * 2 + (lid >> 4);
            uint32_t off = row * 128 + ((q ^ (row & 7)) << 4);
            ldmx4(smb + off,         aH[mi][0], aH[mi][1], aH[mi][2], aH[mi][3]);
            ldmx4(smb + 16384 + off, aL[mi][0], aL[mi][1], aL[mi][2], aL[mi][3]);
        }
        #pragma unroll
        for (int np = 0; np < 2; np++) {
            int row = wn + np * 16 + (lid >> 4) * 8 + (lid & 7);
            int q = ks * 2 + ((lid >> 3) & 1);
            uint32_t off = row * 128 + ((q ^ (row & 7)) << 4);
            ldmx4(smb + 32768 + off, bH[2*np][0], bH[2*np][1], bH[2*np+1][0], bH[2*np+1][1]);
            ldmx4(smb + 49152 + off, bL[2*np][0], bL[2*np][1], bL[2*np+1][0], bL[2*np+1][1]);
        }
        #pragma unroll
        for (int mi = 0; mi < 4; mi++)
            #pragma unroll
            for (int ni = 0; ni < 4; ni++)
                mma16816(acc[mi][ni], aH[mi], bH[ni]);
        #pragma unroll
        for (int mi = 0; mi < 4; mi++)
            #pragma unroll
            for (int ni = 0; ni < 4; ni++)
                mma16816(acc[mi][ni], aH[mi], bL[ni]);
        #pragma unroll
        for (int mi = 0; mi < 4; mi++)
            #pragma unroll
            for (int ni = 0; ni < 4; ni++)
                mma16816(acc[mi][ni], aL[mi], bH[ni]);
    }

    const int g = lid >> 2, c2 = (lid & 3) * 2;
    #pragma unroll
    for (int mi = 0; mi < 4; mi++) {
        #pragma unroll
        for (int ni = 0; ni < 4; ni++) {
            int col = wn + ni * 8 + c2;
            float b0 = brp[h * RFF + col], b1 = brp[h * RFF + col + 1];
            #pragma unroll
            for (int half = 0; half < 2; half++) {
                int row = m0 + wm + mi * 16 + g + half * 8;
                int b = row >> 13, n = row & 8191;
                int bh = b * NHEADS + h;
                float p0 = acc[mi][ni][half * 2 + 0] + b0;
                float p1 = acc[mi][ni][half * 2 + 1] + b1;
                float s0, c0, s1, c1;
                __sincosf(p0, &s0, &c0);
                __sincosf(p1, &s1, &c1);
                c0 *= INV_SQRT_R; s0 *= INV_SQRT_R;
                c1 *= INV_SQRT_R; s1 *= INV_SQRT_R;
                bf16 ch0, cl0, ch1, cl1, sh0, sl0, sh1, sl1;
                bsplit(c0, ch0, cl0); bsplit(c1, ch1, cl1);
                bsplit(s0, sh0, sl0); bsplit(s1, sh1, sl1);
                if (qk == 0) {
                    size_t base = ((size_t)bh * SEQ + n) * FEAT;
                    *(bf162*)&g_qfh[base + col]       = mk2(ch0, ch1);
                    *(bf162*)&g_qfl[base + col]       = mk2(cl0, cl1);
                    *(bf162*)&g_qfh[base + RFF + col] = mk2(sh0, sh1);
                    *(bf162*)&g_qfl[base + RFF + col] = mk2(sl0, sl1);
                } else {
                    size_t kb = ((size_t)bh * FEAT + col) * SEQ + n;
                    g_kfh[kb] = ch0;              g_kfl[kb] = cl0;
                    g_kfh[kb + SEQ] = ch1;        g_kfl[kb + SEQ] = cl1;
                    g_kfh[kb + (size_t)RFF*SEQ] = sh0;        g_kfl[kb + (size_t)RFF*SEQ] = sl0;
                    g_kfh[kb + (size_t)(RFF+1)*SEQ] = sh1;    g_kfl[kb + (size_t)(RFF+1)*SEQ] = sl1;
                }
            }
        }
    }
}

// ---------------- Kv GEMM (split-K) ----------------
#define KV_STG 28672
#define KV_SMEM (2 * KV_STG)

__global__ __launch_bounds__(256, 1) void gemm_kv()
{
    extern __shared__ __align__(128) char sm[];
    const int tid = threadIdx.x, wid = tid >> 5, lid = tid & 31;
    const int ks = blockIdx.x;
    const int bh = blockIdx.y >> 1, m2 = blockIdx.y & 1;
    const int wm = (wid & 3) * 32, wn = (wid >> 2) * 48;
    const uint32_t smb = smem_u32(sm);

    const bf16* Ah = g_kfh + ((size_t)bh * FEAT + m2 * 128) * SEQ + ks * 1024;
    const bf16* Al = g_kfl + ((size_t)bh * FEAT + m2 * 128) * SEQ + ks * 1024;
    const bf16* Bhp = g_vth + (size_t)bh * NPAD * SEQ + ks * 1024;
    const bf16* Blp = g_vtl + (size_t)bh * NPAD * SEQ + ks * 1024;

    float acc[2][6][4];
    #pragma unroll
    for (int i = 0; i < 2; i++)
        #pragma unroll
        for (int j = 0; j < 6; j++)
            #pragma unroll
            for (int e = 0; e < 4; e++) acc[i][j][e] = 0.f;

    auto load_stage = [&](int ci, int s) {
        const int k0 = ci * 32;
        const uint32_t sb = smb + s * KV_STG;
        #pragma unroll
        for (int it = 0; it < 2; it++) {
            int idx = tid + it * 256;
            int row = idx >> 2, q = idx & 3;
            uint32_t soff = row * 64 + ((q ^ ((row >> 1) & 3)) << 4);
            cpa16(sb + soff,        Ah + (size_t)row * SEQ + k0 + q * 8);
            cpa16(sb + 8192 + soff, Al + (size_t)row * SEQ + k0 + q * 8);
        }
        for (int idx = tid; idx < 384; idx += 256) {
            int row = idx >> 2, q = idx & 3;
            uint32_t soff = row * 64 + ((q ^ ((row >> 1) & 3)) << 4);
            cpa16(sb + 16384 + soff, Bhp + (size_t)row * SEQ + k0 + q * 8);
            cpa16(sb + 22528 + soff, Blp + (size_t)row * SEQ + k0 + q * 8);
        }
        cpa_commit();
    };

    load_stage(0, 0);
    #pragma unroll 1
    for (int ci = 0; ci < 32; ci++) {
        const int s = ci & 1;
        if (ci < 31) { load_stage(ci + 1, s ^ 1); asm volatile("cp.async.wait_group 1;"); }
        else         asm volatile("cp.async.wait_group 0;");
        __syncthreads();
        const uint32_t sb = smb + s * KV_STG;
        #pragma unroll
        for (int k2 = 0; k2 < 2; k2++) {
            uint32_t aH[2][4], aL[2][4], bH[6][2], bL[6][2];
            #pragma unroll
            for (int mi = 0; mi < 2; mi++) {
                int row = wm + mi * 16 + (lid & 7) + ((lid >> 3) & 1) * 8;
                int q = k2 * 2 + (lid >> 4);
                uint32_t off = row * 64 + ((q ^ ((row >> 1) & 3)) << 4);
                ldmx4(sb + off,        aH[mi][0], aH[mi][1], aH[mi][2], aH[mi][3]);
                ldmx4(sb + 8192 + off, aL[mi][0], aL[mi][1], aL[mi][2], aL[mi][3]);
            }
            #pragma unroll
            for (int np = 0; np < 3; np++) {
                int row = wn + np * 16 + (lid >> 4) * 8 + (lid & 7);
                int q = k2 * 2 + ((lid >> 3) & 1);
                uint32_t off = row * 64 + ((q ^ ((row >> 1) & 3)) << 4);
                ldmx4(sb + 16384 + off, bH[2*np][0], bH[2*np][1], bH[2*np+1][0], bH[2*np+1][1]);
                ldmx4(sb + 22528 + off, bL[2*np][0], bL[2*np][1], bL[2*np+1][0], bL[2*np+1][1]);
            }
            #pragma unroll
            for (int mi = 0; mi < 2; mi++)
                #pragma unroll
                for (int ni = 0; ni < 6; ni++)
                    mma16816(acc[mi][ni], aH[mi], bH[ni]);
            #pragma unroll
            for (int mi = 0; mi < 2; mi++)
                #pragma unroll
                for (int ni = 0; ni < 6; ni++)
                    mma16816(acc[mi][ni], aH[mi], bL[ni]);
            #pragma unroll
            for (int mi = 0; mi < 2; mi++)
                #pragma unroll
                for (int ni = 0; ni < 6; ni++)
                    mma16816(acc[mi][ni], aL[mi], bH[ni]);
        }
        __syncthreads();
    }

    const int g = lid >> 2, c2 = (lid & 3) * 2;
    #pragma unroll
    for (int mi = 0; mi < 2; mi++) {
        #pragma unroll
        for (int ni = 0; ni < 6; ni++) {
            int rl = wm + mi * 16 + g;
            int col = wn + ni * 8 + c2;
            float* dp = g_kvp + (((size_t)ks * BH + bh) * FEAT + m2 * 128 + rl) * NPAD + col;
            float2 o0 = { acc[mi][ni][0], acc[mi][ni][1] };
            float2 o1 = { acc[mi][ni][2], acc[mi][ni][3] };
            *(float2*)dp = o0;
            *(float2*)(dp + 8 * NPAD) = o1;
        }
    }
}

// ---------------- reduce partials + transpose + split ----------------
__global__ __launch_bounds__(256) void kv_reduce_t()
{
    int i = blockIdx.x * 256 + threadIdx.x;
    if (i >= BH * FEAT * NPAD) return;
    int bh = i / (FEAT * NPAD);
    int rem = i - bh * FEAT * NPAD;
    int f = rem / NPAD, d = rem - f * NPAD;
    float s = 0.f;
    #pragma unroll
    for (int ks = 0; ks < 8; ks++)
        s += g_kvp[(((size_t)ks * BH + bh) * FEAT + f) * NPAD + d];
    bf16 hi, lo; bsplit(s, hi, lo);
    g_dth[((size_t)bh * NPAD + d) * FEAT + f] = hi;
    g_dtl[((size_t)bh * NPAD + d) * FEAT + f] = lo;
}

// ---------------- out GEMM ----------------
#define OUT_SMEM (2 * KV_STG + 512)

__global__ __launch_bounds__(256, 1) void gemm_out()
{
    extern __shared__ __align__(128) char sm[];
    const int tid = threadIdx.x, wid = tid >> 5, lid = tid & 31;
    const int n0 = blockIdx.x * 128;
    const int bh = blockIdx.y;
    const int wm = (wid & 3) * 32, wn = (wid >> 2) * 48;
    const uint32_t smb = smem_u32(sm);
    float* sden = (float*)(sm + 2 * KV_STG);

    const bf16* Ah = g_qfh + ((size_t)bh * SEQ + n0) * FEAT;
    const bf16* Al = g_qfl + ((size_t)bh * SEQ + n0) * FEAT;
    const bf16* Bhp = g_dth + (size_t)bh * NPAD * FEAT;
    const bf16* Blp = g_dtl + (size_t)bh * NPAD * FEAT;

    float acc[2][6][4];
    #pragma unroll
    for (int i = 0; i < 2; i++)
        #pragma unroll
        for (int j = 0; j < 6; j++)
            #pragma unroll
            for (int e = 0; e < 4; e++) acc[i][j][e] = 0.f;

    auto load_stage = [&](int ci, int s) {
        const int k0 = ci * 32;
        const uint32_t sb = smb + s * KV_STG;
        #pragma unroll
        for (int it = 0; it < 2; it++) {
            int idx = tid + it * 256;
            int row = idx >> 2, q = idx & 3;
            uint32_t soff = row * 64 + ((q ^ ((row >> 1) & 3)) << 4);
            cpa16(sb + soff,        Ah + (size_t)row * FEAT + k0 + q * 8);
            cpa16(sb + 8192 + soff, Al + (size_t)row * FEAT + k0 + q * 8);
        }
        for (int idx = tid; idx < 384; idx += 256) {
            int row = idx >> 2, q = idx & 3;
            uint32_t soff = row * 64 + ((q ^ ((row >> 1) & 3)) << 4);
            cpa16(sb + 16384 + soff, Bhp + (size_t)row * FEAT + k0 + q * 8);
            cpa16(sb + 22528 + soff, Blp + (size_t)row * FEAT + k0 + q * 8);
        }
        cpa_commit();
    };

    load_stage(0, 0);
    #pragma unroll 1
    for (int ci = 0; ci < 8; ci++) {
        const int s = ci & 1;
        if (ci < 7) { load_stage(ci + 1, s ^ 1); asm volatile("cp.async.wait_group 1;"); }
        else        asm volatile("cp.async.wait_group 0;");
        __syncthreads();
        const uint32_t sb = smb + s * KV_STG;
        #pragma unroll
        for (int k2 = 0; k2 < 2; k2++) {
            uint32_t aH[2][4], aL[2][4], bH[6][2], bL[6][2];
            #pragma unroll
            for (int mi = 0; mi < 2; mi++) {
                int row = wm + mi * 16 + (lid & 7) + ((lid >> 3) & 1) * 8;
                int q = k2 * 2 + (lid >> 4);
                uint32_t off = row * 64 + ((q ^ ((row >> 1) & 3)) << 4);
                ldmx4(sb + off,        aH[mi][0], aH[mi][1], aH[mi][2], aH[mi][3]);
                ldmx4(sb + 8192 + off, aL[mi][0], aL[mi][1], aL[mi][2], aL[mi][3]);
            }
            #pragma unroll
            for (int np = 0; np < 3; np++) {
                int row = wn + np * 16 + (lid >> 4) * 8 + (lid & 7);
                int q = k2 * 2 + ((lid >> 3) & 1);
                uint32_t off = row * 64 + ((q ^ ((row >> 1) & 3)) << 4);
                ldmx4(sb + 16384 + off, bH[2*np][0], bH[2*np][1], bH[2*np+1][0], bH[2*np+1][1]);
                ldmx4(sb + 22528 + off, bL[2*np][0], bL[2*np][1], bL[2*np+1][0], bL[2*np+1][1]);
            }
            #pragma unroll
            for (int mi = 0; mi < 2; mi++)
                #pragma unroll
                for (int ni = 0; ni < 6; ni++)
                    mma16816(acc[mi][ni], aH[mi], bH[ni]);
            #pragma unroll
            for (int mi = 0; mi < 2; mi++)
                #pragma unroll
                for (int ni = 0; ni < 6; ni++)
                    mma16816(acc[mi][ni], aH[mi], bL[ni]);
            #pragma unroll
            for (int mi = 0; mi < 2; mi++)
                #pragma unroll
                for (int ni = 0; ni < 6; ni++)
                    mma16816(acc[mi][ni], aL[mi], bH[ni]);
        }
        __syncthreads();
    }

    const int g = lid >> 2, c2 = (lid & 3) * 2;
    if ((wid >> 2) == 1 && (lid & 3) == 0) {
        #pragma unroll
        for (int mi = 0; mi < 2; mi++) {
            int rl = wm + mi * 16 + g;
            sden[rl]     = acc[mi][2][0];
            sden[rl + 8] = acc[mi][2][2];
        }
    }
    __syncthreads();

    const int b = bh >> 4, h = bh & 15;
    const int nlim = ((wid >> 2) == 0) ? 6 : 2;
    #pragma unroll
    for (int mi = 0; mi < 2; mi++) {
        int rl = wm + mi * 16 + g;
        float z0 = 1.f / (sden[rl] + 1e-6f);
        float z1 = 1.f / (sden[rl + 8] + 1e-6f);
        size_t rg0 = (size_t)(b * SEQ + n0 + rl) * DIMV + h * 64;
        size_t rg1 = rg0 + 8 * DIMV;
        for (int ni = 0; ni < nlim; ni++) {
            int col = wn + ni * 8 + c2;
            float2 o0 = { acc[mi][ni][0] * z0, acc[mi][ni][1] * z0 };
            float2 o1 = { acc[mi][ni][2] * z1, acc[mi][ni][3] * z1 };
            *(float2*)&g_af[rg0 + col] = o0;
            *(float2*)&g_af[rg1 + col] = o1;
        }
    }
}

// ---------------- launch ----------------
extern "C" void kernel_launch(void* const* d_in, const int* in_sizes, int n_in,
                              void* d_out, int out_size)
{
    const float* x  = (const float*)d_in[0];
    const float* Wq = (const float*)d_in[1];
    const float* Wk = (const float*)d_in[2];
    const float* Wv = (const float*)d_in[3];
    const float* Wp = (const float*)d_in[4];
    const float* bp = (const float*)d_in[5];
    const float* Wr = (const float*)d_in[6];
    const float* br = (const float*)d_in[7];
    float* out = (float*)d_out;

    int8_t *xq1, *xq2, *wq1, *wq2, *pq1, *pq2, *aq1, *aq2;
    float *sx, *sw, *sp, *sa, *af;
    cudaGetSymbolAddress((void**)&xq1, g_xq1); cudaGetSymbolAddress((void**)&xq2, g_xq2);
    cudaGetSymbolAddress((void**)&wq1, g_wq1); cudaGetSymbolAddress((void**)&wq2, g_wq2);
    cudaGetSymbolAddress((void**)&pq1, g_pq1); cudaGetSymbolAddress((void**)&pq2, g_pq2);
    cudaGetSymbolAddress((void**)&aq1, g_aq1); cudaGetSymbolAddress((void**)&aq2, g_aq2);
    cudaGetSymbolAddress((void**)&sx, g_sx);   cudaGetSymbolAddress((void**)&sw, g_sw);
    cudaGetSymbolAddress((void**)&sp, g_sp);   cudaGetSymbolAddress((void**)&sa, g_sa);
    cudaGetSymbolAddress((void**)&af, g_af);

    cudaFuncSetAttribute(gemm_i8<0>, cudaFuncAttributeMaxDynamicSharedMemorySize, IGEMM_SMEM);
    cudaFuncSetAttribute(gemm_i8<3>, cudaFuncAttributeMaxDynamicSharedMemorySize, IGEMM_SMEM);
    cudaFuncSetAttribute(proj_feat, cudaFuncAttributeMaxDynamicSharedMemorySize, PROJ_SMEM);
    cudaFuncSetAttribute(gemm_kv,  cudaFuncAttributeMaxDynamicSharedMemorySize, KV_SMEM);
    cudaFuncSetAttribute(gemm_out, cudaFuncAttributeMaxDynamicSharedMemorySize, OUT_SMEM);

    const int WSZ = DIMV * DIMV;

    quant_rows<<<MROWS / 8, 256>>>(x, xq1, xq2, sx, MROWS);
    quant_rows<<<DIMV / 8, 256>>>(Wq, wq1 + 0 * WSZ, wq2 + 0 * WSZ, sw + 0 * DIMV, DIMV);
    quant_rows<<<DIMV / 8, 256>>>(Wk, wq1 + 1 * WSZ, wq2 + 1 * WSZ, sw + 1 * DIMV, DIMV);
    quant_rows<<<DIMV / 8, 256>>>(Wv, wq1 + 2 * WSZ, wq2 + 2 * WSZ, sw + 2 * DIMV, DIMV);
    quant_rows<<<DIMV / 8, 256>>>(Wp, pq1, pq2, sp, DIMV);
    prep_wrt<<<NHEADS, 256>>>(Wr);
    fill_vt<<<BH * 32, 256>>>();

    // merged QKV int8 GEMM: N = 3072, 512 threads
    gemm_i8<3><<<dim3(3 * DIMV / 128, MROWS / 128), 512, IGEMM_SMEM>>>(
        xq1, xq2, sx, wq1, wq2, sw, nullptr, nullptr);

    proj_feat<<<dim3(MROWS / 128, 32), 256, PROJ_SMEM>>>(br);
    gemm_kv<<<dim3(8, BH * 2), 256, KV_SMEM>>>();
    kv_reduce_t<<<(BH * FEAT * NPAD + 255) / 256, 256>>>();
    gemm_out<<<dim3(SEQ / 128, BH), 256, OUT_SMEM>>>();

    quant_rows<<<MROWS / 8, 256>>>(af, aq1, aq2, sa, MROWS);
    gemm_i8<0><<<dim3(DIMV / 128, MROWS / 128), 512, IGEMM_SMEM>>>(
        aq1, aq2, sa, pq1, pq2, sp, bp, out);
}

// round 10
// speedup vs baseline: 1.0196x; 1.0196x over previous
#include <cuda_runtime.h>
#include <cuda_bf16.h>
#include <math.h>
#include <stdint.h>

#define DIMV 1024
#define NHEADS 16
#define DK 64
#define RFF 128
#define FEAT 256
#define BATCH 2
#define SEQ 8192
#define MROWS 16384
#define BH 32
#define NPAD 96
#define INV_SQRT_R 0.08838834764831845f

typedef __nv_bfloat16 bf16;
typedef __nv_bfloat162 bf162;

// ---------------- scratch (device globals) ----------------
__device__ int8_t g_xq1[MROWS*DIMV], g_xq2[MROWS*DIMV];
__device__ float  g_sx[MROWS];
__device__ int8_t g_wq1[3*DIMV*DIMV], g_wq2[3*DIMV*DIMV];
__device__ float  g_sw[3*DIMV];
__device__ int8_t g_pq1[DIMV*DIMV], g_pq2[DIMV*DIMV];
__device__ float  g_sp[DIMV];
__device__ bf16 g_qh[MROWS*DIMV], g_ql[MROWS*DIMV];
__device__ bf16 g_kh[MROWS*DIMV], g_kl[MROWS*DIMV];
__device__ bf16 g_wrth[NHEADS*RFF*DK], g_wrtl[NHEADS*RFF*DK];
// int8 attention chain buffers
__device__ int8_t g_vq1[(size_t)BH*NPAD*SEQ], g_vq2[(size_t)BH*NPAD*SEQ];
__device__ int8_t g_qfq1[(size_t)BH*SEQ*FEAT], g_qfq2[(size_t)BH*SEQ*FEAT];
__device__ int8_t g_kfq1[(size_t)BH*FEAT*SEQ], g_kfq2[(size_t)BH*FEAT*SEQ];
__device__ float g_kvp[8*BH*FEAT*NPAD];
__device__ int8_t g_dq1[(size_t)BH*NPAD*FEAT], g_dq2[(size_t)BH*NPAD*FEAT];
__device__ float  g_sd[BH*NPAD];
__device__ float g_af[MROWS*DIMV];
__device__ int8_t g_aq1[MROWS*DIMV], g_aq2[MROWS*DIMV];
__device__ float  g_sa[MROWS];

#define INV_SV (127.f/8.f)
#define SF_QF (INV_SQRT_R/127.f)
#define DEQ_KV ((INV_SQRT_R/127.f)*(8.f/127.f))

// ---------------- helpers ----------------
__device__ __forceinline__ uint32_t smem_u32(const void* p) {
    uint32_t a;
    asm("{ .reg .u64 t; cvta.to.shared.u64 t, %1; cvt.u32.u64 %0, t; }" : "=r"(a) : "l"(p));
    return a;
}
__device__ __forceinline__ void cpa16(uint32_t s, const void* g) {
    asm volatile("cp.async.cg.shared.global [%0], [%1], 16;" :: "r"(s), "l"(g));
}
__device__ __forceinline__ void cpa_commit() { asm volatile("cp.async.commit_group;"); }
__device__ __forceinline__ void ldmx4(uint32_t addr, uint32_t& r0, uint32_t& r1, uint32_t& r2, uint32_t& r3) {
    asm volatile("ldmatrix.sync.aligned.m8n8.x4.shared.b16 {%0,%1,%2,%3}, [%4];"
                 : "=r"(r0), "=r"(r1), "=r"(r2), "=r"(r3) : "r"(addr));
}
__device__ __forceinline__ void mma16816(float* d, const uint32_t* a, const uint32_t* b) {
    asm volatile(
        "mma.sync.aligned.m16n8k16.row.col.f32.bf16.bf16.f32 "
        "{%0,%1,%2,%3}, {%4,%5,%6,%7}, {%8,%9}, {%0,%1,%2,%3};"
        : "+f"(d[0]), "+f"(d[1]), "+f"(d[2]), "+f"(d[3])
        : "r"(a[0]), "r"(a[1]), "r"(a[2]), "r"(a[3]), "r"(b[0]), "r"(b[1]));
}
__device__ __forceinline__ void imma16832(int* d, const uint32_t* a, const uint32_t* b) {
    asm volatile(
        "mma.sync.aligned.m16n8k32.row.col.s32.s8.s8.s32 "
        "{%0,%1,%2,%3}, {%4,%5,%6,%7}, {%8,%9}, {%0,%1,%2,%3};"
        : "+r"(d[0]), "+r"(d[1]), "+r"(d[2]), "+r"(d[3])
        : "r"(a[0]), "r"(a[1]), "r"(a[2]), "r"(a[3]), "r"(b[0]), "r"(b[1]));
}
__device__ __forceinline__ void bsplit(float v, bf16& h, bf16& l) {
    h = __float2bfloat16(v);
    l = __float2bfloat16(v - __bfloat162float(h));
}
__device__ __forceinline__ bf162 mk2(bf16 a, bf16 b) { bf162 t; t.x = a; t.y = b; return t; }
__device__ __forceinline__ void iq2(float qv, int8_t& q1, int8_t& q2) {
    float a1 = fminf(fmaxf(rintf(qv), -127.f), 127.f);
    float a2 = fminf(fmaxf(rintf((qv - a1) * 256.f), -127.f), 127.f);
    q1 = (int8_t)a1; q2 = (int8_t)a2;
}

// ---------------- per-row 2-digit int8 quantization ----------------
__global__ __launch_bounds__(256) void quant_rows(
    const float* __restrict__ in, int8_t* __restrict__ q1,
    int8_t* __restrict__ q2, float* __restrict__ sc, int nrows)
{
    int row = blockIdx.x * 8 + (threadIdx.x >> 5);
    if (row >= nrows) return;
    int lid = threadIdx.x & 31;
    const float4* r = (const float4*)(in + (size_t)row * 1024);
    float4 v[8];
    float mx = 0.f;
    #pragma unroll
    for (int i = 0; i < 8; i++) {
        v[i] = r[lid + 32 * i];
        mx = fmaxf(mx, fmaxf(fmaxf(fabsf(v[i].x), fabsf(v[i].y)),
                             fmaxf(fabsf(v[i].z), fabsf(v[i].w))));
    }
    #pragma unroll
    for (int o = 16; o; o >>= 1) mx = fmaxf(mx, __shfl_xor_sync(0xFFFFFFFFu, mx, o));
    mx = fmaxf(mx, 1e-20f);
    float inv = 127.f / mx;
    if (lid == 0) sc[row] = mx / 127.f;
    char4* o1 = (char4*)(q1 + (size_t)row * 1024);
    char4* o2 = (char4*)(q2 + (size_t)row * 1024);
    #pragma unroll
    for (int i = 0; i < 8; i++) {
        float qv[4] = { v[i].x * inv, v[i].y * inv, v[i].z * inv, v[i].w * inv };
        int8_t c1[4], c2[4];
        #pragma unroll
        for (int j = 0; j < 4; j++) iq2(qv[j], c1[j], c2[j]);
        o1[lid + 32 * i] = make_char4(c1[0], c1[1], c1[2], c1[3]);
        o2[lid + 32 * i] = make_char4(c2[0], c2[1], c2[2], c2[3]);
    }
}

// ---------------- WrT prep ----------------
__global__ __launch_bounds__(256) void prep_wrt(const float* __restrict__ Wr)
{
    int h = blockIdx.x;
    for (int e = threadIdx.x; e < RFF * DK; e += 256) {
        int r = e >> 6, j = e & 63;
        float v = Wr[(size_t)h * DK * RFF + j * RFF + r];
        bf16 hi, lo; bsplit(v, hi, lo);
        g_wrth[h * RFF * DK + e] = hi;
        g_wrtl[h * RFF * DK + e] = lo;
    }
}

// ---------------- v padding rows: d=64 -> ones (exact), 65..95 -> zeros ----------------
__global__ __launch_bounds__(256) void fill_vq()
{
    int bx = blockIdx.x;
    int bh = bx >> 5, dr = 64 + (bx & 31);
    char c1 = (dr == 64) ? 16 : 0;
    char c2 = (dr == 64) ? -32 : 0;
    uint32_t w1 = (uint8_t)c1; w1 |= w1 << 8; w1 |= w1 << 16;
    uint32_t w2 = (uint8_t)c2; w2 |= w2 << 8; w2 |= w2 << 16;
    size_t base = ((size_t)bh * NPAD + dr) * SEQ;
    for (int i = threadIdx.x; i < SEQ / 4; i += 256) {
        ((uint32_t*)(g_vq1 + base))[i] = w1;
        ((uint32_t*)(g_vq2 + base))[i] = w2;
    }
}

// ---------------- int8x2 IMMA GEMM (R6 proven shape: 256 threads, 8 warps 2x4) ----------------
#define ISTG 32768
#define IGEMM_SMEM (2 * ISTG)

template<int MODE>
__global__ __launch_bounds__(256, 1) void gemm_i8(
    const int8_t* __restrict__ A1, const int8_t* __restrict__ A2, const float* __restrict__ sA,
    const int8_t* __restrict__ B1, const int8_t* __restrict__ B2, const float* __restrict__ sB,
    const float* __restrict__ bias, float* __restrict__ C)
{
    extern __shared__ __align__(128) char sm[];
    const int tid = threadIdx.x, wid = tid >> 5, lid = tid & 31;
    const int m0 = blockIdx.y * 128, n0 = blockIdx.x * 128;
    const int wm = (wid & 1) * 64;
    const int wn = (wid >> 1) * 32;
    const uint32_t smb = smem_u32(sm);

    int X[4][4][4], Y[4][4][4];
    #pragma unroll
    for (int i = 0; i < 4; i++)
        #pragma unroll
        for (int j = 0; j < 4; j++)
            #pragma unroll
            for (int e = 0; e < 4; e++) { X[i][j][e] = 0; Y[i][j][e] = 0; }

    auto load_stage = [&](int ci, int s) {
        const int k0 = ci * 64;
        const uint32_t sb = smb + s * ISTG;
        #pragma unroll
        for (int it = 0; it < 2; it++) {
            int t = tid + it * 256;
            int row = t >> 2, q = t & 3;
            uint32_t soff = row * 64 + ((q ^ ((row >> 1) & 3)) << 4);
            size_t ga = (size_t)(m0 + row) * DIMV + k0 + q * 16;
            size_t gb = (size_t)(n0 + row) * DIMV + k0 + q * 16;
            cpa16(sb + soff,         A1 + ga);
            cpa16(sb + 8192  + soff, A2 + ga);
            cpa16(sb + 16384 + soff, B1 + gb);
            cpa16(sb + 24576 + soff, B2 + gb);
        }
        cpa_commit();
    };

    load_stage(0, 0);

    #pragma unroll 1
    for (int ci = 0; ci < 16; ci++) {
        const int s = ci & 1;
        if (ci < 15) { load_stage(ci + 1, s ^ 1); asm volatile("cp.async.wait_group 1;"); }
        else         asm volatile("cp.async.wait_group 0;");
        __syncthreads();

        const uint32_t sb = smb + s * ISTG;
        #pragma unroll
        for (int ks = 0; ks < 2; ks++) {
            uint32_t a1f[4][4], a2f[4][4], b1f[4][2], b2f[4][2];
            #pragma unroll
            for (int mi = 0; mi < 4; mi++) {
                int row = wm + mi * 16 + (lid & 7) + ((lid >> 3) & 1) * 8;
                int q = ks * 2 + (lid >> 4);
                uint32_t off = row * 64 + ((q ^ ((row >> 1) & 3)) << 4);
                ldmx4(sb + off,        a1f[mi][0], a1f[mi][1], a1f[mi][2], a1f[mi][3]);
                ldmx4(sb + 8192 + off, a2f[mi][0], a2f[mi][1], a2f[mi][2], a2f[mi][3]);
            }
            #pragma unroll
            for (int np = 0; np < 2; np++) {
                int row = wn + np * 16 + (lid >> 4) * 8 + (lid & 7);
                int q = ks * 2 + ((lid >> 3) & 1);
                uint32_t off = row * 64 + ((q ^ ((row >> 1) & 3)) << 4);
                ldmx4(sb + 16384 + off, b1f[2*np][0], b1f[2*np][1], b1f[2*np+1][0], b1f[2*np+1][1]);
                ldmx4(sb + 24576 + off, b2f[2*np][0], b2f[2*np][1], b2f[2*np+1][0], b2f[2*np+1][1]);
            }
            #pragma unroll
            for (int mi = 0; mi < 4; mi++)
                #pragma unroll
                for (int ni = 0; ni < 4; ni++)
                    imma16832(X[mi][ni], a1f[mi], b1f[ni]);
            #pragma unroll
            for (int mi = 0; mi < 4; mi++)
                #pragma unroll
                for (int ni = 0; ni < 4; ni++)
                    imma16832(Y[mi][ni], a1f[mi], b2f[ni]);
            #pragma unroll
            for (int mi = 0; mi < 4; mi++)
                #pragma unroll
                for (int ni = 0; ni < 4; ni++)
                    imma16832(Y[mi][ni], a2f[mi], b1f[ni]);
        }
        __syncthreads();
    }

    const int g = lid >> 2, c2 = (lid & 3) * 2;
    #pragma unroll
    for (int mi = 0; mi < 4; mi++) {
        int row = m0 + wm + mi * 16 + g;
        float sa0 = sA[row], sa1 = sA[row + 8];
        #pragma unroll
        for (int ni = 0; ni < 4; ni++) {
            int col = n0 + wn + ni * 8 + c2;
            float sb0 = sB[col], sb1 = sB[col + 1];
            float r00 = sa0 * sb0 * ((float)X[mi][ni][0] + (float)Y[mi][ni][0] * (1.f/256.f));
            float r01 = sa0 * sb1 * ((float)X[mi][ni][1] + (float)Y[mi][ni][1] * (1.f/256.f));
            float r10 = sa1 * sb0 * ((float)X[mi][ni][2] + (float)Y[mi][ni][2] * (1.f/256.f));
            float r11 = sa1 * sb1 * ((float)X[mi][ni][3] + (float)Y[mi][ni][3] * (1.f/256.f));
            if (MODE == 0) {
                float b0 = bias ? bias[col] : 0.f;
                float b1 = bias ? bias[col + 1] : 0.f;
                float2 o0 = { r00 + b0, r01 + b1 };
                float2 o1 = { r10 + b0, r11 + b1 };
                *(float2*)&C[(size_t)row * DIMV + col]       = o0;
                *(float2*)&C[(size_t)(row + 8) * DIMV + col] = o1;
            } else {
                if (col < 2048) {
                    bf16* Ch = (col < 1024) ? g_qh : g_kh;
                    bf16* Cl = (col < 1024) ? g_ql : g_kl;
                    int cc = col & 1023;
                    bf16 h0, l0, h1, l1;
                    bsplit(r00, h0, l0); bsplit(r01, h1, l1);
                    *(bf162*)&Ch[(size_t)row * DIMV + cc] = mk2(h0, h1);
                    *(bf162*)&Cl[(size_t)row * DIMV + cc] = mk2(l0, l1);
                    bsplit(r10, h0, l0); bsplit(r11, h1, l1);
                    *(bf162*)&Ch[(size_t)(row + 8) * DIMV + cc] = mk2(h0, h1);
                    *(bf162*)&Cl[(size_t)(row + 8) * DIMV + cc] = mk2(l0, l1);
                } else {
                    int cc = col - 2048;
                    int hh = cc >> 6, d0 = cc & 63;
                    int b = row >> 13, n = row & 8191;
                    size_t base = ((size_t)(b * NHEADS + hh) * NPAD) * SEQ;
                    int8_t q1, q2;
                    iq2(r00 * INV_SV, q1, q2);
                    g_vq1[base + (size_t)d0 * SEQ + n] = q1;       g_vq2[base + (size_t)d0 * SEQ + n] = q2;
                    iq2(r01 * INV_SV, q1, q2);
                    g_vq1[base + (size_t)(d0+1) * SEQ + n] = q1;   g_vq2[base + (size_t)(d0+1) * SEQ + n] = q2;
                    iq2(r10 * INV_SV, q1, q2);
                    g_vq1[base + (size_t)d0 * SEQ + n + 8] = q1;   g_vq2[base + (size_t)d0 * SEQ + n + 8] = q2;
                    iq2(r11 * INV_SV, q1, q2);
                    g_vq1[base + (size_t)(d0+1) * SEQ + n + 8] = q1; g_vq2[base + (size_t)(d0+1) * SEQ + n + 8] = q2;
                }
            }
        }
    }
}

// ---------------- proj + RFF features -> int8 features ----------------
#define PROJ_SMEM 65536

__global__ __launch_bounds__(256, 1) void proj_feat(const float* __restrict__ brp)
{
    extern __shared__ __align__(128) char sm[];
    const int tid = threadIdx.x, wid = tid >> 5, lid = tid & 31;
    const int m0 = blockIdx.x * 128;
    const int qk = blockIdx.y >> 4, h = blockIdx.y & 15;
    const int wm = (wid & 1) * 64, wn = (wid >> 1) * 32;
    const uint32_t smb = smem_u32(sm);

    const bf16* Ah = (qk ? g_kh : g_qh);
    const bf16* Al = (qk ? g_kl : g_ql);
    const bf16* Bh = g_wrth + h * RFF * DK;
    const bf16* Bl = g_wrtl + h * RFF * DK;

    #pragma unroll
    for (int it = 0; it < 4; it++) {
        int idx = tid + it * 256;
        int row = idx >> 3, q = idx & 7;
        uint32_t soff = row * 128 + ((q ^ (row & 7)) << 4);
        *(uint4*)(sm + soff)         = *(const uint4*)(Ah + (size_t)(m0 + row) * DIMV + h * DK + q * 8);
        *(uint4*)(sm + 16384 + soff) = *(const uint4*)(Al + (size_t)(m0 + row) * DIMV + h * DK + q * 8);
        *(uint4*)(sm + 32768 + soff) = *(const uint4*)(Bh + row * DK + q * 8);
        *(uint4*)(sm + 49152 + soff) = *(const uint4*)(Bl + row * DK + q * 8);
    }
    __syncthreads();

    float acc[4][4][4];
    #pragma unroll
    for (int i = 0; i < 4; i++)
        #pragma unroll
        for (int j = 0; j < 4; j++)
            #pragma unroll
            for (int e = 0; e < 4; e++) acc[i][j][e] = 0.f;

    #pragma unroll
    for (int ks = 0; ks < 4; ks++) {
        uint32_t aH[4][4], aL[4][4], bH[4][2], bL[4][2];
        #pragma unroll
        for (int mi = 0; mi < 4; mi++) {
            int row = wm + mi * 16 + (lid & 7) + ((lid >> 3) & 1) * 8;
            int q = ks * 2 + (lid >> 4);
            uint32_t off = row * 128 + ((q ^ (row & 7)) << 4);
            ldmx4(smb + off,         aH[mi][0], aH[mi][1], aH[mi][2], aH[mi][3]);
            ldmx4(smb + 16384 + off, aL[mi][0], aL[mi][1], aL[mi][2], aL[mi][3]);
        }
        #pragma unroll
        for (int np = 0; np < 2; np++) {
            int row = wn + np * 16 + (lid >> 4) * 8 + (lid & 7);
            int q = ks * 2 + ((lid >> 3) & 1);
            uint32_t off = row * 128 + ((q ^ (row & 7)) << 4);
            ldmx4(smb + 32768 + off, bH[2*np][0], bH[2*np][1], bH[2*np+1][0], bH[2*np+1][1]);
            ldmx4(smb + 49152 + off, bL[2*np][0], bL[2*np][1], bL[2*np+1][0], bL[2*np+1][1]);
        }
        #pragma unroll
        for (int mi = 0; mi < 4; mi++)
            #pragma unroll
            for (int ni = 0; ni < 4; ni++)
                mma16816(acc[mi][ni], aH[mi], bH[ni]);
        #pragma unroll
        for (int mi = 0; mi < 4; mi++)
            #pragma unroll
            for (int ni = 0; ni < 4; ni++)
                mma16816(acc[mi][ni], aH[mi], bL[ni]);
        #pragma unroll
        for (int mi = 0; mi < 4; mi++)
            #pragma unroll
            for (int ni = 0; ni < 4; ni++)
                mma16816(acc[mi][ni], aL[mi], bH[ni]);
    }

    const int g = lid >> 2, c2 = (lid & 3) * 2;
    #pragma unroll
    for (int mi = 0; mi < 4; mi++) {
        #pragma unroll
        for (int ni = 0; ni < 4; ni++) {
            int col = wn + ni * 8 + c2;
            float b0 = brp[h * RFF + col], b1 = brp[h * RFF + col + 1];
            #pragma unroll
            for (int half = 0; half < 2; half++) {
                int row = m0 + wm + mi * 16 + g + half * 8;
                int b = row >> 13, n = row & 8191;
                int bh = b * NHEADS + h;
                float p0 = acc[mi][ni][half * 2 + 0] + b0;
                float p1 = acc[mi][ni][half * 2 + 1] + b1;
                float s0, c0, s1, c1;
                __sincosf(p0, &s0, &c0);
                __sincosf(p1, &s1, &c1);
                int8_t cq1a, cq2a, cq1b, cq2b, sq1a, sq2a, sq1b, sq2b;
                iq2(c0 * 127.f, cq1a, cq2a); iq2(c1 * 127.f, cq1b, cq2b);
                iq2(s0 * 127.f, sq1a, sq2a); iq2(s1 * 127.f, sq1b, sq2b);
                if (qk == 0) {
                    size_t base = ((size_t)bh * SEQ + n) * FEAT;
                    char2 pc1; pc1.x = cq1a; pc1.y = cq1b;
                    char2 pc2; pc2.x = cq2a; pc2.y = cq2b;
                    char2 ps1; ps1.x = sq1a; ps1.y = sq1b;
                    char2 ps2; ps2.x = sq2a; ps2.y = sq2b;
                    *(char2*)&g_qfq1[base + col]       = pc1;
                    *(char2*)&g_qfq2[base + col]       = pc2;
                    *(char2*)&g_qfq1[base + RFF + col] = ps1;
                    *(char2*)&g_qfq2[base + RFF + col] = ps2;
                } else {
                    size_t kb = ((size_t)bh * FEAT + col) * SEQ + n;
                    g_kfq1[kb] = cq1a;                      g_kfq2[kb] = cq2a;
                    g_kfq1[kb + SEQ] = cq1b;                g_kfq2[kb + SEQ] = cq2b;
                    g_kfq1[kb + (size_t)RFF*SEQ] = sq1a;    g_kfq2[kb + (size_t)RFF*SEQ] = sq2a;
                    g_kfq1[kb + (size_t)(RFF+1)*SEQ] = sq1b; g_kfq2[kb + (size_t)(RFF+1)*SEQ] = sq2b;
                }
            }
        }
    }
}

// ---------------- Kv GEMM int8 (split-K 8): C[f,d] = sum_n kf*v ----------------
#define KV_STG 28672
#define KV_SMEM (2 * KV_STG)

__global__ __launch_bounds__(256, 1) void gemm_kv()
{
    extern __shared__ __align__(128) char sm[];
    const int tid = threadIdx.x, wid = tid >> 5, lid = tid & 31;
    const int ks = blockIdx.x;
    const int bh = blockIdx.y >> 1, m2 = blockIdx.y & 1;
    const int wm = (wid & 3) * 32, wn = (wid >> 2) * 48;
    const uint32_t smb = smem_u32(sm);

    const int8_t* A1 = g_kfq1 + ((size_t)bh * FEAT + m2 * 128) * SEQ + ks * 1024;
    const int8_t* A2 = g_kfq2 + ((size_t)bh * FEAT + m2 * 128) * SEQ + ks * 1024;
    const int8_t* B1 = g_vq1 + (size_t)bh * NPAD * SEQ + ks * 1024;
    const int8_t* B2 = g_vq2 + (size_t)bh * NPAD * SEQ + ks * 1024;

    int X[2][6][4], Y[2][6][4];
    #pragma unroll
    for (int i = 0; i < 2; i++)
        #pragma unroll
        for (int j = 0; j < 6; j++)
            #pragma unroll
            for (int e = 0; e < 4; e++) { X[i][j][e] = 0; Y[i][j][e] = 0; }

    auto load_stage = [&](int ci, int s) {
        const int k0 = ci * 64;
        const uint32_t sb = smb + s * KV_STG;
        #pragma unroll
        for (int it = 0; it < 2; it++) {
            int idx = tid + it * 256;
            int row = idx >> 2, q = idx & 3;
            uint32_t soff = row * 64 + ((q ^ ((row >> 1) & 3)) << 4);
            cpa16(sb + soff,        A1 + (size_t)row * SEQ + k0 + q * 16);
            cpa16(sb + 8192 + soff, A2 + (size_t)row * SEQ + k0 + q * 16);
        }
        for (int idx = tid; idx < 384; idx += 256) {
            int row = idx >> 2, q = idx & 3;
            uint32_t soff = row * 64 + ((q ^ ((row >> 1) & 3)) << 4);
            cpa16(sb + 16384 + soff, B1 + (size_t)row * SEQ + k0 + q * 16);
            cpa16(sb + 22528 + soff, B2 + (size_t)row * SEQ + k0 + q * 16);
        }
        cpa_commit();
    };

    load_stage(0, 0);
    #pragma unroll 1
    for (int ci = 0; ci < 16; ci++) {
        const int s = ci & 1;
        if (ci < 15) { load_stage(ci + 1, s ^ 1); asm volatile("cp.async.wait_group 1;"); }
        else         asm volatile("cp.async.wait_group 0;");
        __syncthreads();
        const uint32_t sb = smb + s * KV_STG;
        #pragma unroll
        for (int k2 = 0; k2 < 2; k2++) {
            uint32_t a1f[2][4], a2f[2][4], b1f[6][2], b2f[6][2];
            #pragma unroll
            for (int mi = 0; mi < 2; mi++) {
                int row = wm + mi * 16 + (lid & 7) + ((lid >> 3) & 1) * 8;
                int q = k2 * 2 + (lid >> 4);
                uint32_t off = row * 64 + ((q ^ ((row >> 1) & 3)) << 4);
                ldmx4(sb + off,        a1f[mi][0], a1f[mi][1], a1f[mi][2], a1f[mi][3]);
                ldmx4(sb + 8192 + off, a2f[mi][0], a2f[mi][1], a2f[mi][2], a2f[mi][3]);
            }
            #pragma unroll
            for (int np = 0; np < 3; np++) {
                int row = wn + np * 16 + (lid >> 4) * 8 + (lid & 7);
                int q = k2 * 2 + ((lid >> 3) & 1);
                uint32_t off = row * 64 + ((q ^ ((row >> 1) & 3)) << 4);
                ldmx4(sb + 16384 + off, b1f[2*np][0], b1f[2*np][1], b1f[2*np+1][0], b1f[2*np+1][1]);
                ldmx4(sb + 22528 + off, b2f[2*np][0], b2f[2*np][1], b2f[2*np+1][0], b2f[2*np+1][1]);
            }
            #pragma unroll
            for (int mi = 0; mi < 2; mi++)
                #pragma unroll
                for (int ni = 0; ni < 6; ni++)
                    imma16832(X[mi][ni], a1f[mi], b1f[ni]);
            #pragma unroll
            for (int mi = 0; mi < 2; mi++)
                #pragma unroll
                for (int ni = 0; ni < 6; ni++)
                    imma16832(Y[mi][ni], a1f[mi], b2f[ni]);
            #pragma unroll
            for (int mi = 0; mi < 2; mi++)
                #pragma unroll
                for (int ni = 0; ni < 6; ni++)
                    imma16832(Y[mi][ni], a2f[mi], b1f[ni]);
        }
        __syncthreads();
    }

    const int g = lid >> 2, c2 = (lid & 3) * 2;
    #pragma unroll
    for (int mi = 0; mi < 2; mi++) {
        #pragma unroll
        for (int ni = 0; ni < 6; ni++) {
            int rl = wm + mi * 16 + g;
            int col = wn + ni * 8 + c2;
            float* dp = g_kvp + (((size_t)ks * BH + bh) * FEAT + m2 * 128 + rl) * NPAD + col;
            float2 o0 = { DEQ_KV * ((float)X[mi][ni][0] + (float)Y[mi][ni][0] * (1.f/256.f)),
                          DEQ_KV * ((float)X[mi][ni][1] + (float)Y[mi][ni][1] * (1.f/256.f)) };
            float2 o1 = { DEQ_KV * ((float)X[mi][ni][2] + (float)Y[mi][ni][2] * (1.f/256.f)),
                          DEQ_KV * ((float)X[mi][ni][3] + (float)Y[mi][ni][3] * (1.f/256.f)) };
            *(float2*)dp = o0;
            *(float2*)(dp + 8 * NPAD) = o1;
        }
    }
}

// ---------------- reduce partials + transpose + per-row quantize ----------------
__global__ __launch_bounds__(256) void kv_reduce_q()
{
    int wid = threadIdx.x >> 5, lid = threadIdx.x & 31;
    int r = blockIdx.x * 8 + wid;
    int bh = r / NPAD, d = r - bh * NPAD;
    float v[8];
    float mx = 0.f;
    #pragma unroll
    for (int i = 0; i < 8; i++) {
        int f = lid + 32 * i;
        float s = 0.f;
        #pragma unroll
        for (int ks = 0; ks < 8; ks++)
            s += g_kvp[(((size_t)ks * BH + bh) * FEAT + f) * NPAD + d];
        v[i] = s;
        mx = fmaxf(mx, fabsf(s));
    }
    #pragma unroll
    for (int o = 16; o; o >>= 1) mx = fmaxf(mx, __shfl_xor_sync(0xFFFFFFFFu, mx, o));
    mx = fmaxf(mx, 1e-20f);
    float inv = 127.f / mx;
    if (lid == 0) g_sd[r] = mx / 127.f;
    #pragma unroll
    for (int i = 0; i < 8; i++) {
        int f = lid + 32 * i;
        int8_t q1, q2;
        iq2(v[i] * inv, q1, q2);
        g_dq1[(size_t)r * FEAT + f] = q1;
        g_dq2[(size_t)r * FEAT + f] = q2;
    }
}

// ---------------- out GEMM int8: C[n,d] = sum_f qf * Dt, z scaling ----------------
#define OUT_SMEM (2 * KV_STG + 512)

__global__ __launch_bounds__(256, 1) void gemm_out()
{
    extern __shared__ __align__(128) char sm[];
    const int tid = threadIdx.x, wid = tid >> 5, lid = tid & 31;
    const int n0 = blockIdx.x * 128;
    const int bh = blockIdx.y;
    const int wm = (wid & 3) * 32, wn = (wid >> 2) * 48;
    const uint32_t smb = smem_u32(sm);
    float* sden = (float*)(sm + 2 * KV_STG);

    const int8_t* A1 = g_qfq1 + ((size_t)bh * SEQ + n0) * FEAT;
    const int8_t* A2 = g_qfq2 + ((size_t)bh * SEQ + n0) * FEAT;
    const int8_t* B1 = g_dq1 + (size_t)bh * NPAD * FEAT;
    const int8_t* B2 = g_dq2 + (size_t)bh * NPAD * FEAT;

    int X[2][6][4], Y[2][6][4];
    #pragma unroll
    for (int i = 0; i < 2; i++)
        #pragma unroll
        for (int j = 0; j < 6; j++)
            #pragma unroll
            for (int e = 0; e < 4; e++) { X[i][j][e] = 0; Y[i][j][e] = 0; }

    auto load_stage = [&](int ci, int s) {
        const int k0 = ci * 64;
        const uint32_t sb = smb + s * KV_STG;
        #pragma unroll
        for (int it = 0; it < 2; it++) {
            int idx = tid + it * 256;
            int row = idx >> 2, q = idx & 3;
            uint32_t soff = row * 64 + ((q ^ ((row >> 1) & 3)) << 4);
            cpa16(sb + soff,        A1 + (size_t)row * FEAT + k0 + q * 16);
            cpa16(sb + 8192 + soff, A2 + (size_t)row * FEAT + k0 + q * 16);
        }
        for (int idx = tid; idx < 384; idx += 256) {
            int row = idx >> 2, q = idx & 3;
            uint32_t soff = row * 64 + ((q ^ ((row >> 1) & 3)) << 4);
            cpa16(sb + 16384 + soff, B1 + (size_t)row * FEAT + k0 + q * 16);
            cpa16(sb + 22528 + soff, B2 + (size_t)row * FEAT + k0 + q * 16);
        }
        cpa_commit();
    };

    load_stage(0, 0);
    #pragma unroll 1
    for (int ci = 0; ci < 4; ci++) {
        const int s = ci & 1;
        if (ci < 3) { load_stage(ci + 1, s ^ 1); asm volatile("cp.async.wait_group 1;"); }
        else        asm volatile("cp.async.wait_group 0;");
        __syncthreads();
        const uint32_t sb = smb + s * KV_STG;
        #pragma unroll
        for (int k2 = 0; k2 < 2; k2++) {
            uint32_t a1f[2][4], a2f[2][4], b1f[6][2], b2f[6][2];
            #pragma unroll
            for (int mi = 0; mi < 2; mi++) {
                int row = wm + mi * 16 + (lid & 7) + ((lid >> 3) & 1) * 8;
                int q = k2 * 2 + (lid >> 4);
                uint32_t off = row * 64 + ((q ^ ((row >> 1) & 3)) << 4);
                ldmx4(sb + off,        a1f[mi][0], a1f[mi][1], a1f[mi][2], a1f[mi][3]);
                ldmx4(sb + 8192 + off, a2f[mi][0], a2f[mi][1], a2f[mi][2], a2f[mi][3]);
            }
            #pragma unroll
            for (int np = 0; np < 3; np++) {
                int row = wn + np * 16 + (lid >> 4) * 8 + (lid & 7);
                int q = k2 * 2 + ((lid >> 3) & 1);
                uint32_t off = row * 64 + ((q ^ ((row >> 1) & 3)) << 4);
                ldmx4(sb + 16384 + off, b1f[2*np][0], b1f[2*np][1], b1f[2*np+1][0], b1f[2*np+1][1]);
                ldmx4(sb + 22528 + off, b2f[2*np][0], b2f[2*np][1], b2f[2*np+1][0], b2f[2*np+1][1]);
            }
            #pragma unroll
            for (int mi = 0; mi < 2; mi++)
                #pragma unroll
                for (int ni = 0; ni < 6; ni++)
                    imma16832(X[mi][ni], a1f[mi], b1f[ni]);
            #pragma unroll
            for (int mi = 0; mi < 2; mi++)
                #pragma unroll
                for (int ni = 0; ni < 6; ni++)
                    imma16832(Y[mi][ni], a1f[mi], b2f[ni]);
            #pragma unroll
            for (int mi = 0; mi < 2; mi++)
                #pragma unroll
                for (int ni = 0; ni < 6; ni++)
                    imma16832(Y[mi][ni], a2f[mi], b1f[ni]);
        }
        __syncthreads();
    }

    const int g = lid >> 2, c2 = (lid & 3) * 2;
    if ((wid >> 2) == 1 && (lid & 3) == 0) {
        float sden_s = SF_QF * g_sd[bh * NPAD + 64];
        #pragma unroll
        for (int mi = 0; mi < 2; mi++) {
            int rl = wm + mi * 16 + g;
            sden[rl]     = sden_s * ((float)X[mi][2][0] + (float)Y[mi][2][0] * (1.f/256.f));
            sden[rl + 8] = sden_s * ((float)X[mi][2][2] + (float)Y[mi][2][2] * (1.f/256.f));
        }
    }
    __syncthreads();

    const int b = bh >> 4, h = bh & 15;
    const int nlim = ((wid >> 2) == 0) ? 6 : 2;
    #pragma unroll
    for (int mi = 0; mi < 2; mi++) {
        int rl = wm + mi * 16 + g;
        float z0 = 1.f / (sden[rl] + 1e-6f);
        float z1 = 1.f / (sden[rl + 8] + 1e-6f);
        size_t rg0 = (size_t)(b * SEQ + n0 + rl) * DIMV + h * 64;
        size_t rg1 = rg0 + 8 * DIMV;
        for (int ni = 0; ni < nlim; ni++) {
            int col = wn + ni * 8 + c2;
            float sb0 = SF_QF * g_sd[bh * NPAD + col];
            float sb1 = SF_QF * g_sd[bh * NPAD + col + 1];
            float r00 = sb0 * ((float)X[mi][ni][0] + (float)Y[mi][ni][0] * (1.f/256.f));
            float r01 = sb1 * ((float)X[mi][ni][1] + (float)Y[mi][ni][1] * (1.f/256.f));
            float r10 = sb0 * ((float)X[mi][ni][2] + (float)Y[mi][ni][2] * (1.f/256.f));
            float r11 = sb1 * ((float)X[mi][ni][3] + (float)Y[mi][ni][3] * (1.f/256.f));
            float2 o0 = { r00 * z0, r01 * z0 };
            float2 o1 = { r10 * z1, r11 * z1 };
            *(float2*)&g_af[rg0 + col] = o0;
            *(float2*)&g_af[rg1 + col] = o1;
        }
    }
}

// ---------------- launch ----------------
extern "C" void kernel_launch(void* const* d_in, const int* in_sizes, int n_in,
                              void* d_out, int out_size)
{
    const float* x  = (const float*)d_in[0];
    const float* Wq = (const float*)d_in[1];
    const float* Wk = (const float*)d_in[2];
    const float* Wv = (const float*)d_in[3];
    const float* Wp = (const float*)d_in[4];
    const float* bp = (const float*)d_in[5];
    const float* Wr = (const float*)d_in[6];
    const float* br = (const float*)d_in[7];
    float* out = (float*)d_out;

    int8_t *xq1, *xq2, *wq1, *wq2, *pq1, *pq2, *aq1, *aq2;
    float *sx, *sw, *sp, *sa, *af;
    cudaGetSymbolAddress((void**)&xq1, g_xq1); cudaGetSymbolAddress((void**)&xq2, g_xq2);
    cudaGetSymbolAddress((void**)&wq1, g_wq1); cudaGetSymbolAddress((void**)&wq2, g_wq2);
    cudaGetSymbolAddress((void**)&pq1, g_pq1); cudaGetSymbolAddress((void**)&pq2, g_pq2);
    cudaGetSymbolAddress((void**)&aq1, g_aq1); cudaGetSymbolAddress((void**)&aq2, g_aq2);
    cudaGetSymbolAddress((void**)&sx, g_sx);   cudaGetSymbolAddress((void**)&sw, g_sw);
    cudaGetSymbolAddress((void**)&sp, g_sp);   cudaGetSymbolAddress((void**)&sa, g_sa);
    cudaGetSymbolAddress((void**)&af, g_af);

    cudaFuncSetAttribute(gemm_i8<0>, cudaFuncAttributeMaxDynamicSharedMemorySize, IGEMM_SMEM);
    cudaFuncSetAttribute(gemm_i8<3>, cudaFuncAttributeMaxDynamicSharedMemorySize, IGEMM_SMEM);
    cudaFuncSetAttribute(proj_feat, cudaFuncAttributeMaxDynamicSharedMemorySize, PROJ_SMEM);
    cudaFuncSetAttribute(gemm_kv,  cudaFuncAttributeMaxDynamicSharedMemorySize, KV_SMEM);
    cudaFuncSetAttribute(gemm_out, cudaFuncAttributeMaxDynamicSharedMemorySize, OUT_SMEM);

    const int WSZ = DIMV * DIMV;

    quant_rows<<<MROWS / 8, 256>>>(x, xq1, xq2, sx, MROWS);
    quant_rows<<<DIMV / 8, 256>>>(Wq, wq1 + 0 * WSZ, wq2 + 0 * WSZ, sw + 0 * DIMV, DIMV);
    quant_rows<<<DIMV / 8, 256>>>(Wk, wq1 + 1 * WSZ, wq2 + 1 * WSZ, sw + 1 * DIMV, DIMV);
    quant_rows<<<DIMV / 8, 256>>>(Wv, wq1 + 2 * WSZ, wq2 + 2 * WSZ, sw + 2 * DIMV, DIMV);
    quant_rows<<<DIMV / 8, 256>>>(Wp, pq1, pq2, sp, DIMV);
    prep_wrt<<<NHEADS, 256>>>(Wr);
    fill_vq<<<BH * 32, 256>>>();

    // merged QKV int8 GEMM: N = 3072
    gemm_i8<3><<<dim3(3 * DIMV / 128, MROWS / 128), 256, IGEMM_SMEM>>>(
        xq1, xq2, sx, wq1, wq2, sw, nullptr, nullptr);

    proj_feat<<<dim3(MROWS / 128, 32), 256, PROJ_SMEM>>>(br);
    gemm_kv<<<dim3(8, BH * 2), 256, KV_SMEM>>>();
    kv_reduce_q<<<BH * NPAD / 8, 256>>>();
    gemm_out<<<dim3(SEQ / 128, BH), 256, OUT_SMEM>>>();

    quant_rows<<<MROWS / 8, 256>>>(af, aq1, aq2, sa, MROWS);
    gemm_i8<0><<<dim3(DIMV / 128, MROWS / 128), 256, IGEMM_SMEM>>>(
        aq1, aq2, sa, pq1, pq2, sp, bp, out);
}

// round 12
// speedup vs baseline: 1.0492x; 1.0290x over previous
#include <cuda_runtime.h>
#include <cuda_bf16.h>
#include <math.h>
#include <stdint.h>

#define DIMV 1024
#define NHEADS 16
#define DK 64
#define RFF 128
#define FEAT 256
#define BATCH 2
#define SEQ 8192
#define MROWS 16384
#define BH 32
#define NPAD 96
#define INV_SQRT_R 0.08838834764831845f

// ---------------- scratch (device globals) ----------------
__device__ int8_t g_xq1[MROWS*DIMV], g_xq2[MROWS*DIMV];
__device__ float  g_sx[MROWS];
__device__ int8_t g_wq1[3*DIMV*DIMV], g_wq2[3*DIMV*DIMV];
__device__ float  g_sw[3*DIMV];
__device__ int8_t g_pq1[DIMV*DIMV], g_pq2[DIMV*DIMV];
__device__ float  g_sp[DIMV];
// int8 q/k (fixed scale 8/127)
__device__ int8_t g_qq1[MROWS*DIMV], g_qq2[MROWS*DIMV];
__device__ int8_t g_kq1[MROWS*DIMV], g_kq2[MROWS*DIMV];
// int8 WrT (fixed scale 1/127)
__device__ int8_t g_wrq1[NHEADS*RFF*DK], g_wrq2[NHEADS*RFF*DK];
// int8 attention chain buffers
__device__ int8_t g_vq1[(size_t)BH*NPAD*SEQ], g_vq2[(size_t)BH*NPAD*SEQ];
__device__ int8_t g_qfq1[(size_t)BH*SEQ*FEAT], g_qfq2[(size_t)BH*SEQ*FEAT];
__device__ int8_t g_kfq1[(size_t)BH*FEAT*SEQ], g_kfq2[(size_t)BH*FEAT*SEQ];
__device__ float g_kvp[8*BH*FEAT*NPAD];
__device__ int8_t g_dq1[(size_t)BH*NPAD*FEAT], g_dq2[(size_t)BH*NPAD*FEAT];
__device__ float  g_sd[BH*NPAD];
// attention output: fp32 + per-row dynamic quant (unbounded-safe)
__device__ float g_af[MROWS*DIMV];
__device__ int8_t g_aq1[MROWS*DIMV], g_aq2[MROWS*DIMV];
__device__ float  g_sa[MROWS];

#define INV_SV (127.f/8.f)
#define SF_QF (INV_SQRT_R/127.f)
#define DEQ_KV ((INV_SQRT_R/127.f)*(8.f/127.f))
#define INV_SQK (127.f/8.f)
#define DEQ_P ((8.f/127.f)*(1.f/127.f))

// ---------------- helpers ----------------
__device__ __forceinline__ uint32_t smem_u32(const void* p) {
    uint32_t a;
    asm("{ .reg .u64 t; cvta.to.shared.u64 t, %1; cvt.u32.u64 %0, t; }" : "=r"(a) : "l"(p));
    return a;
}
__device__ __forceinline__ void cpa16(uint32_t s, const void* g) {
    asm volatile("cp.async.cg.shared.global [%0], [%1], 16;" :: "r"(s), "l"(g));
}
__device__ __forceinline__ void cpa_commit() { asm volatile("cp.async.commit_group;"); }
__device__ __forceinline__ void ldmx4(uint32_t addr, uint32_t& r0, uint32_t& r1, uint32_t& r2, uint32_t& r3) {
    asm volatile("ldmatrix.sync.aligned.m8n8.x4.shared.b16 {%0,%1,%2,%3}, [%4];"
                 : "=r"(r0), "=r"(r1), "=r"(r2), "=r"(r3) : "r"(addr));
}
__device__ __forceinline__ void imma16832(int* d, const uint32_t* a, const uint32_t* b) {
    asm volatile(
        "mma.sync.aligned.m16n8k32.row.col.s32.s8.s8.s32 "
        "{%0,%1,%2,%3}, {%4,%5,%6,%7}, {%8,%9}, {%0,%1,%2,%3};"
        : "+r"(d[0]), "+r"(d[1]), "+r"(d[2]), "+r"(d[3])
        : "r"(a[0]), "r"(a[1]), "r"(a[2]), "r"(a[3]), "r"(b[0]), "r"(b[1]));
}
__device__ __forceinline__ void iq2(float qv, int8_t& q1, int8_t& q2) {
    float a1 = fminf(fmaxf(rintf(qv), -127.f), 127.f);
    float a2 = fminf(fmaxf(rintf((qv - a1) * 256.f), -127.f), 127.f);
    q1 = (int8_t)a1; q2 = (int8_t)a2;
}

// ---------------- per-row 2-digit int8 quantization ----------------
__global__ __launch_bounds__(256) void quant_rows(
    const float* __restrict__ in, int8_t* __restrict__ q1,
    int8_t* __restrict__ q2, float* __restrict__ sc, int nrows)
{
    int row = blockIdx.x * 8 + (threadIdx.x >> 5);
    if (row >= nrows) return;
    int lid = threadIdx.x & 31;
    const float4* r = (const float4*)(in + (size_t)row * 1024);
    float4 v[8];
    float mx = 0.f;
    #pragma unroll
    for (int i = 0; i < 8; i++) {
        v[i] = r[lid + 32 * i];
        mx = fmaxf(mx, fmaxf(fmaxf(fabsf(v[i].x), fabsf(v[i].y)),
                             fmaxf(fabsf(v[i].z), fabsf(v[i].w))));
    }
    #pragma unroll
    for (int o = 16; o; o >>= 1) mx = fmaxf(mx, __shfl_xor_sync(0xFFFFFFFFu, mx, o));
    mx = fmaxf(mx, 1e-20f);
    float inv = 127.f / mx;
    if (lid == 0) sc[row] = mx / 127.f;
    char4* o1 = (char4*)(q1 + (size_t)row * 1024);
    char4* o2 = (char4*)(q2 + (size_t)row * 1024);
    #pragma unroll
    for (int i = 0; i < 8; i++) {
        float qv[4] = { v[i].x * inv, v[i].y * inv, v[i].z * inv, v[i].w * inv };
        int8_t c1[4], c2[4];
        #pragma unroll
        for (int j = 0; j < 4; j++) iq2(qv[j], c1[j], c2[j]);
        o1[lid + 32 * i] = make_char4(c1[0], c1[1], c1[2], c1[3]);
        o2[lid + 32 * i] = make_char4(c2[0], c2[1], c2[2], c2[3]);
    }
}

// ---------------- WrT prep (int8, fixed scale 1/127) ----------------
__global__ __launch_bounds__(256) void prep_wrt(const float* __restrict__ Wr)
{
    int h = blockIdx.x;
    for (int e = threadIdx.x; e < RFF * DK; e += 256) {
        int r = e >> 6, j = e & 63;
        float v = Wr[(size_t)h * DK * RFF + j * RFF + r];
        int8_t q1, q2;
        iq2(v * 127.f, q1, q2);
        g_wrq1[h * RFF * DK + e] = q1;
        g_wrq2[h * RFF * DK + e] = q2;
    }
}

// ---------------- v padding rows: d=64 -> ones (exact), 65..95 -> zeros ----------------
__global__ __launch_bounds__(256) void fill_vq()
{
    int bx = blockIdx.x;
    int bh = bx >> 5, dr = 64 + (bx & 31);
    char c1 = (dr == 64) ? 16 : 0;
    char c2 = (dr == 64) ? -32 : 0;
    uint32_t w1 = (uint8_t)c1; w1 |= w1 << 8; w1 |= w1 << 16;
    uint32_t w2 = (uint8_t)c2; w2 |= w2 << 8; w2 |= w2 << 16;
    size_t base = ((size_t)bh * NPAD + dr) * SEQ;
    for (int i = threadIdx.x; i < SEQ / 4; i += 256) {
        ((uint32_t*)(g_vq1 + base))[i] = w1;
        ((uint32_t*)(g_vq2 + base))[i] = w2;
    }
}

// ---------------- int8x2 IMMA GEMM (256 threads, 8 warps 2x4) ----------------
// MODE 0: dequant (+bias) -> fp32 C. MODE 3: merged QKV: q/k -> int8 fixed scale, v -> int8 transposed.
#define ISTG 32768
#define IGEMM_SMEM (2 * ISTG)

template<int MODE>
__global__ __launch_bounds__(256, 1) void gemm_i8(
    const int8_t* __restrict__ A1, const int8_t* __restrict__ A2, const float* __restrict__ sA,
    const int8_t* __restrict__ B1, const int8_t* __restrict__ B2, const float* __restrict__ sB,
    const float* __restrict__ bias, float* __restrict__ C)
{
    extern __shared__ __align__(128) char sm[];
    const int tid = threadIdx.x, wid = tid >> 5, lid = tid & 31;
    const int m0 = blockIdx.y * 128, n0 = blockIdx.x * 128;
    const int wm = (wid & 1) * 64;
    const int wn = (wid >> 1) * 32;
    const uint32_t smb = smem_u32(sm);

    int X[4][4][4], Y[4][4][4];
    #pragma unroll
    for (int i = 0; i < 4; i++)
        #pragma unroll
        for (int j = 0; j < 4; j++)
            #pragma unroll
            for (int e = 0; e < 4; e++) { X[i][j][e] = 0; Y[i][j][e] = 0; }

    auto load_stage = [&](int ci, int s) {
        const int k0 = ci * 64;
        const uint32_t sb = smb + s * ISTG;
        #pragma unroll
        for (int it = 0; it < 2; it++) {
            int t = tid + it * 256;
            int row = t >> 2, q = t & 3;
            uint32_t soff = row * 64 + ((q ^ ((row >> 1) & 3)) << 4);
            size_t ga = (size_t)(m0 + row) * DIMV + k0 + q * 16;
            size_t gb = (size_t)(n0 + row) * DIMV + k0 + q * 16;
            cpa16(sb + soff,         A1 + ga);
            cpa16(sb + 8192  + soff, A2 + ga);
            cpa16(sb + 16384 + soff, B1 + gb);
            cpa16(sb + 24576 + soff, B2 + gb);
        }
        cpa_commit();
    };

    load_stage(0, 0);

    #pragma unroll 1
    for (int ci = 0; ci < 16; ci++) {
        const int s = ci & 1;
        if (ci < 15) { load_stage(ci + 1, s ^ 1); asm volatile("cp.async.wait_group 1;"); }
        else         asm volatile("cp.async.wait_group 0;");
        __syncthreads();

        const uint32_t sb = smb + s * ISTG;
        #pragma unroll
        for (int ks = 0; ks < 2; ks++) {
            uint32_t a1f[4][4], a2f[4][4], b1f[4][2], b2f[4][2];
            #pragma unroll
            for (int mi = 0; mi < 4; mi++) {
                int row = wm + mi * 16 + (lid & 7) + ((lid >> 3) & 1) * 8;
                int q = ks * 2 + (lid >> 4);
                uint32_t off = row * 64 + ((q ^ ((row >> 1) & 3)) << 4);
                ldmx4(sb + off,        a1f[mi][0], a1f[mi][1], a1f[mi][2], a1f[mi][3]);
                ldmx4(sb + 8192 + off, a2f[mi][0], a2f[mi][1], a2f[mi][2], a2f[mi][3]);
            }
            #pragma unroll
            for (int np = 0; np < 2; np++) {
                int row = wn + np * 16 + (lid >> 4) * 8 + (lid & 7);
                int q = ks * 2 + ((lid >> 3) & 1);
                uint32_t off = row * 64 + ((q ^ ((row >> 1) & 3)) << 4);
                ldmx4(sb + 16384 + off, b1f[2*np][0], b1f[2*np][1], b1f[2*np+1][0], b1f[2*np+1][1]);
                ldmx4(sb + 24576 + off, b2f[2*np][0], b2f[2*np][1], b2f[2*np+1][0], b2f[2*np+1][1]);
            }
            #pragma unroll
            for (int mi = 0; mi < 4; mi++)
                #pragma unroll
                for (int ni = 0; ni < 4; ni++)
                    imma16832(X[mi][ni], a1f[mi], b1f[ni]);
            #pragma unroll
            for (int mi = 0; mi < 4; mi++)
                #pragma unroll
                for (int ni = 0; ni < 4; ni++)
                    imma16832(Y[mi][ni], a1f[mi], b2f[ni]);
            #pragma unroll
            for (int mi = 0; mi < 4; mi++)
                #pragma unroll
                for (int ni = 0; ni < 4; ni++)
                    imma16832(Y[mi][ni], a2f[mi], b1f[ni]);
        }
        __syncthreads();
    }

    const int g = lid >> 2, c2 = (lid & 3) * 2;
    #pragma unroll
    for (int mi = 0; mi < 4; mi++) {
        int row = m0 + wm + mi * 16 + g;
        float sa0 = sA[row], sa1 = sA[row + 8];
        #pragma unroll
        for (int ni = 0; ni < 4; ni++) {
            int col = n0 + wn + ni * 8 + c2;
            float sb0 = sB[col], sb1 = sB[col + 1];
            float r00 = sa0 * sb0 * ((float)X[mi][ni][0] + (float)Y[mi][ni][0] * (1.f/256.f));
            float r01 = sa0 * sb1 * ((float)X[mi][ni][1] + (float)Y[mi][ni][1] * (1.f/256.f));
            float r10 = sa1 * sb0 * ((float)X[mi][ni][2] + (float)Y[mi][ni][2] * (1.f/256.f));
            float r11 = sa1 * sb1 * ((float)X[mi][ni][3] + (float)Y[mi][ni][3] * (1.f/256.f));
            if (MODE == 0) {
                float b0 = bias ? bias[col] : 0.f;
                float b1 = bias ? bias[col + 1] : 0.f;
                float2 o0 = { r00 + b0, r01 + b1 };
                float2 o1 = { r10 + b0, r11 + b1 };
                *(float2*)&C[(size_t)row * DIMV + col]       = o0;
                *(float2*)&C[(size_t)(row + 8) * DIMV + col] = o1;
            } else {
                if (col < 2048) {
                    int8_t* Cq1 = (col < 1024) ? g_qq1 : g_kq1;
                    int8_t* Cq2 = (col < 1024) ? g_qq2 : g_kq2;
                    int cc = col & 1023;
                    int8_t qa1, qa2, qb1, qb2;
                    iq2(r00 * INV_SQK, qa1, qa2); iq2(r01 * INV_SQK, qb1, qb2);
                    char2 p1; p1.x = qa1; p1.y = qb1;
                    char2 p2; p2.x = qa2; p2.y = qb2;
                    *(char2*)&Cq1[(size_t)row * DIMV + cc] = p1;
                    *(char2*)&Cq2[(size_t)row * DIMV + cc] = p2;
                    iq2(r10 * INV_SQK, qa1, qa2); iq2(r11 * INV_SQK, qb1, qb2);
                    p1.x = qa1; p1.y = qb1;
                    p2.x = qa2; p2.y = qb2;
                    *(char2*)&Cq1[(size_t)(row + 8) * DIMV + cc] = p1;
                    *(char2*)&Cq2[(size_t)(row + 8) * DIMV + cc] = p2;
                } else {
                    int cc = col - 2048;
                    int hh = cc >> 6, d0 = cc & 63;
                    int b = row >> 13, n = row & 8191;
                    size_t base = ((size_t)(b * NHEADS + hh) * NPAD) * SEQ;
                    int8_t q1, q2;
                    iq2(r00 * INV_SV, q1, q2);
                    g_vq1[base + (size_t)d0 * SEQ + n] = q1;       g_vq2[base + (size_t)d0 * SEQ + n] = q2;
                    iq2(r01 * INV_SV, q1, q2);
                    g_vq1[base + (size_t)(d0+1) * SEQ + n] = q1;   g_vq2[base + (size_t)(d0+1) * SEQ + n] = q2;
                    iq2(r10 * INV_SV, q1, q2);
                    g_vq1[base + (size_t)d0 * SEQ + n + 8] = q1;   g_vq2[base + (size_t)d0 * SEQ + n + 8] = q2;
                    iq2(r11 * INV_SV, q1, q2);
                    g_vq1[base + (size_t)(d0+1) * SEQ + n + 8] = q1; g_vq2[base + (size_t)(d0+1) * SEQ + n + 8] = q2;
                }
            }
        }
    }
}

// ---------------- proj + RFF features (int8): p = q[:,h*64:] @ WrT[h]^T ----------------
#define PROJ_SMEM 32768

__global__ __launch_bounds__(256, 1) void proj_feat(const float* __restrict__ brp)
{
    extern __shared__ __align__(128) char sm[];
    const int tid = threadIdx.x, wid = tid >> 5, lid = tid & 31;
    const int m0 = blockIdx.x * 128;
    const int qk = blockIdx.y >> 4, h = blockIdx.y & 15;
    const int wm = (wid & 1) * 64, wn = (wid >> 1) * 32;
    const uint32_t smb = smem_u32(sm);

    const int8_t* Aq1 = qk ? g_kq1 : g_qq1;
    const int8_t* Aq2 = qk ? g_kq2 : g_qq2;
    const int8_t* Bq1 = g_wrq1 + h * RFF * DK;
    const int8_t* Bq2 = g_wrq2 + h * RFF * DK;

    #pragma unroll
    for (int it = 0; it < 2; it++) {
        int t = tid + it * 256;
        int row = t >> 2, q = t & 3;
        uint32_t soff = row * 64 + ((q ^ ((row >> 1) & 3)) << 4);
        size_t ga = (size_t)(m0 + row) * DIMV + h * DK + q * 16;
        size_t gb = (size_t)row * DK + q * 16;
        *(uint4*)(sm + soff)         = *(const uint4*)(Aq1 + ga);
        *(uint4*)(sm + 8192  + soff) = *(const uint4*)(Aq2 + ga);
        *(uint4*)(sm + 16384 + soff) = *(const uint4*)(Bq1 + gb);
        *(uint4*)(sm + 24576 + soff) = *(const uint4*)(Bq2 + gb);
    }
    __syncthreads();

    int X[4][4][4], Y[4][4][4];
    #pragma unroll
    for (int i = 0; i < 4; i++)
        #pragma unroll
        for (int j = 0; j < 4; j++)
            #pragma unroll
            for (int e = 0; e < 4; e++) { X[i][j][e] = 0; Y[i][j][e] = 0; }

    #pragma unroll
    for (int ks = 0; ks < 2; ks++) {
        uint32_t a1f[4][4], a2f[4][4], b1f[4][2], b2f[4][2];
        #pragma unroll
        for (int mi = 0; mi < 4; mi++) {
            int row = wm + mi * 16 + (lid & 7) + ((lid >> 3) & 1) * 8;
            int q = ks * 2 + (lid >> 4);
            uint32_t off = row * 64 + ((q ^ ((row >> 1) & 3)) << 4);
            ldmx4(smb + off,        a1f[mi][0], a1f[mi][1], a1f[mi][2], a1f[mi][3]);
            ldmx4(smb + 8192 + off, a2f[mi][0], a2f[mi][1], a2f[mi][2], a2f[mi][3]);
        }
        #pragma unroll
        for (int np = 0; np < 2; np++) {
            int row = wn + np * 16 + (lid >> 4) * 8 + (lid & 7);
            int q = ks * 2 + ((lid >> 3) & 1);
            uint32_t off = row * 64 + ((q ^ ((row >> 1) & 3)) << 4);
            ldmx4(smb + 16384 + off, b1f[2*np][0], b1f[2*np][1], b1f[2*np+1][0], b1f[2*np+1][1]);
            ldmx4(smb + 24576 + off, b2f[2*np][0], b2f[2*np][1], b2f[2*np+1][0], b2f[2*np+1][1]);
        }
        #pragma unroll
        for (int mi = 0; mi < 4; mi++)
            #pragma unroll
            for (int ni = 0; ni < 4; ni++)
                imma16832(X[mi][ni], a1f[mi], b1f[ni]);
        #pragma unroll
        for (int mi = 0; mi < 4; mi++)
            #pragma unroll
            for (int ni = 0; ni < 4; ni++)
                imma16832(Y[mi][ni], a1f[mi], b2f[ni]);
        #pragma unroll
        for (int mi = 0; mi < 4; mi++)
            #pragma unroll
            for (int ni = 0; ni < 4; ni++)
                imma16832(Y[mi][ni], a2f[mi], b1f[ni]);
    }

    const int g = lid >> 2, c2 = (lid & 3) * 2;
    #pragma unroll
    for (int mi = 0; mi < 4; mi++) {
        #pragma unroll
        for (int ni = 0; ni < 4; ni++) {
            int col = wn + ni * 8 + c2;
            float b0 = brp[h * RFF + col], b1 = brp[h * RFF + col + 1];
            #pragma unroll
            for (int half = 0; half < 2; half++) {
                int row = m0 + wm + mi * 16 + g + half * 8;
                int b = row >> 13, n = row & 8191;
                int bh = b * NHEADS + h;
                int e0 = half * 2, e1 = half * 2 + 1;
                float p0 = DEQ_P * ((float)X[mi][ni][e0] + (float)Y[mi][ni][e0] * (1.f/256.f)) + b0;
                float p1 = DEQ_P * ((float)X[mi][ni][e1] + (float)Y[mi][ni][e1] * (1.f/256.f)) + b1;
                float s0, c0, s1, c1;
                __sincosf(p0, &s0, &c0);
                __sincosf(p1, &s1, &c1);
                int8_t cq1a, cq2a, cq1b, cq2b, sq1a, sq2a, sq1b, sq2b;
                iq2(c0 * 127.f, cq1a, cq2a); iq2(c1 * 127.f, cq1b, cq2b);
                iq2(s0 * 127.f, sq1a, sq2a); iq2(s1 * 127.f, sq1b, sq2b);
                if (qk == 0) {
                    size_t base = ((size_t)bh * SEQ + n) * FEAT;
                    char2 pc1; pc1.x = cq1a; pc1.y = cq1b;
                    char2 pc2; pc2.x = cq2a; pc2.y = cq2b;
                    char2 ps1; ps1.x = sq1a; ps1.y = sq1b;
                    char2 ps2; ps2.x = sq2a; ps2.y = sq2b;
                    *(char2*)&g_qfq1[base + col]       = pc1;
                    *(char2*)&g_qfq2[base + col]       = pc2;
                    *(char2*)&g_qfq1[base + RFF + col] = ps1;
                    *(char2*)&g_qfq2[base + RFF + col] = ps2;
                } else {
                    size_t kb = ((size_t)bh * FEAT + col) * SEQ + n;
                    g_kfq1[kb] = cq1a;                      g_kfq2[kb] = cq2a;
                    g_kfq1[kb + SEQ] = cq1b;                g_kfq2[kb + SEQ] = cq2b;
                    g_kfq1[kb + (size_t)RFF*SEQ] = sq1a;    g_kfq2[kb + (size_t)RFF*SEQ] = sq2a;
                    g_kfq1[kb + (size_t)(RFF+1)*SEQ] = sq1b; g_kfq2[kb + (size_t)(RFF+1)*SEQ] = sq2b;
                }
            }
        }
    }
}

// ---------------- Kv GEMM int8 (split-K 8): C[f,d] = sum_n kf*v ----------------
#define KV_STG 28672
#define KV_SMEM (2 * KV_STG)

__global__ __launch_bounds__(256, 1) void gemm_kv()
{
    extern __shared__ __align__(128) char sm[];
    const int tid = threadIdx.x, wid = tid >> 5, lid = tid & 31;
    const int ks = blockIdx.x;
    const int bh = blockIdx.y >> 1, m2 = blockIdx.y & 1;
    const int wm = (wid & 3) * 32, wn = (wid >> 2) * 48;
    const uint32_t smb = smem_u32(sm);

    const int8_t* A1 = g_kfq1 + ((size_t)bh * FEAT + m2 * 128) * SEQ + ks * 1024;
    const int8_t* A2 = g_kfq2 + ((size_t)bh * FEAT + m2 * 128) * SEQ + ks * 1024;
    const int8_t* B1 = g_vq1 + (size_t)bh * NPAD * SEQ + ks * 1024;
    const int8_t* B2 = g_vq2 + (size_t)bh * NPAD * SEQ + ks * 1024;

    int X[2][6][4], Y[2][6][4];
    #pragma unroll
    for (int i = 0; i < 2; i++)
        #pragma unroll
        for (int j = 0; j < 6; j++)
            #pragma unroll
            for (int e = 0; e < 4; e++) { X[i][j][e] = 0; Y[i][j][e] = 0; }

    auto load_stage = [&](int ci, int s) {
        const int k0 = ci * 64;
        const uint32_t sb = smb + s * KV_STG;
        #pragma unroll
        for (int it = 0; it < 2; it++) {
            int idx = tid + it * 256;
            int row = idx >> 2, q = idx & 3;
            uint32_t soff = row * 64 + ((q ^ ((row >> 1) & 3)) << 4);
            cpa16(sb + soff,        A1 + (size_t)row * SEQ + k0 + q * 16);
            cpa16(sb + 8192 + soff, A2 + (size_t)row * SEQ + k0 + q * 16);
        }
        for (int idx = tid; idx < 384; idx += 256) {
            int row = idx >> 2, q = idx & 3;
            uint32_t soff = row * 64 + ((q ^ ((row >> 1) & 3)) << 4);
            cpa16(sb + 16384 + soff, B1 + (size_t)row * SEQ + k0 + q * 16);
            cpa16(sb + 22528 + soff, B2 + (size_t)row * SEQ + k0 + q * 16);
        }
        cpa_commit();
    };

    load_stage(0, 0);
    #pragma unroll 1
    for (int ci = 0; ci < 16; ci++) {
        const int s = ci & 1;
        if (ci < 15) { load_stage(ci + 1, s ^ 1); asm volatile("cp.async.wait_group 1;"); }
        else         asm volatile("cp.async.wait_group 0;");
        __syncthreads();
        const uint32_t sb = smb + s * KV_STG;
        #pragma unroll
        for (int k2 = 0; k2 < 2; k2++) {
            uint32_t a1f[2][4], a2f[2][4], b1f[6][2], b2f[6][2];
            #pragma unroll
            for (int mi = 0; mi < 2; mi++) {
                int row = wm + mi * 16 + (lid & 7) + ((lid >> 3) & 1) * 8;
                int q = k2 * 2 + (lid >> 4);
                uint32_t off = row * 64 + ((q ^ ((row >> 1) & 3)) << 4);
                ldmx4(sb + off,        a1f[mi][0], a1f[mi][1], a1f[mi][2], a1f[mi][3]);
                ldmx4(sb + 8192 + off, a2f[mi][0], a2f[mi][1], a2f[mi][2], a2f[mi][3]);
            }
            #pragma unroll
            for (int np = 0; np < 3; np++) {
                int row = wn + np * 16 + (lid >> 4) * 8 + (lid & 7);
                int q = k2 * 2 + ((lid >> 3) & 1);
                uint32_t off = row * 64 + ((q ^ ((row >> 1) & 3)) << 4);
                ldmx4(sb + 16384 + off, b1f[2*np][0], b1f[2*np][1], b1f[2*np+1][0], b1f[2*np+1][1]);
                ldmx4(sb + 22528 + off, b2f[2*np][0], b2f[2*np][1], b2f[2*np+1][0], b2f[2*np+1][1]);
            }
            #pragma unroll
            for (int mi = 0; mi < 2; mi++)
                #pragma unroll
                for (int ni = 0; ni < 6; ni++)
                    imma16832(X[mi][ni], a1f[mi], b1f[ni]);
            #pragma unroll
            for (int mi = 0; mi < 2; mi++)
                #pragma unroll
                for (int ni = 0; ni < 6; ni++)
                    imma16832(Y[mi][ni], a1f[mi], b2f[ni]);
            #pragma unroll
            for (int mi = 0; mi < 2; mi++)
                #pragma unroll
                for (int ni = 0; ni < 6; ni++)
                    imma16832(Y[mi][ni], a2f[mi], b1f[ni]);
        }
        __syncthreads();
    }

    const int g = lid >> 2, c2 = (lid & 3) * 2;
    #pragma unroll
    for (int mi = 0; mi < 2; mi++) {
        #pragma unroll
        for (int ni = 0; ni < 6; ni++) {
            int rl = wm + mi * 16 + g;
            int col = wn + ni * 8 + c2;
            float* dp = g_kvp + (((size_t)ks * BH + bh) * FEAT + m2 * 128 + rl) * NPAD + col;
            float2 o0 = { DEQ_KV * ((float)X[mi][ni][0] + (float)Y[mi][ni][0] * (1.f/256.f)),
                          DEQ_KV * ((float)X[mi][ni][1] + (float)Y[mi][ni][1] * (1.f/256.f)) };
            float2 o1 = { DEQ_KV * ((float)X[mi][ni][2] + (float)Y[mi][ni][2] * (1.f/256.f)),
                          DEQ_KV * ((float)X[mi][ni][3] + (float)Y[mi][ni][3] * (1.f/256.f)) };
            *(float2*)dp = o0;
            *(float2*)(dp + 8 * NPAD) = o1;
        }
    }
}

// ---------------- reduce partials + transpose + per-row quantize ----------------
__global__ __launch_bounds__(256) void kv_reduce_q()
{
    int wid = threadIdx.x >> 5, lid = threadIdx.x & 31;
    int r = blockIdx.x * 8 + wid;
    int bh = r / NPAD, d = r - bh * NPAD;
    float v[8];
    float mx = 0.f;
    #pragma unroll
    for (int i = 0; i < 8; i++) {
        int f = lid + 32 * i;
        float s = 0.f;
        #pragma unroll
        for (int ks = 0; ks < 8; ks++)
            s += g_kvp[(((size_t)ks * BH + bh) * FEAT + f) * NPAD + d];
        v[i] = s;
        mx = fmaxf(mx, fabsf(s));
    }
    #pragma unroll
    for (int o = 16; o; o >>= 1) mx = fmaxf(mx, __shfl_xor_sync(0xFFFFFFFFu, mx, o));
    mx = fmaxf(mx, 1e-20f);
    float inv = 127.f / mx;
    if (lid == 0) g_sd[r] = mx / 127.f;
    #pragma unroll
    for (int i = 0; i < 8; i++) {
        int f = lid + 32 * i;
        int8_t q1, q2;
        iq2(v[i] * inv, q1, q2);
        g_dq1[(size_t)r * FEAT + f] = q1;
        g_dq2[(size_t)r * FEAT + f] = q2;
    }
}

// ---------------- out GEMM int8: C[n,d] = sum_f qf * Dt, z scaling -> fp32 ----------------
#define OUT_SMEM (2 * KV_STG + 512)

__global__ __launch_bounds__(256, 1) void gemm_out()
{
    extern __shared__ __align__(128) char sm[];
    const int tid = threadIdx.x, wid = tid >> 5, lid = tid & 31;
    const int n0 = blockIdx.x * 128;
    const int bh = blockIdx.y;
    const int wm = (wid & 3) * 32, wn = (wid >> 2) * 48;
    const uint32_t smb = smem_u32(sm);
    float* sden = (float*)(sm + 2 * KV_STG);

    const int8_t* A1 = g_qfq1 + ((size_t)bh * SEQ + n0) * FEAT;
    const int8_t* A2 = g_qfq2 + ((size_t)bh * SEQ + n0) * FEAT;
    const int8_t* B1 = g_dq1 + (size_t)bh * NPAD * FEAT;
    const int8_t* B2 = g_dq2 + (size_t)bh * NPAD * FEAT;

    int X[2][6][4], Y[2][6][4];
    #pragma unroll
    for (int i = 0; i < 2; i++)
        #pragma unroll
        for (int j = 0; j < 6; j++)
            #pragma unroll
            for (int e = 0; e < 4; e++) { X[i][j][e] = 0; Y[i][j][e] = 0; }

    auto load_stage = [&](int ci, int s) {
        const int k0 = ci * 64;
        const uint32_t sb = smb + s * KV_STG;
        #pragma unroll
        for (int it = 0; it < 2; it++) {
            int idx = tid + it * 256;
            int row = idx >> 2, q = idx & 3;
            uint32_t soff = row * 64 + ((q ^ ((row >> 1) & 3)) << 4);
            cpa16(sb + soff,        A1 + (size_t)row * FEAT + k0 + q * 16);
            cpa16(sb + 8192 + soff, A2 + (size_t)row * FEAT + k0 + q * 16);
        }
        for (int idx = tid; idx < 384; idx += 256) {
            int row = idx >> 2, q = idx & 3;
            uint32_t soff = row * 64 + ((q ^ ((row >> 1) & 3)) << 4);
            cpa16(sb + 16384 + soff, B1 + (size_t)row * FEAT + k0 + q * 16);
            cpa16(sb + 22528 + soff, B2 + (size_t)row * FEAT + k0 + q * 16);
        }
        cpa_commit();
    };

    load_stage(0, 0);
    #pragma unroll 1
    for (int ci = 0; ci < 4; ci++) {
        const int s = ci & 1;
        if (ci < 3) { load_stage(ci + 1, s ^ 1); asm volatile("cp.async.wait_group 1;"); }
        else        asm volatile("cp.async.wait_group 0;");
        __syncthreads();
        const uint32_t sb = smb + s * KV_STG;
        #pragma unroll
        for (int k2 = 0; k2 < 2; k2++) {
            uint32_t a1f[2][4], a2f[2][4], b1f[6][2], b2f[6][2];
            #pragma unroll
            for (int mi = 0; mi < 2; mi++) {
                int row = wm + mi * 16 + (lid & 7) + ((lid >> 3) & 1) * 8;
                int q = k2 * 2 + (lid >> 4);
                uint32_t off = row * 64 + ((q ^ ((row >> 1) & 3)) << 4);
                ldmx4(sb + off,        a1f[mi][0], a1f[mi][1], a1f[mi][2], a1f[mi][3]);
                ldmx4(sb + 8192 + off, a2f[mi][0], a2f[mi][1], a2f[mi][2], a2f[mi][3]);
            }
            #pragma unroll
            for (int np = 0; np < 3; np++) {
                int row = wn + np * 16 + (lid >> 4) * 8 + (lid & 7);
                int q = k2 * 2 + ((lid >> 3) & 1);
                uint32_t off = row * 64 + ((q ^ ((row >> 1) & 3)) << 4);
                ldmx4(sb + 16384 + off, b1f[2*np][0], b1f[2*np][1], b1f[2*np+1][0], b1f[2*np+1][1]);
                ldmx4(sb + 22528 + off, b2f[2*np][0], b2f[2*np][1], b2f[2*np+1][0], b2f[2*np+1][1]);
            }
            #pragma unroll
            for (int mi = 0; mi < 2; mi++)
                #pragma unroll
                for (int ni = 0; ni < 6; ni++)
                    imma16832(X[mi][ni], a1f[mi], b1f[ni]);
            #pragma unroll
            for (int mi = 0; mi < 2; mi++)
                #pragma unroll
                for (int ni = 0; ni < 6; ni++)
                    imma16832(Y[mi][ni], a1f[mi], b2f[ni]);
            #pragma unroll
            for (int mi = 0; mi < 2; mi++)
                #pragma unroll
                for (int ni = 0; ni < 6; ni++)
                    imma16832(Y[mi][ni], a2f[mi], b1f[ni]);
        }
        __syncthreads();
    }

    const int g = lid >> 2, c2 = (lid & 3) * 2;
    if ((wid >> 2) == 1 && (lid & 3) == 0) {
        float sden_s = SF_QF * g_sd[bh * NPAD + 64];
        #pragma unroll
        for (int mi = 0; mi < 2; mi++) {
            int rl = wm + mi * 16 + g;
            sden[rl]     = sden_s * ((float)X[mi][2][0] + (float)Y[mi][2][0] * (1.f/256.f));
            sden[rl + 8] = sden_s * ((float)X[mi][2][2] + (float)Y[mi][2][2] * (1.f/256.f));
        }
    }
    __syncthreads();

    const int b = bh >> 4, h = bh & 15;
    const int nlim = ((wid >> 2) == 0) ? 6 : 2;
    #pragma unroll
    for (int mi = 0; mi < 2; mi++) {
        int rl = wm + mi * 16 + g;
        float z0 = 1.f / (sden[rl] + 1e-6f);
        float z1 = 1.f / (sden[rl + 8] + 1e-6f);
        size_t rg0 = (size_t)(b * SEQ + n0 + rl) * DIMV + h * 64;
        size_t rg1 = rg0 + 8 * DIMV;
        for (int ni = 0; ni < nlim; ni++) {
            int col = wn + ni * 8 + c2;
            float sb0 = SF_QF * g_sd[bh * NPAD + col];
            float sb1 = SF_QF * g_sd[bh * NPAD + col + 1];
            float r00 = sb0 * ((float)X[mi][ni][0] + (float)Y[mi][ni][0] * (1.f/256.f));
            float r01 = sb1 * ((float)X[mi][ni][1] + (float)Y[mi][ni][1] * (1.f/256.f));
            float r10 = sb0 * ((float)X[mi][ni][2] + (float)Y[mi][ni][2] * (1.f/256.f));
            float r11 = sb1 * ((float)X[mi][ni][3] + (float)Y[mi][ni][3] * (1.f/256.f));
            float2 o0 = { r00 * z0, r01 * z0 };
            float2 o1 = { r10 * z1, r11 * z1 };
            *(float2*)&g_af[rg0 + col] = o0;
            *(float2*)&g_af[rg1 + col] = o1;
        }
    }
}

// ---------------- launch ----------------
extern "C" void kernel_launch(void* const* d_in, const int* in_sizes, int n_in,
                              void* d_out, int out_size)
{
    const float* x  = (const float*)d_in[0];
    const float* Wq = (const float*)d_in[1];
    const float* Wk = (const float*)d_in[2];
    const float* Wv = (const float*)d_in[3];
    const float* Wp = (const float*)d_in[4];
    const float* bp = (const float*)d_in[5];
    const float* Wr = (const float*)d_in[6];
    const float* br = (const float*)d_in[7];
    float* out = (float*)d_out;

    int8_t *xq1, *xq2, *wq1, *wq2, *pq1, *pq2, *aq1, *aq2;
    float *sx, *sw, *sp, *sa, *af;
    cudaGetSymbolAddress((void**)&xq1, g_xq1); cudaGetSymbolAddress((void**)&xq2, g_xq2);
    cudaGetSymbolAddress((void**)&wq1, g_wq1); cudaGetSymbolAddress((void**)&wq2, g_wq2);
    cudaGetSymbolAddress((void**)&pq1, g_pq1); cudaGetSymbolAddress((void**)&pq2, g_pq2);
    cudaGetSymbolAddress((void**)&aq1, g_aq1); cudaGetSymbolAddress((void**)&aq2, g_aq2);
    cudaGetSymbolAddress((void**)&sx, g_sx);   cudaGetSymbolAddress((void**)&sw, g_sw);
    cudaGetSymbolAddress((void**)&sp, g_sp);   cudaGetSymbolAddress((void**)&sa, g_sa);
    cudaGetSymbolAddress((void**)&af, g_af);

    cudaFuncSetAttribute(gemm_i8<0>, cudaFuncAttributeMaxDynamicSharedMemorySize, IGEMM_SMEM);
    cudaFuncSetAttribute(gemm_i8<3>, cudaFuncAttributeMaxDynamicSharedMemorySize, IGEMM_SMEM);
    cudaFuncSetAttribute(proj_feat, cudaFuncAttributeMaxDynamicSharedMemorySize, PROJ_SMEM);
    cudaFuncSetAttribute(gemm_kv,  cudaFuncAttributeMaxDynamicSharedMemorySize, KV_SMEM);
    cudaFuncSetAttribute(gemm_out, cudaFuncAttributeMaxDynamicSharedMemorySize, OUT_SMEM);

    const int WSZ = DIMV * DIMV;

    quant_rows<<<MROWS / 8, 256>>>(x, xq1, xq2, sx, MROWS);
    quant_rows<<<DIMV / 8, 256>>>(Wq, wq1 + 0 * WSZ, wq2 + 0 * WSZ, sw + 0 * DIMV, DIMV);
    quant_rows<<<DIMV / 8, 256>>>(Wk, wq1 + 1 * WSZ, wq2 + 1 * WSZ, sw + 1 * DIMV, DIMV);
    quant_rows<<<DIMV / 8, 256>>>(Wv, wq1 + 2 * WSZ, wq2 + 2 * WSZ, sw + 2 * DIMV, DIMV);
    quant_rows<<<DIMV / 8, 256>>>(Wp, pq1, pq2, sp, DIMV);
    prep_wrt<<<NHEADS, 256>>>(Wr);
    fill_vq<<<BH * 32, 256>>>();

    // merged QKV int8 GEMM: N = 3072 (q/k int8 fixed-scale + vT int8)
    gemm_i8<3><<<dim3(3 * DIMV / 128, MROWS / 128), 256, IGEMM_SMEM>>>(
        xq1, xq2, sx, wq1, wq2, sw, nullptr, nullptr);

    proj_feat<<<dim3(MROWS / 128, 32), 256, PROJ_SMEM>>>(br);
    gemm_kv<<<dim3(8, BH * 2), 256, KV_SMEM>>>();
    kv_reduce_q<<<BH * NPAD / 8, 256>>>();
    gemm_out<<<dim3(SEQ / 128, BH), 256, OUT_SMEM>>>();

    quant_rows<<<MROWS / 8, 256>>>(af, aq1, aq2, sa, MROWS);
    gemm_i8<0><<<dim3(DIMV / 128, MROWS / 128), 256, IGEMM_SMEM>>>(
        aq1, aq2, sa, pq1, pq2, sp, bp, out);
}

// round 13
// speedup vs baseline: 1.0541x; 1.0047x over previous
#include <cuda_runtime.h>
#include <cuda_bf16.h>
#include <math.h>
#include <stdint.h>

#define DIMV 1024
#define NHEADS 16
#define DK 64
#define RFF 128
#define FEAT 256
#define BATCH 2
#define SEQ 8192
#define MROWS 16384
#define BH 32
#define NPAD 96
#define INV_SQRT_R 0.08838834764831845f

// ---------------- scratch (device globals) ----------------
__device__ int8_t g_xq1[MROWS*DIMV], g_xq2[MROWS*DIMV];
__device__ float  g_sx[MROWS];
__device__ int8_t g_wq1[3*DIMV*DIMV], g_wq2[3*DIMV*DIMV];
__device__ float  g_sw[3*DIMV];
__device__ int8_t g_pq1[DIMV*DIMV], g_pq2[DIMV*DIMV];
__device__ float  g_sp[DIMV];
__device__ int8_t g_qq1[MROWS*DIMV], g_qq2[MROWS*DIMV];
__device__ int8_t g_kq1[MROWS*DIMV], g_kq2[MROWS*DIMV];
__device__ int8_t g_wrq1[NHEADS*RFF*DK], g_wrq2[NHEADS*RFF*DK];
__device__ int8_t g_vq1[(size_t)BH*NPAD*SEQ], g_vq2[(size_t)BH*NPAD*SEQ];
__device__ int8_t g_qfq1[(size_t)BH*SEQ*FEAT], g_qfq2[(size_t)BH*SEQ*FEAT];
__device__ int8_t g_kfq1[(size_t)BH*FEAT*SEQ], g_kfq2[(size_t)BH*FEAT*SEQ];
__device__ float g_kvp[8*BH*FEAT*NPAD];
__device__ int8_t g_dq1[(size_t)BH*NPAD*FEAT], g_dq2[(size_t)BH*NPAD*FEAT];
__device__ float  g_sd[BH*NPAD];
__device__ float g_af[MROWS*DIMV];
__device__ int8_t g_aq1[MROWS*DIMV], g_aq2[MROWS*DIMV];
__device__ float  g_sa[MROWS];

#define INV_SV (127.f/8.f)
#define SF_QF (INV_SQRT_R/127.f)
#define DEQ_KV ((INV_SQRT_R/127.f)*(8.f/127.f))
#define INV_SQK (127.f/8.f)
#define DEQ_P ((8.f/127.f)*(1.f/127.f))

// ---------------- helpers ----------------
__device__ __forceinline__ uint32_t smem_u32(const void* p) {
    uint32_t a;
    asm("{ .reg .u64 t; cvta.to.shared.u64 t, %1; cvt.u32.u64 %0, t; }" : "=r"(a) : "l"(p));
    return a;
}
__device__ __forceinline__ void cpa16(uint32_t s, const void* g) {
    asm volatile("cp.async.cg.shared.global [%0], [%1], 16;" :: "r"(s), "l"(g));
}
__device__ __forceinline__ void cpa_commit() { asm volatile("cp.async.commit_group;"); }
__device__ __forceinline__ void ldmx4(uint32_t addr, uint32_t& r0, uint32_t& r1, uint32_t& r2, uint32_t& r3) {
    asm volatile("ldmatrix.sync.aligned.m8n8.x4.shared.b16 {%0,%1,%2,%3}, [%4];"
                 : "=r"(r0), "=r"(r1), "=r"(r2), "=r"(r3) : "r"(addr));
}
__device__ __forceinline__ void imma16832(int* d, const uint32_t* a, const uint32_t* b) {
    asm volatile(
        "mma.sync.aligned.m16n8k32.row.col.s32.s8.s8.s32 "
        "{%0,%1,%2,%3}, {%4,%5,%6,%7}, {%8,%9}, {%0,%1,%2,%3};"
        : "+r"(d[0]), "+r"(d[1]), "+r"(d[2]), "+r"(d[3])
        : "r"(a[0]), "r"(a[1]), "r"(a[2]), "r"(a[3]), "r"(b[0]), "r"(b[1]));
}
__device__ __forceinline__ void iq2(float qv, int8_t& q1, int8_t& q2) {
    float a1 = fminf(fmaxf(rintf(qv), -127.f), 127.f);
    float a2 = fminf(fmaxf(rintf((qv - a1) * 256.f), -127.f), 127.f);
    q1 = (int8_t)a1; q2 = (int8_t)a2;
}

// ---------------- per-row 2-digit int8 quantization ----------------
__global__ __launch_bounds__(256) void quant_rows(
    const float* __restrict__ in, int8_t* __restrict__ q1,
    int8_t* __restrict__ q2, float* __restrict__ sc, int nrows)
{
    int row = blockIdx.x * 8 + (threadIdx.x >> 5);
    if (row >= nrows) return;
    int lid = threadIdx.x & 31;
    const float4* r = (const float4*)(in + (size_t)row * 1024);
    float4 v[8];
    float mx = 0.f;
    #pragma unroll
    for (int i = 0; i < 8; i++) {
        v[i] = r[lid + 32 * i];
        mx = fmaxf(mx, fmaxf(fmaxf(fabsf(v[i].x), fabsf(v[i].y)),
                             fmaxf(fabsf(v[i].z), fabsf(v[i].w))));
    }
    #pragma unroll
    for (int o = 16; o; o >>= 1) mx = fmaxf(mx, __shfl_xor_sync(0xFFFFFFFFu, mx, o));
    mx = fmaxf(mx, 1e-20f);
    float inv = 127.f / mx;
    if (lid == 0) sc[row] = mx / 127.f;
    char4* o1 = (char4*)(q1 + (size_t)row * 1024);
    char4* o2 = (char4*)(q2 + (size_t)row * 1024);
    #pragma unroll
    for (int i = 0; i < 8; i++) {
        float qv[4] = { v[i].x * inv, v[i].y * inv, v[i].z * inv, v[i].w * inv };
        int8_t c1[4], c2[4];
        #pragma unroll
        for (int j = 0; j < 4; j++) iq2(qv[j], c1[j], c2[j]);
        o1[lid + 32 * i] = make_char4(c1[0], c1[1], c1[2], c1[3]);
        o2[lid + 32 * i] = make_char4(c2[0], c2[1], c2[2], c2[3]);
    }
}

// ---------------- WrT prep (int8, fixed scale 1/127) ----------------
__global__ __launch_bounds__(256) void prep_wrt(const float* __restrict__ Wr)
{
    int h = blockIdx.x;
    for (int e = threadIdx.x; e < RFF * DK; e += 256) {
        int r = e >> 6, j = e & 63;
        float v = Wr[(size_t)h * DK * RFF + j * RFF + r];
        int8_t q1, q2;
        iq2(v * 127.f, q1, q2);
        g_wrq1[h * RFF * DK + e] = q1;
        g_wrq2[h * RFF * DK + e] = q2;
    }
}

// ---------------- v padding rows ----------------
__global__ __launch_bounds__(256) void fill_vq()
{
    int bx = blockIdx.x;
    int bh = bx >> 5, dr = 64 + (bx & 31);
    char c1 = (dr == 64) ? 16 : 0;
    char c2 = (dr == 64) ? -32 : 0;
    uint32_t w1 = (uint8_t)c1; w1 |= w1 << 8; w1 |= w1 << 16;
    uint32_t w2 = (uint8_t)c2; w2 |= w2 << 8; w2 |= w2 << 16;
    size_t base = ((size_t)bh * NPAD + dr) * SEQ;
    for (int i = threadIdx.x; i < SEQ / 4; i += 256) {
        ((uint32_t*)(g_vq1 + base))[i] = w1;
        ((uint32_t*)(g_vq2 + base))[i] = w2;
    }
}

// ---------------- int8x2 IMMA GEMM ----------------
// MODE 0: dequant (+bias) -> fp32 C. MODE 3: merged QKV -> int8 q/k + vT, smem-staged coalesced stores.
#define ISTG 32768
#define IGEMM_SMEM (2 * ISTG)

template<int MODE>
__global__ __launch_bounds__(256, 1) void gemm_i8(
    const int8_t* __restrict__ A1, const int8_t* __restrict__ A2, const float* __restrict__ sA,
    const int8_t* __restrict__ B1, const int8_t* __restrict__ B2, const float* __restrict__ sB,
    const float* __restrict__ bias, float* __restrict__ C)
{
    extern __shared__ __align__(128) char sm[];
    const int tid = threadIdx.x, wid = tid >> 5, lid = tid & 31;
    const int m0 = blockIdx.y * 128, n0 = blockIdx.x * 128;
    const int wm = (wid & 1) * 64;
    const int wn = (wid >> 1) * 32;
    const uint32_t smb = smem_u32(sm);

    int X[4][4][4], Y[4][4][4];
    #pragma unroll
    for (int i = 0; i < 4; i++)
        #pragma unroll
        for (int j = 0; j < 4; j++)
            #pragma unroll
            for (int e = 0; e < 4; e++) { X[i][j][e] = 0; Y[i][j][e] = 0; }

    auto load_stage = [&](int ci, int s) {
        const int k0 = ci * 64;
        const uint32_t sb = smb + s * ISTG;
        #pragma unroll
        for (int it = 0; it < 2; it++) {
            int t = tid + it * 256;
            int row = t >> 2, q = t & 3;
            uint32_t soff = row * 64 + ((q ^ ((row >> 1) & 3)) << 4);
            size_t ga = (size_t)(m0 + row) * DIMV + k0 + q * 16;
            size_t gb = (size_t)(n0 + row) * DIMV + k0 + q * 16;
            cpa16(sb + soff,         A1 + ga);
            cpa16(sb + 8192  + soff, A2 + ga);
            cpa16(sb + 16384 + soff, B1 + gb);
            cpa16(sb + 24576 + soff, B2 + gb);
        }
        cpa_commit();
    };

    load_stage(0, 0);

    #pragma unroll 1
    for (int ci = 0; ci < 16; ci++) {
        const int s = ci & 1;
        if (ci < 15) { load_stage(ci + 1, s ^ 1); asm volatile("cp.async.wait_group 1;"); }
        else         asm volatile("cp.async.wait_group 0;");
        __syncthreads();

        const uint32_t sb = smb + s * ISTG;
        #pragma unroll
        for (int ks = 0; ks < 2; ks++) {
            uint32_t a1f[4][4], a2f[4][4], b1f[4][2], b2f[4][2];
            #pragma unroll
            for (int mi = 0; mi < 4; mi++) {
                int row = wm + mi * 16 + (lid & 7) + ((lid >> 3) & 1) * 8;
                int q = ks * 2 + (lid >> 4);
                uint32_t off = row * 64 + ((q ^ ((row >> 1) & 3)) << 4);
                ldmx4(sb + off,        a1f[mi][0], a1f[mi][1], a1f[mi][2], a1f[mi][3]);
                ldmx4(sb + 8192 + off, a2f[mi][0], a2f[mi][1], a2f[mi][2], a2f[mi][3]);
            }
            #pragma unroll
            for (int np = 0; np < 2; np++) {
                int row = wn + np * 16 + (lid >> 4) * 8 + (lid & 7);
                int q = ks * 2 + ((lid >> 3) & 1);
                uint32_t off = row * 64 + ((q ^ ((row >> 1) & 3)) << 4);
                ldmx4(sb + 16384 + off, b1f[2*np][0], b1f[2*np][1], b1f[2*np+1][0], b1f[2*np+1][1]);
                ldmx4(sb + 24576 + off, b2f[2*np][0], b2f[2*np][1], b2f[2*np+1][0], b2f[2*np+1][1]);
            }
            #pragma unroll
            for (int mi = 0; mi < 4; mi++)
                #pragma unroll
                for (int ni = 0; ni < 4; ni++)
                    imma16832(X[mi][ni], a1f[mi], b1f[ni]);
            #pragma unroll
            for (int mi = 0; mi < 4; mi++)
                #pragma unroll
                for (int ni = 0; ni < 4; ni++)
                    imma16832(Y[mi][ni], a1f[mi], b2f[ni]);
            #pragma unroll
            for (int mi = 0; mi < 4; mi++)
                #pragma unroll
                for (int ni = 0; ni < 4; ni++)
                    imma16832(Y[mi][ni], a2f[mi], b1f[ni]);
        }
        __syncthreads();
    }

    const int g = lid >> 2, c2 = (lid & 3) * 2;
    if (MODE == 0) {
        #pragma unroll
        for (int mi = 0; mi < 4; mi++) {
            int row = m0 + wm + mi * 16 + g;
            float sa0 = sA[row], sa1 = sA[row + 8];
            #pragma unroll
            for (int ni = 0; ni < 4; ni++) {
                int col = n0 + wn + ni * 8 + c2;
                float sb0 = sB[col], sb1 = sB[col + 1];
                float r00 = sa0 * sb0 * ((float)X[mi][ni][0] + (float)Y[mi][ni][0] * (1.f/256.f));
                float r01 = sa0 * sb1 * ((float)X[mi][ni][1] + (float)Y[mi][ni][1] * (1.f/256.f));
                float r10 = sa1 * sb0 * ((float)X[mi][ni][2] + (float)Y[mi][ni][2] * (1.f/256.f));
                float r11 = sa1 * sb1 * ((float)X[mi][ni][3] + (float)Y[mi][ni][3] * (1.f/256.f));
                float b0 = bias ? bias[col] : 0.f;
                float b1 = bias ? bias[col + 1] : 0.f;
                float2 o0 = { r00 + b0, r01 + b1 };
                float2 o1 = { r10 + b0, r11 + b1 };
                *(float2*)&C[(size_t)row * DIMV + col]       = o0;
                *(float2*)&C[(size_t)(row + 8) * DIMV + col] = o1;
            }
        }
    } else {
        // smem-staged int8 epilogue: s1/s2 are 16KB tiles (digit 1, digit 2)
        int8_t* s1 = (int8_t*)sm;
        int8_t* s2 = (int8_t*)sm + 16384;
        const bool isv = (n0 >= 2048);
        #pragma unroll
        for (int mi = 0; mi < 4; mi++) {
            int rowg = m0 + wm + mi * 16 + g;
            float sa0 = sA[rowg], sa1 = sA[rowg + 8];
            int rl0 = wm + mi * 16 + g, rl1 = rl0 + 8;
            #pragma unroll
            for (int ni = 0; ni < 4; ni++) {
                int cl = wn + ni * 8 + c2;
                float sb0 = sB[n0 + cl], sb1 = sB[n0 + cl + 1];
                float scale = isv ? INV_SV : INV_SQK;
                float r00 = sa0 * sb0 * ((float)X[mi][ni][0] + (float)Y[mi][ni][0] * (1.f/256.f)) * scale;
                float r01 = sa0 * sb1 * ((float)X[mi][ni][1] + (float)Y[mi][ni][1] * (1.f/256.f)) * scale;
                float r10 = sa1 * sb0 * ((float)X[mi][ni][2] + (float)Y[mi][ni][2] * (1.f/256.f)) * scale;
                float r11 = sa1 * sb1 * ((float)X[mi][ni][3] + (float)Y[mi][ni][3] * (1.f/256.f)) * scale;
                int8_t qa1, qa2, qb1, qb2;
                if (!isv) {
                    // [row][col] layout
                    iq2(r00, qa1, qa2); iq2(r01, qb1, qb2);
                    s1[rl0 * 128 + cl] = qa1; s1[rl0 * 128 + cl + 1] = qb1;
                    s2[rl0 * 128 + cl] = qa2; s2[rl0 * 128 + cl + 1] = qb2;
                    iq2(r10, qa1, qa2); iq2(r11, qb1, qb2);
                    s1[rl1 * 128 + cl] = qa1; s1[rl1 * 128 + cl + 1] = qb1;
                    s2[rl1 * 128 + cl] = qa2; s2[rl1 * 128 + cl + 1] = qb2;
                } else {
                    // transposed [col][row] layout
                    iq2(r00, qa1, qa2);
                    s1[cl * 128 + rl0] = qa1;       s2[cl * 128 + rl0] = qa2;
                    iq2(r01, qa1, qa2);
                    s1[(cl+1) * 128 + rl0] = qa1;   s2[(cl+1) * 128 + rl0] = qa2;
                    iq2(r10, qa1, qa2);
                    s1[cl * 128 + rl1] = qa1;       s2[cl * 128 + rl1] = qa2;
                    iq2(r11, qa1, qa2);
                    s1[(cl+1) * 128 + rl1] = qa1;   s2[(cl+1) * 128 + rl1] = qa2;
                }
            }
        }
        __syncthreads();
        if (!isv) {
            int8_t* Cq1 = (n0 < 1024) ? g_qq1 : g_kq1;
            int8_t* Cq2 = (n0 < 1024) ? g_qq2 : g_kq2;
            const int cc0 = n0 & 1023;
            #pragma unroll
            for (int it = 0; it < 4; it++) {
                int idx = tid + it * 256;          // 0..1023
                int row = idx >> 3, off = (idx & 7) * 16;
                size_t ga = (size_t)(m0 + row) * DIMV + cc0 + off;
                *(uint4*)&Cq1[ga] = *(uint4*)&s1[row * 128 + off];
                *(uint4*)&Cq2[ga] = *(uint4*)&s2[row * 128 + off];
            }
        } else {
            const int b = m0 >> 13, nseq = m0 & 8191;
            #pragma unroll
            for (int it = 0; it < 4; it++) {
                int idx = tid + it * 256;          // 0..1023
                int col = idx >> 3, off = (idx & 7) * 16;
                int ccg = (n0 - 2048) + col;
                int hh = ccg >> 6, d0 = ccg & 63;
                size_t ga = (((size_t)(b * NHEADS + hh) * NPAD) + d0) * SEQ + nseq + off;
                *(uint4*)&g_vq1[ga] = *(uint4*)&s1[col * 128 + off];
                *(uint4*)&g_vq2[ga] = *(uint4*)&s2[col * 128 + off];
            }
        }
    }
}

// ---------------- proj + RFF features (int8), smem-staged coalesced stores ----------------
#define PROJ_SMEM 65536

__global__ __launch_bounds__(256, 1) void proj_feat(const float* __restrict__ brp)
{
    extern __shared__ __align__(128) char sm[];
    const int tid = threadIdx.x, wid = tid >> 5, lid = tid & 31;
    const int m0 = blockIdx.x * 128;
    const int qk = blockIdx.y >> 4, h = blockIdx.y & 15;
    const int wm = (wid & 1) * 64, wn = (wid >> 1) * 32;
    const uint32_t smb = smem_u32(sm);

    const int8_t* Aq1 = qk ? g_kq1 : g_qq1;
    const int8_t* Aq2 = qk ? g_kq2 : g_qq2;
    const int8_t* Bq1 = g_wrq1 + h * RFF * DK;
    const int8_t* Bq2 = g_wrq2 + h * RFF * DK;

    #pragma unroll
    for (int it = 0; it < 2; it++) {
        int t = tid + it * 256;
        int row = t >> 2, q = t & 3;
        uint32_t soff = row * 64 + ((q ^ ((row >> 1) & 3)) << 4);
        size_t ga = (size_t)(m0 + row) * DIMV + h * DK + q * 16;
        size_t gb = (size_t)row * DK + q * 16;
        *(uint4*)(sm + soff)         = *(const uint4*)(Aq1 + ga);
        *(uint4*)(sm + 8192  + soff) = *(const uint4*)(Aq2 + ga);
        *(uint4*)(sm + 16384 + soff) = *(const uint4*)(Bq1 + gb);
        *(uint4*)(sm + 24576 + soff) = *(const uint4*)(Bq2 + gb);
    }
    __syncthreads();

    int X[4][4][4], Y[4][4][4];
    #pragma unroll
    for (int i = 0; i < 4; i++)
        #pragma unroll
        for (int j = 0; j < 4; j++)
            #pragma unroll
            for (int e = 0; e < 4; e++) { X[i][j][e] = 0; Y[i][j][e] = 0; }

    #pragma unroll
    for (int ks = 0; ks < 2; ks++) {
        uint32_t a1f[4][4], a2f[4][4], b1f[4][2], b2f[4][2];
        #pragma unroll
        for (int mi = 0; mi < 4; mi++) {
            int row = wm + mi * 16 + (lid & 7) + ((lid >> 3) & 1) * 8;
            int q = ks * 2 + (lid >> 4);
            uint32_t off = row * 64 + ((q ^ ((row >> 1) & 3)) << 4);
            ldmx4(smb + off,        a1f[mi][0], a1f[mi][1], a1f[mi][2], a1f[mi][3]);
            ldmx4(smb + 8192 + off, a2f[mi][0], a2f[mi][1], a2f[mi][2], a2f[mi][3]);
        }
        #pragma unroll
        for (int np = 0; np < 2; np++) {
            int row = wn + np * 16 + (lid >> 4) * 8 + (lid & 7);
            int q = ks * 2 + ((lid >> 3) & 1);
            uint32_t off = row * 64 + ((q ^ ((row >> 1) & 3)) << 4);
            ldmx4(smb + 16384 + off, b1f[2*np][0], b1f[2*np][1], b1f[2*np+1][0], b1f[2*np+1][1]);
            ldmx4(smb + 24576 + off, b2f[2*np][0], b2f[2*np][1], b2f[2*np+1][0], b2f[2*np+1][1]);
        }
        #pragma unroll
        for (int mi = 0; mi < 4; mi++)
            #pragma unroll
            for (int ni = 0; ni < 4; ni++)
                imma16832(X[mi][ni], a1f[mi], b1f[ni]);
        #pragma unroll
        for (int mi = 0; mi < 4; mi++)
            #pragma unroll
            for (int ni = 0; ni < 4; ni++)
                imma16832(Y[mi][ni], a1f[mi], b2f[ni]);
        #pragma unroll
        for (int mi = 0; mi < 4; mi++)
            #pragma unroll
            for (int ni = 0; ni < 4; ni++)
                imma16832(Y[mi][ni], a2f[mi], b1f[ni]);
    }

    __syncthreads();   // inputs consumed; reuse smem for epilogue staging

    // s1/s2: 32KB per digit. qk==0: [n(128)][f(256)].  qk==1: [f(256)][n(128)].
    int8_t* s1 = (int8_t*)sm;
    int8_t* s2 = (int8_t*)sm + 32768;

    const int g = lid >> 2, c2 = (lid & 3) * 2;
    #pragma unroll
    for (int mi = 0; mi < 4; mi++) {
        #pragma unroll
        for (int ni = 0; ni < 4; ni++) {
            int col = wn + ni * 8 + c2;
            float b0 = brp[h * RFF + col], b1 = brp[h * RFF + col + 1];
            #pragma unroll
            for (int half = 0; half < 2; half++) {
                int nl = wm + mi * 16 + g + half * 8;
                int e0 = half * 2, e1 = half * 2 + 1;
                float p0 = DEQ_P * ((float)X[mi][ni][e0] + (float)Y[mi][ni][e0] * (1.f/256.f)) + b0;
                float p1 = DEQ_P * ((float)X[mi][ni][e1] + (float)Y[mi][ni][e1] * (1.f/256.f)) + b1;
                float s0, c0, s1v, c1;
                __sincosf(p0, &s0, &c0);
                __sincosf(p1, &s1v, &c1);
                int8_t cq1a, cq2a, cq1b, cq2b, sq1a, sq2a, sq1b, sq2b;
                iq2(c0 * 127.f, cq1a, cq2a); iq2(c1 * 127.f, cq1b, cq2b);
                iq2(s0 * 127.f, sq1a, sq2a); iq2(s1v * 127.f, sq1b, sq2b);
                if (qk == 0) {
                    int base = nl * 256;
                    s1[base + col] = cq1a;       s1[base + col + 1] = cq1b;
                    s2[base + col] = cq2a;       s2[base + col + 1] = cq2b;
                    s1[base + RFF + col] = sq1a; s1[base + RFF + col + 1] = sq1b;
                    s2[base + RFF + col] = sq2a; s2[base + RFF + col + 1] = sq2b;
                } else {
                    s1[col * 128 + nl] = cq1a;         s2[col * 128 + nl] = cq2a;
                    s1[(col+1) * 128 + nl] = cq1b;     s2[(col+1) * 128 + nl] = cq2b;
                    s1[(RFF+col) * 128 + nl] = sq1a;   s2[(RFF+col) * 128 + nl] = sq2a;
                    s1[(RFF+col+1) * 128 + nl] = sq1b; s2[(RFF+col+1) * 128 + nl] = sq2b;
                }
            }
        }
    }
    __syncthreads();

    const int b = m0 >> 13, nseq = m0 & 8191;
    const int bh = b * NHEADS + h;
    if (qk == 0) {
        #pragma unroll
        for (int it = 0; it < 8; it++) {
            int idx = tid + it * 256;           // 0..2047
            int n = idx >> 4, off = (idx & 15) * 16;
            size_t ga = ((size_t)bh * SEQ + nseq + n) * FEAT + off;
            *(uint4*)&g_qfq1[ga] = *(uint4*)&s1[n * 256 + off];
            *(uint4*)&g_qfq2[ga] = *(uint4*)&s2[n * 256 + off];
        }
    } else {
        #pragma unroll
        for (int it = 0; it < 8; it++) {
            int idx = tid + it * 256;           // 0..2047
            int f = idx >> 3, off = (idx & 7) * 16;
            size_t ga = ((size_t)bh * FEAT + f) * SEQ + nseq + off;
            *(uint4*)&g_kfq1[ga] = *(uint4*)&s1[f * 128 + off];
            *(uint4*)&g_kfq2[ga] = *(uint4*)&s2[f * 128 + off];
        }
    }
}

// ---------------- Kv GEMM int8 (split-K 8) ----------------
#define KV_STG 28672
#define KV_SMEM (2 * KV_STG)

__global__ __launch_bounds__(256, 1) void gemm_kv()
{
    extern __shared__ __align__(128) char sm[];
    const int tid = threadIdx.x, wid = tid >> 5, lid = tid & 31;
    const int ks = blockIdx.x;
    const int bh = blockIdx.y >> 1, m2 = blockIdx.y & 1;
    const int wm = (wid & 3) * 32, wn = (wid >> 2) * 48;
    const uint32_t smb = smem_u32(sm);

    const int8_t* A1 = g_kfq1 + ((size_t)bh * FEAT + m2 * 128) * SEQ + ks * 1024;
    const int8_t* A2 = g_kfq2 + ((size_t)bh * FEAT + m2 * 128) * SEQ + ks * 1024;
    const int8_t* B1 = g_vq1 + (size_t)bh * NPAD * SEQ + ks * 1024;
    const int8_t* B2 = g_vq2 + (size_t)bh * NPAD * SEQ + ks * 1024;

    int X[2][6][4], Y[2][6][4];
    #pragma unroll
    for (int i = 0; i < 2; i++)
        #pragma unroll
        for (int j = 0; j < 6; j++)
            #pragma unroll
            for (int e = 0; e < 4; e++) { X[i][j][e] = 0; Y[i][j][e] = 0; }

    auto load_stage = [&](int ci, int s) {
        const int k0 = ci * 64;
        const uint32_t sb = smb + s * KV_STG;
        #pragma unroll
        for (int it = 0; it < 2; it++) {
            int idx = tid + it * 256;
            int row = idx >> 2, q = idx & 3;
            uint32_t soff = row * 64 + ((q ^ ((row >> 1) & 3)) << 4);
            cpa16(sb + soff,        A1 + (size_t)row * SEQ + k0 + q * 16);
            cpa16(sb + 8192 + soff, A2 + (size_t)row * SEQ + k0 + q * 16);
        }
        for (int idx = tid; idx < 384; idx += 256) {
            int row = idx >> 2, q = idx & 3;
            uint32_t soff = row * 64 + ((q ^ ((row >> 1) & 3)) << 4);
            cpa16(sb + 16384 + soff, B1 + (size_t)row * SEQ + k0 + q * 16);
            cpa16(sb + 22528 + soff, B2 + (size_t)row * SEQ + k0 + q * 16);
        }
        cpa_commit();
    };

    load_stage(0, 0);
    #pragma unroll 1
    for (int ci = 0; ci < 16; ci++) {
        const int s = ci & 1;
        if (ci < 15) { load_stage(ci + 1, s ^ 1); asm volatile("cp.async.wait_group 1;"); }
        else         asm volatile("cp.async.wait_group 0;");
        __syncthreads();
        const uint32_t sb = smb + s * KV_STG;
        #pragma unroll
        for (int k2 = 0; k2 < 2; k2++) {
            uint32_t a1f[2][4], a2f[2][4], b1f[6][2], b2f[6][2];
            #pragma unroll
            for (int mi = 0; mi < 2; mi++) {
                int row = wm + mi * 16 + (lid & 7) + ((lid >> 3) & 1) * 8;
                int q = k2 * 2 + (lid >> 4);
                uint32_t off = row * 64 + ((q ^ ((row >> 1) & 3)) << 4);
                ldmx4(sb + off,        a1f[mi][0], a1f[mi][1], a1f[mi][2], a1f[mi][3]);
                ldmx4(sb + 8192 + off, a2f[mi][0], a2f[mi][1], a2f[mi][2], a2f[mi][3]);
            }
            #pragma unroll
            for (int np = 0; np < 3; np++) {
                int row = wn + np * 16 + (lid >> 4) * 8 + (lid & 7);
                int q = k2 * 2 + ((lid >> 3) & 1);
                uint32_t off = row * 64 + ((q ^ ((row >> 1) & 3)) << 4);
                ldmx4(sb + 16384 + off, b1f[2*np][0], b1f[2*np][1], b1f[2*np+1][0], b1f[2*np+1][1]);
                ldmx4(sb + 22528 + off, b2f[2*np][0], b2f[2*np][1], b2f[2*np+1][0], b2f[2*np+1][1]);
            }
            #pragma unroll
            for (int mi = 0; mi < 2; mi++)
                #pragma unroll
                for (int ni = 0; ni < 6; ni++)
                    imma16832(X[mi][ni], a1f[mi], b1f[ni]);
            #pragma unroll
            for (int mi = 0; mi < 2; mi++)
                #pragma unroll
                for (int ni = 0; ni < 6; ni++)
                    imma16832(Y[mi][ni], a1f[mi], b2f[ni]);
            #pragma unroll
            for (int mi = 0; mi < 2; mi++)
                #pragma unroll
                for (int ni = 0; ni < 6; ni++)
                    imma16832(Y[mi][ni], a2f[mi], b1f[ni]);
        }
        __syncthreads();
    }

    const int g = lid >> 2, c2 = (lid & 3) * 2;
    #pragma unroll
    for (int mi = 0; mi < 2; mi++) {
        #pragma unroll
        for (int ni = 0; ni < 6; ni++) {
            int rl = wm + mi * 16 + g;
            int col = wn + ni * 8 + c2;
            float* dp = g_kvp + (((size_t)ks * BH + bh) * FEAT + m2 * 128 + rl) * NPAD + col;
            float2 o0 = { DEQ_KV * ((float)X[mi][ni][0] + (float)Y[mi][ni][0] * (1.f/256.f)),
                          DEQ_KV * ((float)X[mi][ni][1] + (float)Y[mi][ni][1] * (1.f/256.f)) };
            float2 o1 = { DEQ_KV * ((float)X[mi][ni][2] + (float)Y[mi][ni][2] * (1.f/256.f)),
                          DEQ_KV * ((float)X[mi][ni][3] + (float)Y[mi][ni][3] * (1.f/256.f)) };
            *(float2*)dp = o0;
            *(float2*)(dp + 8 * NPAD) = o1;
        }
    }
}

// ---------------- reduce partials + transpose + per-row quantize ----------------
__global__ __launch_bounds__(256) void kv_reduce_q()
{
    int wid = threadIdx.x >> 5, lid = threadIdx.x & 31;
    int r = blockIdx.x * 8 + wid;
    int bh = r / NPAD, d = r - bh * NPAD;
    float v[8];
    float mx = 0.f;
    #pragma unroll
    for (int i = 0; i < 8; i++) {
        int f = lid + 32 * i;
        float s = 0.f;
        #pragma unroll
        for (int ks = 0; ks < 8; ks++)
            s += g_kvp[(((size_t)ks * BH + bh) * FEAT + f) * NPAD + d];
        v[i] = s;
        mx = fmaxf(mx, fabsf(s));
    }
    #pragma unroll
    for (int o = 16; o; o >>= 1) mx = fmaxf(mx, __shfl_xor_sync(0xFFFFFFFFu, mx, o));
    mx = fmaxf(mx, 1e-20f);
    float inv = 127.f / mx;
    if (lid == 0) g_sd[r] = mx / 127.f;
    #pragma unroll
    for (int i = 0; i < 8; i++) {
        int f = lid + 32 * i;
        int8_t q1, q2;
        iq2(v[i] * inv, q1, q2);
        g_dq1[(size_t)r * FEAT + f] = q1;
        g_dq2[(size_t)r * FEAT + f] = q2;
    }
}

// ---------------- out GEMM int8 -> fp32 af ----------------
#define OUT_SMEM (2 * KV_STG + 512)

__global__ __launch_bounds__(256, 1) void gemm_out()
{
    extern __shared__ __align__(128) char sm[];
    const int tid = threadIdx.x, wid = tid >> 5, lid = tid & 31;
    const int n0 = blockIdx.x * 128;
    const int bh = blockIdx.y;
    const int wm = (wid & 3) * 32, wn = (wid >> 2) * 48;
    const uint32_t smb = smem_u32(sm);
    float* sden = (float*)(sm + 2 * KV_STG);

    const int8_t* A1 = g_qfq1 + ((size_t)bh * SEQ + n0) * FEAT;
    const int8_t* A2 = g_qfq2 + ((size_t)bh * SEQ + n0) * FEAT;
    const int8_t* B1 = g_dq1 + (size_t)bh * NPAD * FEAT;
    const int8_t* B2 = g_dq2 + (size_t)bh * NPAD * FEAT;

    int X[2][6][4], Y[2][6][4];
    #pragma unroll
    for (int i = 0; i < 2; i++)
        #pragma unroll
        for (int j = 0; j < 6; j++)
            #pragma unroll
            for (int e = 0; e < 4; e++) { X[i][j][e] = 0; Y[i][j][e] = 0; }

    auto load_stage = [&](int ci, int s) {
        const int k0 = ci * 64;
        const uint32_t sb = smb + s * KV_STG;
        #pragma unroll
        for (int it = 0; it < 2; it++) {
            int idx = tid + it * 256;
            int row = idx >> 2, q = idx & 3;
            uint32_t soff = row * 64 + ((q ^ ((row >> 1) & 3)) << 4);
            cpa16(sb + soff,        A1 + (size_t)row * FEAT + k0 + q * 16);
            cpa16(sb + 8192 + soff, A2 + (size_t)row * FEAT + k0 + q * 16);
        }
        for (int idx = tid; idx < 384; idx += 256) {
            int row = idx >> 2, q = idx & 3;
            uint32_t soff = row * 64 + ((q ^ ((row >> 1) & 3)) << 4);
            cpa16(sb + 16384 + soff, B1 + (size_t)row * FEAT + k0 + q * 16);
            cpa16(sb + 22528 + soff, B2 + (size_t)row * FEAT + k0 + q * 16);
        }
        cpa_commit();
    };

    load_stage(0, 0);
    #pragma unroll 1
    for (int ci = 0; ci < 4; ci++) {
        const int s = ci & 1;
        if (ci < 3) { load_stage(ci + 1, s ^ 1); asm volatile("cp.async.wait_group 1;"); }
        else        asm volatile("cp.async.wait_group 0;");
        __syncthreads();
        const uint32_t sb = smb + s * KV_STG;
        #pragma unroll
        for (int k2 = 0; k2 < 2; k2++) {
            uint32_t a1f[2][4], a2f[2][4], b1f[6][2], b2f[6][2];
            #pragma unroll
            for (int mi = 0; mi < 2; mi++) {
                int row = wm + mi * 16 + (lid & 7) + ((lid >> 3) & 1) * 8;
                int q = k2 * 2 + (lid >> 4);
                uint32_t off = row * 64 + ((q ^ ((row >> 1) & 3)) << 4);
                ldmx4(sb + off,        a1f[mi][0], a1f[mi][1], a1f[mi][2], a1f[mi][3]);
                ldmx4(sb + 8192 + off, a2f[mi][0], a2f[mi][1], a2f[mi][2], a2f[mi][3]);
            }
            #pragma unroll
            for (int np = 0; np < 3; np++) {
                int row = wn + np * 16 + (lid >> 4) * 8 + (lid & 7);
                int q = k2 * 2 + ((lid >> 3) & 1);
                uint32_t off = row * 64 + ((q ^ ((row >> 1) & 3)) << 4);
                ldmx4(sb + 16384 + off, b1f[2*np][0], b1f[2*np][1], b1f[2*np+1][0], b1f[2*np+1][1]);
                ldmx4(sb + 22528 + off, b2f[2*np][0], b2f[2*np][1], b2f[2*np+1][0], b2f[2*np+1][1]);
            }
            #pragma unroll
            for (int mi = 0; mi < 2; mi++)
                #pragma unroll
                for (int ni = 0; ni < 6; ni++)
                    imma16832(X[mi][ni], a1f[mi], b1f[ni]);
            #pragma unroll
            for (int mi = 0; mi < 2; mi++)
                #pragma unroll
                for (int ni = 0; ni < 6; ni++)
                    imma16832(Y[mi][ni], a1f[mi], b2f[ni]);
            #pragma unroll
            for (int mi = 0; mi < 2; mi++)
                #pragma unroll
                for (int ni = 0; ni < 6; ni++)
                    imma16832(Y[mi][ni], a2f[mi], b1f[ni]);
        }
        __syncthreads();
    }

    const int g = lid >> 2, c2 = (lid & 3) * 2;
    if ((wid >> 2) == 1 && (lid & 3) == 0) {
        float sden_s = SF_QF * g_sd[bh * NPAD + 64];
        #pragma unroll
        for (int mi = 0; mi < 2; mi++) {
            int rl = wm + mi * 16 + g;
            sden[rl]     = sden_s * ((float)X[mi][2][0] + (float)Y[mi][2][0] * (1.f/256.f));
            sden[rl + 8] = sden_s * ((float)X[mi][2][2] + (float)Y[mi][2][2] * (1.f/256.f));
        }
    }
    __syncthreads();

    const int b = bh >> 4, h = bh & 15;
    const int nlim = ((wid >> 2) == 0) ? 6 : 2;
    #pragma unroll
    for (int mi = 0; mi < 2; mi++) {
        int rl = wm + mi * 16 + g;
        float z0 = 1.f / (sden[rl] + 1e-6f);
        float z1 = 1.f / (sden[rl + 8] + 1e-6f);
        size_t rg0 = (size_t)(b * SEQ + n0 + rl) * DIMV + h * 64;
        size_t rg1 = rg0 + 8 * DIMV;
        for (int ni = 0; ni < nlim; ni++) {
            int col = wn + ni * 8 + c2;
            float sb0 = SF_QF * g_sd[bh * NPAD + col];
            float sb1 = SF_QF * g_sd[bh * NPAD + col + 1];
            float r00 = sb0 * ((float)X[mi][ni][0] + (float)Y[mi][ni][0] * (1.f/256.f));
            float r01 = sb1 * ((float)X[mi][ni][1] + (float)Y[mi][ni][1] * (1.f/256.f));
            float r10 = sb0 * ((float)X[mi][ni][2] + (float)Y[mi][ni][2] * (1.f/256.f));
            float r11 = sb1 * ((float)X[mi][ni][3] + (float)Y[mi][ni][3] * (1.f/256.f));
            float2 o0 = { r00 * z0, r01 * z0 };
            float2 o1 = { r10 * z1, r11 * z1 };
            *(float2*)&g_af[rg0 + col] = o0;
            *(float2*)&g_af[rg1 + col] = o1;
        }
    }
}

// ---------------- launch ----------------
extern "C" void kernel_launch(void* const* d_in, const int* in_sizes, int n_in,
                              void* d_out, int out_size)
{
    const float* x  = (const float*)d_in[0];
    const float* Wq = (const float*)d_in[1];
    const float* Wk = (const float*)d_in[2];
    const float* Wv = (const float*)d_in[3];
    const float* Wp = (const float*)d_in[4];
    const float* bp = (const float*)d_in[5];
    const float* Wr = (const float*)d_in[6];
    const float* br = (const float*)d_in[7];
    float* out = (float*)d_out;

    int8_t *xq1, *xq2, *wq1, *wq2, *pq1, *pq2, *aq1, *aq2;
    float *sx, *sw, *sp, *sa, *af;
    cudaGetSymbolAddress((void**)&xq1, g_xq1); cudaGetSymbolAddress((void**)&xq2, g_xq2);
    cudaGetSymbolAddress((void**)&wq1, g_wq1); cudaGetSymbolAddress((void**)&wq2, g_wq2);
    cudaGetSymbolAddress((void**)&pq1, g_pq1); cudaGetSymbolAddress((void**)&pq2, g_pq2);
    cudaGetSymbolAddress((void**)&aq1, g_aq1); cudaGetSymbolAddress((void**)&aq2, g_aq2);
    cudaGetSymbolAddress((void**)&sx, g_sx);   cudaGetSymbolAddress((void**)&sw, g_sw);
    cudaGetSymbolAddress((void**)&sp, g_sp);   cudaGetSymbolAddress((void**)&sa, g_sa);
    cudaGetSymbolAddress((void**)&af, g_af);

    cudaFuncSetAttribute(gemm_i8<0>, cudaFuncAttributeMaxDynamicSharedMemorySize, IGEMM_SMEM);
    cudaFuncSetAttribute(gemm_i8<3>, cudaFuncAttributeMaxDynamicSharedMemorySize, IGEMM_SMEM);
    cudaFuncSetAttribute(proj_feat, cudaFuncAttributeMaxDynamicSharedMemorySize, PROJ_SMEM);
    cudaFuncSetAttribute(gemm_kv,  cudaFuncAttributeMaxDynamicSharedMemorySize, KV_SMEM);
    cudaFuncSetAttribute(gemm_out, cudaFuncAttributeMaxDynamicSharedMemorySize, OUT_SMEM);

    const int WSZ = DIMV * DIMV;

    quant_rows<<<MROWS / 8, 256>>>(x, xq1, xq2, sx, MROWS);
    quant_rows<<<DIMV / 8, 256>>>(Wq, wq1 + 0 * WSZ, wq2 + 0 * WSZ, sw + 0 * DIMV, DIMV);
    quant_rows<<<DIMV / 8, 256>>>(Wk, wq1 + 1 * WSZ, wq2 + 1 * WSZ, sw + 1 * DIMV, DIMV);
    quant_rows<<<DIMV / 8, 256>>>(Wv, wq1 + 2 * WSZ, wq2 + 2 * WSZ, sw + 2 * DIMV, DIMV);
    quant_rows<<<DIMV / 8, 256>>>(Wp, pq1, pq2, sp, DIMV);
    prep_wrt<<<NHEADS, 256>>>(Wr);
    fill_vq<<<BH * 32, 256>>>();

    gemm_i8<3><<<dim3(3 * DIMV / 128, MROWS / 128), 256, IGEMM_SMEM>>>(
        xq1, xq2, sx, wq1, wq2, sw, nullptr, nullptr);

    proj_feat<<<dim3(MROWS / 128, 32), 256, PROJ_SMEM>>>(br);
    gemm_kv<<<dim3(8, BH * 2), 256, KV_SMEM>>>();
    kv_reduce_q<<<BH * NPAD / 8, 256>>>();
    gemm_out<<<dim3(SEQ / 128, BH), 256, OUT_SMEM>>>();

    quant_rows<<<MROWS / 8, 256>>>(af, aq1, aq2, sa, MROWS);
    gemm_i8<0><<<dim3(DIMV / 128, MROWS / 128), 256, IGEMM_SMEM>>>(
        aq1, aq2, sa, pq1, pq2, sp, bp, out);
}

// round 14
// speedup vs baseline: 1.1248x; 1.0670x over previous
#include <cuda_runtime.h>
#include <cuda_bf16.h>
#include <math.h>
#include <stdint.h>

#define DIMV 1024
#define NHEADS 16
#define DK 64
#define RFF 128
#define FEAT 256
#define BATCH 2
#define SEQ 8192
#define MROWS 16384
#define BH 32
#define NPAD 96
#define INV_SQRT_R 0.08838834764831845f

// ---------------- scratch (device globals) ----------------
__device__ int8_t g_xq1[MROWS*DIMV], g_xq2[MROWS*DIMV];
__device__ float  g_sx[MROWS];
__device__ int8_t g_wq1[3*DIMV*DIMV], g_wq2[3*DIMV*DIMV];
__device__ float  g_sw[3*DIMV];
__device__ int8_t g_pq1[DIMV*DIMV], g_pq2[DIMV*DIMV];
__device__ float  g_sp[DIMV];
__device__ int8_t g_qq1[MROWS*DIMV], g_qq2[MROWS*DIMV];
__device__ int8_t g_kq1[MROWS*DIMV], g_kq2[MROWS*DIMV];
__device__ int8_t g_wrq1[NHEADS*RFF*DK], g_wrq2[NHEADS*RFF*DK];
__device__ int8_t g_vq1[(size_t)BH*NPAD*SEQ], g_vq2[(size_t)BH*NPAD*SEQ];
__device__ int8_t g_qfq1[(size_t)BH*SEQ*FEAT], g_qfq2[(size_t)BH*SEQ*FEAT];
__device__ int8_t g_kfq1[(size_t)BH*FEAT*SEQ], g_kfq2[(size_t)BH*FEAT*SEQ];
__device__ float g_kvp[8*BH*FEAT*NPAD];
__device__ int8_t g_dq1[(size_t)BH*NPAD*FEAT], g_dq2[(size_t)BH*NPAD*FEAT];
__device__ float  g_sd[BH*NPAD];
__device__ float g_af[MROWS*DIMV];
__device__ int8_t g_aq1[MROWS*DIMV], g_aq2[MROWS*DIMV];
__device__ float  g_sa[MROWS];

#define INV_SV (127.f/8.f)
#define SF_QF (INV_SQRT_R/127.f)
#define DEQ_KV ((INV_SQRT_R/127.f)*(8.f/127.f))
#define INV_SQK (127.f/8.f)
#define DEQ_P ((8.f/127.f)*(1.f/127.f))

// ---------------- helpers ----------------
__device__ __forceinline__ uint32_t smem_u32(const void* p) {
    uint32_t a;
    asm("{ .reg .u64 t; cvta.to.shared.u64 t, %1; cvt.u32.u64 %0, t; }" : "=r"(a) : "l"(p));
    return a;
}
__device__ __forceinline__ void cpa16(uint32_t s, const void* g) {
    asm volatile("cp.async.cg.shared.global [%0], [%1], 16;" :: "r"(s), "l"(g));
}
__device__ __forceinline__ void cpa_commit() { asm volatile("cp.async.commit_group;"); }
__device__ __forceinline__ void ldmx4(uint32_t addr, uint32_t& r0, uint32_t& r1, uint32_t& r2, uint32_t& r3) {
    asm volatile("ldmatrix.sync.aligned.m8n8.x4.shared.b16 {%0,%1,%2,%3}, [%4];"
                 : "=r"(r0), "=r"(r1), "=r"(r2), "=r"(r3) : "r"(addr));
}
__device__ __forceinline__ void imma16832(int* d, const uint32_t* a, const uint32_t* b) {
    asm volatile(
        "mma.sync.aligned.m16n8k32.row.col.s32.s8.s8.s32 "
        "{%0,%1,%2,%3}, {%4,%5,%6,%7}, {%8,%9}, {%0,%1,%2,%3};"
        : "+r"(d[0]), "+r"(d[1]), "+r"(d[2]), "+r"(d[3])
        : "r"(a[0]), "r"(a[1]), "r"(a[2]), "r"(a[3]), "r"(b[0]), "r"(b[1]));
}
__device__ __forceinline__ void iq2(float qv, int8_t& q1, int8_t& q2) {
    float a1 = fminf(fmaxf(rintf(qv), -127.f), 127.f);
    float a2 = fminf(fmaxf(rintf((qv - a1) * 256.f), -127.f), 127.f);
    q1 = (int8_t)a1; q2 = (int8_t)a2;
}

// ---------------- per-row 2-digit int8 quantization ----------------
__global__ __launch_bounds__(256) void quant_rows(
    const float* __restrict__ in, int8_t* __restrict__ q1,
    int8_t* __restrict__ q2, float* __restrict__ sc, int nrows)
{
    int row = blockIdx.x * 8 + (threadIdx.x >> 5);
    if (row >= nrows) return;
    int lid = threadIdx.x & 31;
    const float4* r = (const float4*)(in + (size_t)row * 1024);
    float4 v[8];
    float mx = 0.f;
    #pragma unroll
    for (int i = 0; i < 8; i++) {
        v[i] = r[lid + 32 * i];
        mx = fmaxf(mx, fmaxf(fmaxf(fabsf(v[i].x), fabsf(v[i].y)),
                             fmaxf(fabsf(v[i].z), fabsf(v[i].w))));
    }
    #pragma unroll
    for (int o = 16; o; o >>= 1) mx = fmaxf(mx, __shfl_xor_sync(0xFFFFFFFFu, mx, o));
    mx = fmaxf(mx, 1e-20f);
    float inv = 127.f / mx;
    if (lid == 0) sc[row] = mx / 127.f;
    char4* o1 = (char4*)(q1 + (size_t)row * 1024);
    char4* o2 = (char4*)(q2 + (size_t)row * 1024);
    #pragma unroll
    for (int i = 0; i < 8; i++) {
        float qv[4] = { v[i].x * inv, v[i].y * inv, v[i].z * inv, v[i].w * inv };
        int8_t c1[4], c2[4];
        #pragma unroll
        for (int j = 0; j < 4; j++) iq2(qv[j], c1[j], c2[j]);
        o1[lid + 32 * i] = make_char4(c1[0], c1[1], c1[2], c1[3]);
        o2[lid + 32 * i] = make_char4(c2[0], c2[1], c2[2], c2[3]);
    }
}

// ---------------- WrT prep (int8, fixed scale 1/127) ----------------
__global__ __launch_bounds__(256) void prep_wrt(const float* __restrict__ Wr)
{
    int h = blockIdx.x;
    for (int e = threadIdx.x; e < RFF * DK; e += 256) {
        int r = e >> 6, j = e & 63;
        float v = Wr[(size_t)h * DK * RFF + j * RFF + r];
        int8_t q1, q2;
        iq2(v * 127.f, q1, q2);
        g_wrq1[h * RFF * DK + e] = q1;
        g_wrq2[h * RFF * DK + e] = q2;
    }
}

// ---------------- v padding rows ----------------
__global__ __launch_bounds__(256) void fill_vq()
{
    int bx = blockIdx.x;
    int bh = bx >> 5, dr = 64 + (bx & 31);
    char c1 = (dr == 64) ? 16 : 0;
    char c2 = (dr == 64) ? -32 : 0;
    uint32_t w1 = (uint8_t)c1; w1 |= w1 << 8; w1 |= w1 << 16;
    uint32_t w2 = (uint8_t)c2; w2 |= w2 << 8; w2 |= w2 << 16;
    size_t base = ((size_t)bh * NPAD + dr) * SEQ;
    for (int i = threadIdx.x; i < SEQ / 4; i += 256) {
        ((uint32_t*)(g_vq1 + base))[i] = w1;
        ((uint32_t*)(g_vq2 + base))[i] = w2;
    }
}

// ---------------- int8x2 IMMA GEMM: 128x64 tile, 2 CTAs/SM ----------------
// 8 warps as 4(m) x 2(n): 32x32 warp tiles. Stage: A1 8K | A2 8K | B1 4K | B2 4K = 24KB.
// MODE 0: dequant (+bias) -> fp32 C. MODE 3: merged QKV -> int8 q/k + vT (smem-staged).
#define ISTG 24576
#define IGEMM_SMEM (2 * ISTG)

template<int MODE>
__global__ __launch_bounds__(256, 2) void gemm_i8(
    const int8_t* __restrict__ A1, const int8_t* __restrict__ A2, const float* __restrict__ sA,
    const int8_t* __restrict__ B1, const int8_t* __restrict__ B2, const float* __restrict__ sB,
    const float* __restrict__ bias, float* __restrict__ C)
{
    extern __shared__ __align__(128) char sm[];
    const int tid = threadIdx.x, wid = tid >> 5, lid = tid & 31;
    const int m0 = blockIdx.y * 128, n0 = blockIdx.x * 64;
    const int wm = (wid & 3) * 32;      // 4 m-positions
    const int wn = (wid >> 2) * 32;     // 2 n-positions
    const uint32_t smb = smem_u32(sm);

    int X[2][4][4], Y[2][4][4];
    #pragma unroll
    for (int i = 0; i < 2; i++)
        #pragma unroll
        for (int j = 0; j < 4; j++)
            #pragma unroll
            for (int e = 0; e < 4; e++) { X[i][j][e] = 0; Y[i][j][e] = 0; }

    auto load_stage = [&](int ci, int s) {
        const int k0 = ci * 64;
        const uint32_t sb = smb + s * ISTG;
        #pragma unroll
        for (int it = 0; it < 2; it++) {
            int t = tid + it * 256;               // 0..511  (A rows)
            int row = t >> 2, q = t & 3;
            uint32_t soff = row * 64 + ((q ^ ((row >> 1) & 3)) << 4);
            size_t ga = (size_t)(m0 + row) * DIMV + k0 + q * 16;
            cpa16(sb + soff,        A1 + ga);
            cpa16(sb + 8192 + soff, A2 + ga);
        }
        {
            int row = tid >> 2, q = tid & 3;      // 0..63   (B rows)
            uint32_t soff = row * 64 + ((q ^ ((row >> 1) & 3)) << 4);
            size_t gb = (size_t)(n0 + row) * DIMV + k0 + q * 16;
            cpa16(sb + 16384 + soff, B1 + gb);
            cpa16(sb + 20480 + soff, B2 + gb);
        }
        cpa_commit();
    };

    load_stage(0, 0);

    #pragma unroll 1
    for (int ci = 0; ci < 16; ci++) {
        const int s = ci & 1;
        if (ci < 15) { load_stage(ci + 1, s ^ 1); asm volatile("cp.async.wait_group 1;"); }
        else         asm volatile("cp.async.wait_group 0;");
        __syncthreads();

        const uint32_t sb = smb + s * ISTG;
        #pragma unroll
        for (int ks = 0; ks < 2; ks++) {
            uint32_t a1f[2][4], a2f[2][4], b1f[4][2], b2f[4][2];
            #pragma unroll
            for (int mi = 0; mi < 2; mi++) {
                int row = wm + mi * 16 + (lid & 7) + ((lid >> 3) & 1) * 8;
                int q = ks * 2 + (lid >> 4);
                uint32_t off = row * 64 + ((q ^ ((row >> 1) & 3)) << 4);
                ldmx4(sb + off,        a1f[mi][0], a1f[mi][1], a1f[mi][2], a1f[mi][3]);
                ldmx4(sb + 8192 + off, a2f[mi][0], a2f[mi][1], a2f[mi][2], a2f[mi][3]);
            }
            #pragma unroll
            for (int np = 0; np < 2; np++) {
                int row = wn + np * 16 + (lid >> 4) * 8 + (lid & 7);
                int q = ks * 2 + ((lid >> 3) & 1);
                uint32_t off = row * 64 + ((q ^ ((row >> 1) & 3)) << 4);
                ldmx4(sb + 16384 + off, b1f[2*np][0], b1f[2*np][1], b1f[2*np+1][0], b1f[2*np+1][1]);
                ldmx4(sb + 20480 + off, b2f[2*np][0], b2f[2*np][1], b2f[2*np+1][0], b2f[2*np+1][1]);
            }
            #pragma unroll
            for (int mi = 0; mi < 2; mi++)
                #pragma unroll
                for (int ni = 0; ni < 4; ni++)
                    imma16832(X[mi][ni], a1f[mi], b1f[ni]);
            #pragma unroll
            for (int mi = 0; mi < 2; mi++)
                #pragma unroll
                for (int ni = 0; ni < 4; ni++)
                    imma16832(Y[mi][ni], a1f[mi], b2f[ni]);
            #pragma unroll
            for (int mi = 0; mi < 2; mi++)
                #pragma unroll
                for (int ni = 0; ni < 4; ni++)
                    imma16832(Y[mi][ni], a2f[mi], b1f[ni]);
        }
        __syncthreads();
    }

    const int g = lid >> 2, c2 = (lid & 3) * 2;
    if (MODE == 0) {
        #pragma unroll
        for (int mi = 0; mi < 2; mi++) {
            int row = m0 + wm + mi * 16 + g;
            float sa0 = sA[row], sa1 = sA[row + 8];
            #pragma unroll
            for (int ni = 0; ni < 4; ni++) {
                int col = n0 + wn + ni * 8 + c2;
                float sb0 = sB[col], sb1 = sB[col + 1];
                float r00 = sa0 * sb0 * ((float)X[mi][ni][0] + (float)Y[mi][ni][0] * (1.f/256.f));
                float r01 = sa0 * sb1 * ((float)X[mi][ni][1] + (float)Y[mi][ni][1] * (1.f/256.f));
                float r10 = sa1 * sb0 * ((float)X[mi][ni][2] + (float)Y[mi][ni][2] * (1.f/256.f));
                float r11 = sa1 * sb1 * ((float)X[mi][ni][3] + (float)Y[mi][ni][3] * (1.f/256.f));
                float b0 = bias ? bias[col] : 0.f;
                float b1 = bias ? bias[col + 1] : 0.f;
                float2 o0 = { r00 + b0, r01 + b1 };
                float2 o1 = { r10 + b0, r11 + b1 };
                *(float2*)&C[(size_t)row * DIMV + col]       = o0;
                *(float2*)&C[(size_t)(row + 8) * DIMV + col] = o1;
            }
        }
    } else {
        // smem-staged int8 epilogue: s1/s2 8KB tiles
        int8_t* s1 = (int8_t*)sm;
        int8_t* s2 = (int8_t*)sm + 8192;
        const bool isv = (n0 >= 2048);
        #pragma unroll
        for (int mi = 0; mi < 2; mi++) {
            int rowg = m0 + wm + mi * 16 + g;
            float sa0 = sA[rowg], sa1 = sA[rowg + 8];
            int rl0 = wm + mi * 16 + g, rl1 = rl0 + 8;
            #pragma unroll
            for (int ni = 0; ni < 4; ni++) {
                int cl = wn + ni * 8 + c2;
                float sb0 = sB[n0 + cl], sb1 = sB[n0 + cl + 1];
                float scale = isv ? INV_SV : INV_SQK;
                float r00 = sa0 * sb0 * ((float)X[mi][ni][0] + (float)Y[mi][ni][0] * (1.f/256.f)) * scale;
                float r01 = sa0 * sb1 * ((float)X[mi][ni][1] + (float)Y[mi][ni][1] * (1.f/256.f)) * scale;
                float r10 = sa1 * sb0 * ((float)X[mi][ni][2] + (float)Y[mi][ni][2] * (1.f/256.f)) * scale;
                float r11 = sa1 * sb1 * ((float)X[mi][ni][3] + (float)Y[mi][ni][3] * (1.f/256.f)) * scale;
                int8_t qa1, qa2, qb1, qb2;
                if (!isv) {
                    iq2(r00, qa1, qa2); iq2(r01, qb1, qb2);
                    s1[rl0 * 64 + cl] = qa1; s1[rl0 * 64 + cl + 1] = qb1;
                    s2[rl0 * 64 + cl] = qa2; s2[rl0 * 64 + cl + 1] = qb2;
                    iq2(r10, qa1, qa2); iq2(r11, qb1, qb2);
                    s1[rl1 * 64 + cl] = qa1; s1[rl1 * 64 + cl + 1] = qb1;
                    s2[rl1 * 64 + cl] = qa2; s2[rl1 * 64 + cl + 1] = qb2;
                } else {
                    iq2(r00, qa1, qa2);
                    s1[cl * 128 + rl0] = qa1;       s2[cl * 128 + rl0] = qa2;
                    iq2(r01, qa1, qa2);
                    s1[(cl+1) * 128 + rl0] = qa1;   s2[(cl+1) * 128 + rl0] = qa2;
                    iq2(r10, qa1, qa2);
                    s1[cl * 128 + rl1] = qa1;       s2[cl * 128 + rl1] = qa2;
                    iq2(r11, qa1, qa2);
                    s1[(cl+1) * 128 + rl1] = qa1;   s2[(cl+1) * 128 + rl1] = qa2;
                }
            }
        }
        __syncthreads();
        if (!isv) {
            int8_t* Cq1 = (n0 < 1024) ? g_qq1 : g_kq1;
            int8_t* Cq2 = (n0 < 1024) ? g_qq2 : g_kq2;
            const int cc0 = n0 & 1023;
            #pragma unroll
            for (int it = 0; it < 2; it++) {
                int idx = tid + it * 256;          // 0..511
                int row = idx >> 2, off = (idx & 3) * 16;
                size_t ga = (size_t)(m0 + row) * DIMV + cc0 + off;
                *(uint4*)&Cq1[ga] = *(uint4*)&s1[row * 64 + off];
                *(uint4*)&Cq2[ga] = *(uint4*)&s2[row * 64 + off];
            }
        } else {
            const int b = m0 >> 13, nseq = m0 & 8191;
            #pragma unroll
            for (int it = 0; it < 2; it++) {
                int idx = tid + it * 256;          // 0..511
                int col = idx >> 3, off = (idx & 7) * 16;
                int ccg = (n0 - 2048) + col;
                int hh = ccg >> 6, d0 = ccg & 63;
                size_t ga = (((size_t)(b * NHEADS + hh) * NPAD) + d0) * SEQ + nseq + off;
                *(uint4*)&g_vq1[ga] = *(uint4*)&s1[col * 128 + off];
                *(uint4*)&g_vq2[ga] = *(uint4*)&s2[col * 128 + off];
            }
        }
    }
}

// ---------------- proj + RFF features (int8), smem-staged coalesced stores ----------------
#define PROJ_SMEM 65536

__global__ __launch_bounds__(256, 1) void proj_feat(const float* __restrict__ brp)
{
    extern __shared__ __align__(128) char sm[];
    const int tid = threadIdx.x, wid = tid >> 5, lid = tid & 31;
    const int m0 = blockIdx.x * 128;
    const int qk = blockIdx.y >> 4, h = blockIdx.y & 15;
    const int wm = (wid & 1) * 64, wn = (wid >> 1) * 32;
    const uint32_t smb = smem_u32(sm);

    const int8_t* Aq1 = qk ? g_kq1 : g_qq1;
    const int8_t* Aq2 = qk ? g_kq2 : g_qq2;
    const int8_t* Bq1 = g_wrq1 + h * RFF * DK;
    const int8_t* Bq2 = g_wrq2 + h * RFF * DK;

    #pragma unroll
    for (int it = 0; it < 2; it++) {
        int t = tid + it * 256;
        int row = t >> 2, q = t & 3;
        uint32_t soff = row * 64 + ((q ^ ((row >> 1) & 3)) << 4);
        size_t ga = (size_t)(m0 + row) * DIMV + h * DK + q * 16;
        size_t gb = (size_t)row * DK + q * 16;
        *(uint4*)(sm + soff)         = *(const uint4*)(Aq1 + ga);
        *(uint4*)(sm + 8192  + soff) = *(const uint4*)(Aq2 + ga);
        *(uint4*)(sm + 16384 + soff) = *(const uint4*)(Bq1 + gb);
        *(uint4*)(sm + 24576 + soff) = *(const uint4*)(Bq2 + gb);
    }
    __syncthreads();

    int X[4][4][4], Y[4][4][4];
    #pragma unroll
    for (int i = 0; i < 4; i++)
        #pragma unroll
        for (int j = 0; j < 4; j++)
            #pragma unroll
            for (int e = 0; e < 4; e++) { X[i][j][e] = 0; Y[i][j][e] = 0; }

    #pragma unroll
    for (int ks = 0; ks < 2; ks++) {
        uint32_t a1f[4][4], a2f[4][4], b1f[4][2], b2f[4][2];
        #pragma unroll
        for (int mi = 0; mi < 4; mi++) {
            int row = wm + mi * 16 + (lid & 7) + ((lid >> 3) & 1) * 8;
            int q = ks * 2 + (lid >> 4);
            uint32_t off = row * 64 + ((q ^ ((row >> 1) & 3)) << 4);
            ldmx4(smb + off,        a1f[mi][0], a1f[mi][1], a1f[mi][2], a1f[mi][3]);
            ldmx4(smb + 8192 + off, a2f[mi][0], a2f[mi][1], a2f[mi][2], a2f[mi][3]);
        }
        #pragma unroll
        for (int np = 0; np < 2; np++) {
            int row = wn + np * 16 + (lid >> 4) * 8 + (lid & 7);
            int q = ks * 2 + ((lid >> 3) & 1);
            uint32_t off = row * 64 + ((q ^ ((row >> 1) & 3)) << 4);
            ldmx4(smb + 16384 + off, b1f[2*np][0], b1f[2*np][1], b1f[2*np+1][0], b1f[2*np+1][1]);
            ldmx4(smb + 24576 + off, b2f[2*np][0], b2f[2*np][1], b2f[2*np+1][0], b2f[2*np+1][1]);
        }
        #pragma unroll
        for (int mi = 0; mi < 4; mi++)
            #pragma unroll
            for (int ni = 0; ni < 4; ni++)
                imma16832(X[mi][ni], a1f[mi], b1f[ni]);
        #pragma unroll
        for (int mi = 0; mi < 4; mi++)
            #pragma unroll
            for (int ni = 0; ni < 4; ni++)
                imma16832(Y[mi][ni], a1f[mi], b2f[ni]);
        #pragma unroll
        for (int mi = 0; mi < 4; mi++)
            #pragma unroll
            for (int ni = 0; ni < 4; ni++)
                imma16832(Y[mi][ni], a2f[mi], b1f[ni]);
    }

    __syncthreads();   // inputs consumed; reuse smem for epilogue staging

    int8_t* s1 = (int8_t*)sm;
    int8_t* s2 = (int8_t*)sm + 32768;

    const int g = lid >> 2, c2 = (lid & 3) * 2;
    #pragma unroll
    for (int mi = 0; mi < 4; mi++) {
        #pragma unroll
        for (int ni = 0; ni < 4; ni++) {
            int col = wn + ni * 8 + c2;
            float b0 = brp[h * RFF + col], b1 = brp[h * RFF + col + 1];
            #pragma unroll
            for (int half = 0; half < 2; half++) {
                int nl = wm + mi * 16 + g + half * 8;
                int e0 = half * 2, e1 = half * 2 + 1;
                float p0 = DEQ_P * ((float)X[mi][ni][e0] + (float)Y[mi][ni][e0] * (1.f/256.f)) + b0;
                float p1 = DEQ_P * ((float)X[mi][ni][e1] + (float)Y[mi][ni][e1] * (1.f/256.f)) + b1;
                float s0, c0, s1v, c1;
                __sincosf(p0, &s0, &c0);
                __sincosf(p1, &s1v, &c1);
                int8_t cq1a, cq2a, cq1b, cq2b, sq1a, sq2a, sq1b, sq2b;
                iq2(c0 * 127.f, cq1a, cq2a); iq2(c1 * 127.f, cq1b, cq2b);
                iq2(s0 * 127.f, sq1a, sq2a); iq2(s1v * 127.f, sq1b, sq2b);
                if (qk == 0) {
                    int base = nl * 256;
                    s1[base + col] = cq1a;       s1[base + col + 1] = cq1b;
                    s2[base + col] = cq2a;       s2[base + col + 1] = cq2b;
                    s1[base + RFF + col] = sq1a; s1[base + RFF + col + 1] = sq1b;
                    s2[base + RFF + col] = sq2a; s2[base + RFF + col + 1] = sq2b;
                } else {
                    s1[col * 128 + nl] = cq1a;         s2[col * 128 + nl] = cq2a;
                    s1[(col+1) * 128 + nl] = cq1b;     s2[(col+1) * 128 + nl] = cq2b;
                    s1[(RFF+col) * 128 + nl] = sq1a;   s2[(RFF+col) * 128 + nl] = sq2a;
                    s1[(RFF+col+1) * 128 + nl] = sq1b; s2[(RFF+col+1) * 128 + nl] = sq2b;
                }
            }
        }
    }
    __syncthreads();

    const int b = m0 >> 13, nseq = m0 & 8191;
    const int bh = b * NHEADS + h;
    if (qk == 0) {
        #pragma unroll
        for (int it = 0; it < 8; it++) {
            int idx = tid + it * 256;
            int n = idx >> 4, off = (idx & 15) * 16;
            size_t ga = ((size_t)bh * SEQ + nseq + n) * FEAT + off;
            *(uint4*)&g_qfq1[ga] = *(uint4*)&s1[n * 256 + off];
            *(uint4*)&g_qfq2[ga] = *(uint4*)&s2[n * 256 + off];
        }
    } else {
        #pragma unroll
        for (int it = 0; it < 8; it++) {
            int idx = tid + it * 256;
            int f = idx >> 3, off = (idx & 7) * 16;
            size_t ga = ((size_t)bh * FEAT + f) * SEQ + nseq + off;
            *(uint4*)&g_kfq1[ga] = *(uint4*)&s1[f * 128 + off];
            *(uint4*)&g_kfq2[ga] = *(uint4*)&s2[f * 128 + off];
        }
    }
}

// ---------------- Kv GEMM int8 (split-K 8) ----------------
#define KV_STG 28672
#define KV_SMEM (2 * KV_STG)

__global__ __launch_bounds__(256, 1) void gemm_kv()
{
    extern __shared__ __align__(128) char sm[];
    const int tid = threadIdx.x, wid = tid >> 5, lid = tid & 31;
    const int ks = blockIdx.x;
    const int bh = blockIdx.y >> 1, m2 = blockIdx.y & 1;
    const int wm = (wid & 3) * 32, wn = (wid >> 2) * 48;
    const uint32_t smb = smem_u32(sm);

    const int8_t* A1 = g_kfq1 + ((size_t)bh * FEAT + m2 * 128) * SEQ + ks * 1024;
    const int8_t* A2 = g_kfq2 + ((size_t)bh * FEAT + m2 * 128) * SEQ + ks * 1024;
    const int8_t* B1 = g_vq1 + (size_t)bh * NPAD * SEQ + ks * 1024;
    const int8_t* B2 = g_vq2 + (size_t)bh * NPAD * SEQ + ks * 1024;

    int X[2][6][4], Y[2][6][4];
    #pragma unroll
    for (int i = 0; i < 2; i++)
        #pragma unroll
        for (int j = 0; j < 6; j++)
            #pragma unroll
            for (int e = 0; e < 4; e++) { X[i][j][e] = 0; Y[i][j][e] = 0; }

    auto load_stage = [&](int ci, int s) {
        const int k0 = ci * 64;
        const uint32_t sb = smb + s * KV_STG;
        #pragma unroll
        for (int it = 0; it < 2; it++) {
            int idx = tid + it * 256;
            int row = idx >> 2, q = idx & 3;
            uint32_t soff = row * 64 + ((q ^ ((row >> 1) & 3)) << 4);
            cpa16(sb + soff,        A1 + (size_t)row * SEQ + k0 + q * 16);
            cpa16(sb + 8192 + soff, A2 + (size_t)row * SEQ + k0 + q * 16);
        }
        for (int idx = tid; idx < 384; idx += 256) {
            int row = idx >> 2, q = idx & 3;
            uint32_t soff = row * 64 + ((q ^ ((row >> 1) & 3)) << 4);
            cpa16(sb + 16384 + soff, B1 + (size_t)row * SEQ + k0 + q * 16);
            cpa16(sb + 22528 + soff, B2 + (size_t)row * SEQ + k0 + q * 16);
        }
        cpa_commit();
    };

    load_stage(0, 0);
    #pragma unroll 1
    for (int ci = 0; ci < 16; ci++) {
        const int s = ci & 1;
        if (ci < 15) { load_stage(ci + 1, s ^ 1); asm volatile("cp.async.wait_group 1;"); }
        else         asm volatile("cp.async.wait_group 0;");
        __syncthreads();
        const uint32_t sb = smb + s * KV_STG;
        #pragma unroll
        for (int k2 = 0; k2 < 2; k2++) {
            uint32_t a1f[2][4], a2f[2][4], b1f[6][2], b2f[6][2];
            #pragma unroll
            for (int mi = 0; mi < 2; mi++) {
                int row = wm + mi * 16 + (lid & 7) + ((lid >> 3) & 1) * 8;
                int q = k2 * 2 + (lid >> 4);
                uint32_t off = row * 64 + ((q ^ ((row >> 1) & 3)) << 4);
                ldmx4(sb + off,        a1f[mi][0], a1f[mi][1], a1f[mi][2], a1f[mi][3]);
                ldmx4(sb + 8192 + off, a2f[mi][0], a2f[mi][1], a2f[mi][2], a2f[mi][3]);
            }
            #pragma unroll
            for (int np = 0; np < 3; np++) {
                int row = wn + np * 16 + (lid >> 4) * 8 + (lid & 7);
                int q = k2 * 2 + ((lid >> 3) & 1);
                uint32_t off = row * 64 + ((q ^ ((row >> 1) & 3)) << 4);
                ldmx4(sb + 16384 + off, b1f[2*np][0], b1f[2*np][1], b1f[2*np+1][0], b1f[2*np+1][1]);
                ldmx4(sb + 22528 + off, b2f[2*np][0], b2f[2*np][1], b2f[2*np+1][0], b2f[2*np+1][1]);
            }
            #pragma unroll
            for (int mi = 0; mi < 2; mi++)
                #pragma unroll
                for (int ni = 0; ni < 6; ni++)
                    imma16832(X[mi][ni], a1f[mi], b1f[ni]);
            #pragma unroll
            for (int mi = 0; mi < 2; mi++)
                #pragma unroll
                for (int ni = 0; ni < 6; ni++)
                    imma16832(Y[mi][ni], a1f[mi], b2f[ni]);
            #pragma unroll
            for (int mi = 0; mi < 2; mi++)
                #pragma unroll
                for (int ni = 0; ni < 6; ni++)
                    imma16832(Y[mi][ni], a2f[mi], b1f[ni]);
        }
        __syncthreads();
    }

    const int g = lid >> 2, c2 = (lid & 3) * 2;
    #pragma unroll
    for (int mi = 0; mi < 2; mi++) {
        #pragma unroll
        for (int ni = 0; ni < 6; ni++) {
            int rl = wm + mi * 16 + g;
            int col = wn + ni * 8 + c2;
            float* dp = g_kvp + (((size_t)ks * BH + bh) * FEAT + m2 * 128 + rl) * NPAD + col;
            float2 o0 = { DEQ_KV * ((float)X[mi][ni][0] + (float)Y[mi][ni][0] * (1.f/256.f)),
                          DEQ_KV * ((float)X[mi][ni][1] + (float)Y[mi][ni][1] * (1.f/256.f)) };
            float2 o1 = { DEQ_KV * ((float)X[mi][ni][2] + (float)Y[mi][ni][2] * (1.f/256.f)),
                          DEQ_KV * ((float)X[mi][ni][3] + (float)Y[mi][ni][3] * (1.f/256.f)) };
            *(float2*)dp = o0;
            *(float2*)(dp + 8 * NPAD) = o1;
        }
    }
}

// ---------------- reduce partials + transpose + per-row quantize ----------------
__global__ __launch_bounds__(256) void kv_reduce_q()
{
    int wid = threadIdx.x >> 5, lid = threadIdx.x & 31;
    int r = blockIdx.x * 8 + wid;
    int bh = r / NPAD, d = r - bh * NPAD;
    float v[8];
    float mx = 0.f;
    #pragma unroll
    for (int i = 0; i < 8; i++) {
        int f = lid + 32 * i;
        float s = 0.f;
        #pragma unroll
        for (int ks = 0; ks < 8; ks++)
            s += g_kvp[(((size_t)ks * BH + bh) * FEAT + f) * NPAD + d];
        v[i] = s;
        mx = fmaxf(mx, fabsf(s));
    }
    #pragma unroll
    for (int o = 16; o; o >>= 1) mx = fmaxf(mx, __shfl_xor_sync(0xFFFFFFFFu, mx, o));
    mx = fmaxf(mx, 1e-20f);
    float inv = 127.f / mx;
    if (lid == 0) g_sd[r] = mx / 127.f;
    #pragma unroll
    for (int i = 0; i < 8; i++) {
        int f = lid + 32 * i;
        int8_t q1, q2;
        iq2(v[i] * inv, q1, q2);
        g_dq1[(size_t)r * FEAT + f] = q1;
        g_dq2[(size_t)r * FEAT + f] = q2;
    }
}

// ---------------- out GEMM int8 -> fp32 af ----------------
#define OUT_SMEM (2 * KV_STG + 512)

__global__ __launch_bounds__(256, 1) void gemm_out()
{
    extern __shared__ __align__(128) char sm[];
    const int tid = threadIdx.x, wid = tid >> 5, lid = tid & 31;
    const int n0 = blockIdx.x * 128;
    const int bh = blockIdx.y;
    const int wm = (wid & 3) * 32, wn = (wid >> 2) * 48;
    const uint32_t smb = smem_u32(sm);
    float* sden = (float*)(sm + 2 * KV_STG);

    const int8_t* A1 = g_qfq1 + ((size_t)bh * SEQ + n0) * FEAT;
    const int8_t* A2 = g_qfq2 + ((size_t)bh * SEQ + n0) * FEAT;
    const int8_t* B1 = g_dq1 + (size_t)bh * NPAD * FEAT;
    const int8_t* B2 = g_dq2 + (size_t)bh * NPAD * FEAT;

    int X[2][6][4], Y[2][6][4];
    #pragma unroll
    for (int i = 0; i < 2; i++)
        #pragma unroll
        for (int j = 0; j < 6; j++)
            #pragma unroll
            for (int e = 0; e < 4; e++) { X[i][j][e] = 0; Y[i][j][e] = 0; }

    auto load_stage = [&](int ci, int s) {
        const int k0 = ci * 64;
        const uint32_t sb = smb + s * KV_STG;
        #pragma unroll
        for (int it = 0; it < 2; it++) {
            int idx = tid + it * 256;
            int row = idx >> 2, q = idx & 3;
            uint32_t soff = row * 64 + ((q ^ ((row >> 1) & 3)) << 4);
            cpa16(sb + soff,        A1 + (size_t)row * FEAT + k0 + q * 16);
            cpa16(sb + 8192 + soff, A2 + (size_t)row * FEAT + k0 + q * 16);
        }
        for (int idx = tid; idx < 384; idx += 256) {
            int row = idx >> 2, q = idx & 3;
            uint32_t soff = row * 64 + ((q ^ ((row >> 1) & 3)) << 4);
            cpa16(sb + 16384 + soff, B1 + (size_t)row * FEAT + k0 + q * 16);
            cpa16(sb + 22528 + soff, B2 + (size_t)row * FEAT + k0 + q * 16);
        }
        cpa_commit();
    };

    load_stage(0, 0);
    #pragma unroll 1
    for (int ci = 0; ci < 4; ci++) {
        const int s = ci & 1;
        if (ci < 3) { load_stage(ci + 1, s ^ 1); asm volatile("cp.async.wait_group 1;"); }
        else        asm volatile("cp.async.wait_group 0;");
        __syncthreads();
        const uint32_t sb = smb + s * KV_STG;
        #pragma unroll
        for (int k2 = 0; k2 < 2; k2++) {
            uint32_t a1f[2][4], a2f[2][4], b1f[6][2], b2f[6][2];
            #pragma unroll
            for (int mi = 0; mi < 2; mi++) {
                int row = wm + mi * 16 + (lid & 7) + ((lid >> 3) & 1) * 8;
                int q = k2 * 2 + (lid >> 4);
                uint32_t off = row * 64 + ((q ^ ((row >> 1) & 3)) << 4);
                ldmx4(sb + off,        a1f[mi][0], a1f[mi][1], a1f[mi][2], a1f[mi][3]);
                ldmx4(sb + 8192 + off, a2f[mi][0], a2f[mi][1], a2f[mi][2], a2f[mi][3]);
            }
            #pragma unroll
            for (int np = 0; np < 3; np++) {
                int row = wn + np * 16 + (lid >> 4) * 8 + (lid & 7);
                int q = k2 * 2 + ((lid >> 3) & 1);
                uint32_t off = row * 64 + ((q ^ ((row >> 1) & 3)) << 4);
                ldmx4(sb + 16384 + off, b1f[2*np][0], b1f[2*np][1], b1f[2*np+1][0], b1f[2*np+1][1]);
                ldmx4(sb + 22528 + off, b2f[2*np][0], b2f[2*np][1], b2f[2*np+1][0], b2f[2*np+1][1]);
            }
            #pragma unroll
            for (int mi = 0; mi < 2; mi++)
                #pragma unroll
                for (int ni = 0; ni < 6; ni++)
                    imma16832(X[mi][ni], a1f[mi], b1f[ni]);
            #pragma unroll
            for (int mi = 0; mi < 2; mi++)
                #pragma unroll
                for (int ni = 0; ni < 6; ni++)
                    imma16832(Y[mi][ni], a1f[mi], b2f[ni]);
            #pragma unroll
            for (int mi = 0; mi < 2; mi++)
                #pragma unroll
                for (int ni = 0; ni < 6; ni++)
                    imma16832(Y[mi][ni], a2f[mi], b1f[ni]);
        }
        __syncthreads();
    }

    const int g = lid >> 2, c2 = (lid & 3) * 2;
    if ((wid >> 2) == 1 && (lid & 3) == 0) {
        float sden_s = SF_QF * g_sd[bh * NPAD + 64];
        #pragma unroll
        for (int mi = 0; mi < 2; mi++) {
            int rl = wm + mi * 16 + g;
            sden[rl]     = sden_s * ((float)X[mi][2][0] + (float)Y[mi][2][0] * (1.f/256.f));
            sden[rl + 8] = sden_s * ((float)X[mi][2][2] + (float)Y[mi][2][2] * (1.f/256.f));
        }
    }
    __syncthreads();

    const int b = bh >> 4, h = bh & 15;
    const int nlim = ((wid >> 2) == 0) ? 6 : 2;
    #pragma unroll
    for (int mi = 0; mi < 2; mi++) {
        int rl = wm + mi * 16 + g;
        float z0 = 1.f / (sden[rl] + 1e-6f);
        float z1 = 1.f / (sden[rl + 8] + 1e-6f);
        size_t rg0 = (size_t)(b * SEQ + n0 + rl) * DIMV + h * 64;
        size_t rg1 = rg0 + 8 * DIMV;
        for (int ni = 0; ni < nlim; ni++) {
            int col = wn + ni * 8 + c2;
            float sb0 = SF_QF * g_sd[bh * NPAD + col];
            float sb1 = SF_QF * g_sd[bh * NPAD + col + 1];
            float r00 = sb0 * ((float)X[mi][ni][0] + (float)Y[mi][ni][0] * (1.f/256.f));
            float r01 = sb1 * ((float)X[mi][ni][1] + (float)Y[mi][ni][1] * (1.f/256.f));
            float r10 = sb0 * ((float)X[mi][ni][2] + (float)Y[mi][ni][2] * (1.f/256.f));
            float r11 = sb1 * ((float)X[mi][ni][3] + (float)Y[mi][ni][3] * (1.f/256.f));
            float2 o0 = { r00 * z0, r01 * z0 };
            float2 o1 = { r10 * z1, r11 * z1 };
            *(float2*)&g_af[rg0 + col] = o0;
            *(float2*)&g_af[rg1 + col] = o1;
        }
    }
}

// ---------------- launch ----------------
extern "C" void kernel_launch(void* const* d_in, const int* in_sizes, int n_in,
                              void* d_out, int out_size)
{
    const float* x  = (const float*)d_in[0];
    const float* Wq = (const float*)d_in[1];
    const float* Wk = (const float*)d_in[2];
    const float* Wv = (const float*)d_in[3];
    const float* Wp = (const float*)d_in[4];
    const float* bp = (const float*)d_in[5];
    const float* Wr = (const float*)d_in[6];
    const float* br = (const float*)d_in[7];
    float* out = (float*)d_out;

    int8_t *xq1, *xq2, *wq1, *wq2, *pq1, *pq2, *aq1, *aq2;
    float *sx, *sw, *sp, *sa, *af;
    cudaGetSymbolAddress((void**)&xq1, g_xq1); cudaGetSymbolAddress((void**)&xq2, g_xq2);
    cudaGetSymbolAddress((void**)&wq1, g_wq1); cudaGetSymbolAddress((void**)&wq2, g_wq2);
    cudaGetSymbolAddress((void**)&pq1, g_pq1); cudaGetSymbolAddress((void**)&pq2, g_pq2);
    cudaGetSymbolAddress((void**)&aq1, g_aq1); cudaGetSymbolAddress((void**)&aq2, g_aq2);
    cudaGetSymbolAddress((void**)&sx, g_sx);   cudaGetSymbolAddress((void**)&sw, g_sw);
    cudaGetSymbolAddress((void**)&sp, g_sp);   cudaGetSymbolAddress((void**)&sa, g_sa);
    cudaGetSymbolAddress((void**)&af, g_af);

    cudaFuncSetAttribute(gemm_i8<0>, cudaFuncAttributeMaxDynamicSharedMemorySize, IGEMM_SMEM);
    cudaFuncSetAttribute(gemm_i8<3>, cudaFuncAttributeMaxDynamicSharedMemorySize, IGEMM_SMEM);
    cudaFuncSetAttribute(proj_feat, cudaFuncAttributeMaxDynamicSharedMemorySize, PROJ_SMEM);
    cudaFuncSetAttribute(gemm_kv,  cudaFuncAttributeMaxDynamicSharedMemorySize, KV_SMEM);
    cudaFuncSetAttribute(gemm_out, cudaFuncAttributeMaxDynamicSharedMemorySize, OUT_SMEM);

    const int WSZ = DIMV * DIMV;

    quant_rows<<<MROWS / 8, 256>>>(x, xq1, xq2, sx, MROWS);
    quant_rows<<<DIMV / 8, 256>>>(Wq, wq1 + 0 * WSZ, wq2 + 0 * WSZ, sw + 0 * DIMV, DIMV);
    quant_rows<<<DIMV / 8, 256>>>(Wk, wq1 + 1 * WSZ, wq2 + 1 * WSZ, sw + 1 * DIMV, DIMV);
    quant_rows<<<DIMV / 8, 256>>>(Wv, wq1 + 2 * WSZ, wq2 + 2 * WSZ, sw + 2 * DIMV, DIMV);
    quant_rows<<<DIMV / 8, 256>>>(Wp, pq1, pq2, sp, DIMV);
    prep_wrt<<<NHEADS, 256>>>(Wr);
    fill_vq<<<BH * 32, 256>>>();

    // merged QKV int8 GEMM: N = 3072, 128x64 tiles, 2 CTAs/SM
    gemm_i8<3><<<dim3(3 * DIMV / 64, MROWS / 128), 256, IGEMM_SMEM>>>(
        xq1, xq2, sx, wq1, wq2, sw, nullptr, nullptr);

    proj_feat<<<dim3(MROWS / 128, 32), 256, PROJ_SMEM>>>(br);
    gemm_kv<<<dim3(8, BH * 2), 256, KV_SMEM>>>();
    kv_reduce_q<<<BH * NPAD / 8, 256>>>();
    gemm_out<<<dim3(SEQ / 128, BH), 256, OUT_SMEM>>>();

    quant_rows<<<MROWS / 8, 256>>>(af, aq1, aq2, sa, MROWS);
    gemm_i8<0><<<dim3(DIMV / 64, MROWS / 128), 256, IGEMM_SMEM>>>(
        aq1, aq2, sa, pq1, pq2, sp, bp, out);
}

// round 15
// speedup vs baseline: 1.1852x; 1.0537x over previous
#include <cuda_runtime.h>
#include <cuda_bf16.h>
#include <math.h>
#include <stdint.h>

#define DIMV 1024
#define NHEADS 16
#define DK 64
#define RFF 128
#define FEAT 256
#define BATCH 2
#define SEQ 8192
#define MROWS 16384
#define BH 32
#define NPAD 96
#define INV_SQRT_R 0.08838834764831845f

// ---------------- scratch (device globals) ----------------
__device__ int8_t g_xq1[MROWS*DIMV], g_xq2[MROWS*DIMV];
__device__ float  g_sx[MROWS];
__device__ int8_t g_wq1[3*DIMV*DIMV], g_wq2[3*DIMV*DIMV];
__device__ float  g_sw[3*DIMV];
__device__ int8_t g_pq1[DIMV*DIMV], g_pq2[DIMV*DIMV];
__device__ float  g_sp[DIMV];
__device__ int8_t g_qq1[MROWS*DIMV], g_qq2[MROWS*DIMV];
__device__ int8_t g_kq1[MROWS*DIMV], g_kq2[MROWS*DIMV];
__device__ int8_t g_wrq1[NHEADS*RFF*DK], g_wrq2[NHEADS*RFF*DK];
__device__ int8_t g_vq1[(size_t)BH*NPAD*SEQ], g_vq2[(size_t)BH*NPAD*SEQ];
__device__ int8_t g_qfq1[(size_t)BH*SEQ*FEAT], g_qfq2[(size_t)BH*SEQ*FEAT];
__device__ int8_t g_kfq1[(size_t)BH*FEAT*SEQ], g_kfq2[(size_t)BH*FEAT*SEQ];
__device__ float g_kvp[8*BH*FEAT*NPAD];
__device__ int8_t g_dq1[(size_t)BH*NPAD*FEAT], g_dq2[(size_t)BH*NPAD*FEAT];
__device__ float  g_sd[BH*NPAD];
__device__ float g_af[MROWS*DIMV];
__device__ int8_t g_aq1[MROWS*DIMV], g_aq2[MROWS*DIMV];
__device__ float  g_sa[MROWS];

#define INV_SV (127.f/8.f)
#define SF_QF (INV_SQRT_R/127.f)
#define DEQ_KV ((INV_SQRT_R/127.f)*(8.f/127.f))
#define INV_SQK (127.f/8.f)
#define DEQ_P ((8.f/127.f)*(1.f/127.f))

// ---------------- helpers ----------------
__device__ __forceinline__ uint32_t smem_u32(const void* p) {
    uint32_t a;
    asm("{ .reg .u64 t; cvta.to.shared.u64 t, %1; cvt.u32.u64 %0, t; }" : "=r"(a) : "l"(p));
    return a;
}
__device__ __forceinline__ void cpa16(uint32_t s, const void* g) {
    asm volatile("cp.async.cg.shared.global [%0], [%1], 16;" :: "r"(s), "l"(g));
}
__device__ __forceinline__ void cpa_commit() { asm volatile("cp.async.commit_group;"); }
__device__ __forceinline__ void ldmx4(uint32_t addr, uint32_t& r0, uint32_t& r1, uint32_t& r2, uint32_t& r3) {
    asm volatile("ldmatrix.sync.aligned.m8n8.x4.shared.b16 {%0,%1,%2,%3}, [%4];"
                 : "=r"(r0), "=r"(r1), "=r"(r2), "=r"(r3) : "r"(addr));
}
__device__ __forceinline__ void imma16832(int* d, const uint32_t* a, const uint32_t* b) {
    asm volatile(
        "mma.sync.aligned.m16n8k32.row.col.s32.s8.s8.s32 "
        "{%0,%1,%2,%3}, {%4,%5,%6,%7}, {%8,%9}, {%0,%1,%2,%3};"
        : "+r"(d[0]), "+r"(d[1]), "+r"(d[2]), "+r"(d[3])
        : "r"(a[0]), "r"(a[1]), "r"(a[2]), "r"(a[3]), "r"(b[0]), "r"(b[1]));
}
__device__ __forceinline__ void iq2(float qv, int8_t& q1, int8_t& q2) {
    float a1 = fminf(fmaxf(rintf(qv), -127.f), 127.f);
    float a2 = fminf(fmaxf(rintf((qv - a1) * 256.f), -127.f), 127.f);
    q1 = (int8_t)a1; q2 = (int8_t)a2;
}

// ---------------- per-row 2-digit int8 quantization ----------------
__global__ __launch_bounds__(256) void quant_rows(
    const float* __restrict__ in, int8_t* __restrict__ q1,
    int8_t* __restrict__ q2, float* __restrict__ sc, int nrows)
{
    int row = blockIdx.x * 8 + (threadIdx.x >> 5);
    if (row >= nrows) return;
    int lid = threadIdx.x & 31;
    const float4* r = (const float4*)(in + (size_t)row * 1024);
    float4 v[8];
    float mx = 0.f;
    #pragma unroll
    for (int i = 0; i < 8; i++) {
        v[i] = r[lid + 32 * i];
        mx = fmaxf(mx, fmaxf(fmaxf(fabsf(v[i].x), fabsf(v[i].y)),
                             fmaxf(fabsf(v[i].z), fabsf(v[i].w))));
    }
    #pragma unroll
    for (int o = 16; o; o >>= 1) mx = fmaxf(mx, __shfl_xor_sync(0xFFFFFFFFu, mx, o));
    mx = fmaxf(mx, 1e-20f);
    float inv = 127.f / mx;
    if (lid == 0) sc[row] = mx / 127.f;
    char4* o1 = (char4*)(q1 + (size_t)row * 1024);
    char4* o2 = (char4*)(q2 + (size_t)row * 1024);
    #pragma unroll
    for (int i = 0; i < 8; i++) {
        float qv[4] = { v[i].x * inv, v[i].y * inv, v[i].z * inv, v[i].w * inv };
        int8_t c1[4], c2[4];
        #pragma unroll
        for (int j = 0; j < 4; j++) iq2(qv[j], c1[j], c2[j]);
        o1[lid + 32 * i] = make_char4(c1[0], c1[1], c1[2], c1[3]);
        o2[lid + 32 * i] = make_char4(c2[0], c2[1], c2[2], c2[3]);
    }
}

// ---------------- WrT prep (int8, fixed scale 1/127) ----------------
__global__ __launch_bounds__(256) void prep_wrt(const float* __restrict__ Wr)
{
    int h = blockIdx.x;
    for (int e = threadIdx.x; e < RFF * DK; e += 256) {
        int r = e >> 6, j = e & 63;
        float v = Wr[(size_t)h * DK * RFF + j * RFF + r];
        int8_t q1, q2;
        iq2(v * 127.f, q1, q2);
        g_wrq1[h * RFF * DK + e] = q1;
        g_wrq2[h * RFF * DK + e] = q2;
    }
}

// ---------------- v padding rows ----------------
__global__ __launch_bounds__(256) void fill_vq()
{
    int bx = blockIdx.x;
    int bh = bx >> 5, dr = 64 + (bx & 31);
    char c1 = (dr == 64) ? 16 : 0;
    char c2 = (dr == 64) ? -32 : 0;
    uint32_t w1 = (uint8_t)c1; w1 |= w1 << 8; w1 |= w1 << 16;
    uint32_t w2 = (uint8_t)c2; w2 |= w2 << 8; w2 |= w2 << 16;
    size_t base = ((size_t)bh * NPAD + dr) * SEQ;
    for (int i = threadIdx.x; i < SEQ / 4; i += 256) {
        ((uint32_t*)(g_vq1 + base))[i] = w1;
        ((uint32_t*)(g_vq2 + base))[i] = w2;
    }
}

// ---------------- int8x2 IMMA GEMM: 128x64 tile, 2 CTAs/SM ----------------
#define ISTG 24576
#define IGEMM_SMEM (2 * ISTG)

template<int MODE>
__global__ __launch_bounds__(256, 2) void gemm_i8(
    const int8_t* __restrict__ A1, const int8_t* __restrict__ A2, const float* __restrict__ sA,
    const int8_t* __restrict__ B1, const int8_t* __restrict__ B2, const float* __restrict__ sB,
    const float* __restrict__ bias, float* __restrict__ C)
{
    extern __shared__ __align__(128) char sm[];
    const int tid = threadIdx.x, wid = tid >> 5, lid = tid & 31;
    const int m0 = blockIdx.y * 128, n0 = blockIdx.x * 64;
    const int wm = (wid & 3) * 32;
    const int wn = (wid >> 2) * 32;
    const uint32_t smb = smem_u32(sm);

    int X[2][4][4], Y[2][4][4];
    #pragma unroll
    for (int i = 0; i < 2; i++)
        #pragma unroll
        for (int j = 0; j < 4; j++)
            #pragma unroll
            for (int e = 0; e < 4; e++) { X[i][j][e] = 0; Y[i][j][e] = 0; }

    auto load_stage = [&](int ci, int s) {
        const int k0 = ci * 64;
        const uint32_t sb = smb + s * ISTG;
        #pragma unroll
        for (int it = 0; it < 2; it++) {
            int t = tid + it * 256;
            int row = t >> 2, q = t & 3;
            uint32_t soff = row * 64 + ((q ^ ((row >> 1) & 3)) << 4);
            size_t ga = (size_t)(m0 + row) * DIMV + k0 + q * 16;
            cpa16(sb + soff,        A1 + ga);
            cpa16(sb + 8192 + soff, A2 + ga);
        }
        {
            int row = tid >> 2, q = tid & 3;
            uint32_t soff = row * 64 + ((q ^ ((row >> 1) & 3)) << 4);
            size_t gb = (size_t)(n0 + row) * DIMV + k0 + q * 16;
            cpa16(sb + 16384 + soff, B1 + gb);
            cpa16(sb + 20480 + soff, B2 + gb);
        }
        cpa_commit();
    };

    load_stage(0, 0);

    #pragma unroll 1
    for (int ci = 0; ci < 16; ci++) {
        const int s = ci & 1;
        if (ci < 15) { load_stage(ci + 1, s ^ 1); asm volatile("cp.async.wait_group 1;"); }
        else         asm volatile("cp.async.wait_group 0;");
        __syncthreads();

        const uint32_t sb = smb + s * ISTG;
        #pragma unroll
        for (int ks = 0; ks < 2; ks++) {
            uint32_t a1f[2][4], a2f[2][4], b1f[4][2], b2f[4][2];
            #pragma unroll
            for (int mi = 0; mi < 2; mi++) {
                int row = wm + mi * 16 + (lid & 7) + ((lid >> 3) & 1) * 8;
                int q = ks * 2 + (lid >> 4);
                uint32_t off = row * 64 + ((q ^ ((row >> 1) & 3)) << 4);
                ldmx4(sb + off,        a1f[mi][0], a1f[mi][1], a1f[mi][2], a1f[mi][3]);
                ldmx4(sb + 8192 + off, a2f[mi][0], a2f[mi][1], a2f[mi][2], a2f[mi][3]);
            }
            #pragma unroll
            for (int np = 0; np < 2; np++) {
                int row = wn + np * 16 + (lid >> 4) * 8 + (lid & 7);
                int q = ks * 2 + ((lid >> 3) & 1);
                uint32_t off = row * 64 + ((q ^ ((row >> 1) & 3)) << 4);
                ldmx4(sb + 16384 + off, b1f[2*np][0], b1f[2*np][1], b1f[2*np+1][0], b1f[2*np+1][1]);
                ldmx4(sb + 20480 + off, b2f[2*np][0], b2f[2*np][1], b2f[2*np+1][0], b2f[2*np+1][1]);
            }
            #pragma unroll
            for (int mi = 0; mi < 2; mi++)
                #pragma unroll
                for (int ni = 0; ni < 4; ni++)
                    imma16832(X[mi][ni], a1f[mi], b1f[ni]);
            #pragma unroll
            for (int mi = 0; mi < 2; mi++)
                #pragma unroll
                for (int ni = 0; ni < 4; ni++)
                    imma16832(Y[mi][ni], a1f[mi], b2f[ni]);
            #pragma unroll
            for (int mi = 0; mi < 2; mi++)
                #pragma unroll
                for (int ni = 0; ni < 4; ni++)
                    imma16832(Y[mi][ni], a2f[mi], b1f[ni]);
        }
        __syncthreads();
    }

    const int g = lid >> 2, c2 = (lid & 3) * 2;
    if (MODE == 0) {
        #pragma unroll
        for (int mi = 0; mi < 2; mi++) {
            int row = m0 + wm + mi * 16 + g;
            float sa0 = sA[row], sa1 = sA[row + 8];
            #pragma unroll
            for (int ni = 0; ni < 4; ni++) {
                int col = n0 + wn + ni * 8 + c2;
                float sb0 = sB[col], sb1 = sB[col + 1];
                float r00 = sa0 * sb0 * ((float)X[mi][ni][0] + (float)Y[mi][ni][0] * (1.f/256.f));
                float r01 = sa0 * sb1 * ((float)X[mi][ni][1] + (float)Y[mi][ni][1] * (1.f/256.f));
                float r10 = sa1 * sb0 * ((float)X[mi][ni][2] + (float)Y[mi][ni][2] * (1.f/256.f));
                float r11 = sa1 * sb1 * ((float)X[mi][ni][3] + (float)Y[mi][ni][3] * (1.f/256.f));
                float b0 = bias ? bias[col] : 0.f;
                float b1 = bias ? bias[col + 1] : 0.f;
                float2 o0 = { r00 + b0, r01 + b1 };
                float2 o1 = { r10 + b0, r11 + b1 };
                *(float2*)&C[(size_t)row * DIMV + col]       = o0;
                *(float2*)&C[(size_t)(row + 8) * DIMV + col] = o1;
            }
        }
    } else {
        int8_t* s1 = (int8_t*)sm;
        int8_t* s2 = (int8_t*)sm + 8192;
        const bool isv = (n0 >= 2048);
        #pragma unroll
        for (int mi = 0; mi < 2; mi++) {
            int rowg = m0 + wm + mi * 16 + g;
            float sa0 = sA[rowg], sa1 = sA[rowg + 8];
            int rl0 = wm + mi * 16 + g, rl1 = rl0 + 8;
            #pragma unroll
            for (int ni = 0; ni < 4; ni++) {
                int cl = wn + ni * 8 + c2;
                float sb0 = sB[n0 + cl], sb1 = sB[n0 + cl + 1];
                float scale = isv ? INV_SV : INV_SQK;
                float r00 = sa0 * sb0 * ((float)X[mi][ni][0] + (float)Y[mi][ni][0] * (1.f/256.f)) * scale;
                float r01 = sa0 * sb1 * ((float)X[mi][ni][1] + (float)Y[mi][ni][1] * (1.f/256.f)) * scale;
                float r10 = sa1 * sb0 * ((float)X[mi][ni][2] + (float)Y[mi][ni][2] * (1.f/256.f)) * scale;
                float r11 = sa1 * sb1 * ((float)X[mi][ni][3] + (float)Y[mi][ni][3] * (1.f/256.f)) * scale;
                int8_t qa1, qa2, qb1, qb2;
                if (!isv) {
                    iq2(r00, qa1, qa2); iq2(r01, qb1, qb2);
                    s1[rl0 * 64 + cl] = qa1; s1[rl0 * 64 + cl + 1] = qb1;
                    s2[rl0 * 64 + cl] = qa2; s2[rl0 * 64 + cl + 1] = qb2;
                    iq2(r10, qa1, qa2); iq2(r11, qb1, qb2);
                    s1[rl1 * 64 + cl] = qa1; s1[rl1 * 64 + cl + 1] = qb1;
                    s2[rl1 * 64 + cl] = qa2; s2[rl1 * 64 + cl + 1] = qb2;
                } else {
                    iq2(r00, qa1, qa2);
                    s1[cl * 128 + rl0] = qa1;       s2[cl * 128 + rl0] = qa2;
                    iq2(r01, qa1, qa2);
                    s1[(cl+1) * 128 + rl0] = qa1;   s2[(cl+1) * 128 + rl0] = qa2;
                    iq2(r10, qa1, qa2);
                    s1[cl * 128 + rl1] = qa1;       s2[cl * 128 + rl1] = qa2;
                    iq2(r11, qa1, qa2);
                    s1[(cl+1) * 128 + rl1] = qa1;   s2[(cl+1) * 128 + rl1] = qa2;
                }
            }
        }
        __syncthreads();
        if (!isv) {
            int8_t* Cq1 = (n0 < 1024) ? g_qq1 : g_kq1;
            int8_t* Cq2 = (n0 < 1024) ? g_qq2 : g_kq2;
            const int cc0 = n0 & 1023;
            #pragma unroll
            for (int it = 0; it < 2; it++) {
                int idx = tid + it * 256;
                int row = idx >> 2, off = (idx & 3) * 16;
                size_t ga = (size_t)(m0 + row) * DIMV + cc0 + off;
                *(uint4*)&Cq1[ga] = *(uint4*)&s1[row * 64 + off];
                *(uint4*)&Cq2[ga] = *(uint4*)&s2[row * 64 + off];
            }
        } else {
            const int b = m0 >> 13, nseq = m0 & 8191;
            #pragma unroll
            for (int it = 0; it < 2; it++) {
                int idx = tid + it * 256;
                int col = idx >> 3, off = (idx & 7) * 16;
                int ccg = (n0 - 2048) + col;
                int hh = ccg >> 6, d0 = ccg & 63;
                size_t ga = (((size_t)(b * NHEADS + hh) * NPAD) + d0) * SEQ + nseq + off;
                *(uint4*)&g_vq1[ga] = *(uint4*)&s1[col * 128 + off];
                *(uint4*)&g_vq2[ga] = *(uint4*)&s2[col * 128 + off];
            }
        }
    }
}

// ---------------- proj + RFF features (int8), M=64 per CTA, 2 CTAs/SM ----------------
// 8 warps as 2(m) x 4(n): 32x32 warp tiles. Mainloop smem: A1 4K | A2 4K | B1 8K | B2 8K.
// Epilogue staging reuses 32KB.
#define PROJ_SMEM 32768

__global__ __launch_bounds__(256, 2) void proj_feat(const float* __restrict__ brp)
{
    extern __shared__ __align__(128) char sm[];
    const int tid = threadIdx.x, wid = tid >> 5, lid = tid & 31;
    const int m0 = blockIdx.x * 64;
    const int qk = blockIdx.y >> 4, h = blockIdx.y & 15;
    const int wm = (wid & 1) * 32, wn = (wid >> 1) * 32;
    const uint32_t smb = smem_u32(sm);

    const int8_t* Aq1 = qk ? g_kq1 : g_qq1;
    const int8_t* Aq2 = qk ? g_kq2 : g_qq2;
    const int8_t* Bq1 = g_wrq1 + h * RFF * DK;
    const int8_t* Bq2 = g_wrq2 + h * RFF * DK;

    {
        int row = tid >> 2, q = tid & 3;              // A: 64 rows
        uint32_t soff = row * 64 + ((q ^ ((row >> 1) & 3)) << 4);
        size_t ga = (size_t)(m0 + row) * DIMV + h * DK + q * 16;
        *(uint4*)(sm + soff)        = *(const uint4*)(Aq1 + ga);
        *(uint4*)(sm + 4096 + soff) = *(const uint4*)(Aq2 + ga);
    }
    #pragma unroll
    for (int it = 0; it < 2; it++) {
        int t = tid + it * 256;                        // B: 128 rows
        int row = t >> 2, q = t & 3;
        uint32_t soff = row * 64 + ((q ^ ((row >> 1) & 3)) << 4);
        size_t gb = (size_t)row * DK + q * 16;
        *(uint4*)(sm + 8192  + soff) = *(const uint4*)(Bq1 + gb);
        *(uint4*)(sm + 16384 + soff) = *(const uint4*)(Bq2 + gb);
    }
    __syncthreads();

    int X[2][4][4], Y[2][4][4];
    #pragma unroll
    for (int i = 0; i < 2; i++)
        #pragma unroll
        for (int j = 0; j < 4; j++)
            #pragma unroll
            for (int e = 0; e < 4; e++) { X[i][j][e] = 0; Y[i][j][e] = 0; }

    #pragma unroll
    for (int ks = 0; ks < 2; ks++) {
        uint32_t a1f[2][4], a2f[2][4], b1f[4][2], b2f[4][2];
        #pragma unroll
        for (int mi = 0; mi < 2; mi++) {
            int row = wm + mi * 16 + (lid & 7) + ((lid >> 3) & 1) * 8;
            int q = ks * 2 + (lid >> 4);
            uint32_t off = row * 64 + ((q ^ ((row >> 1) & 3)) << 4);
            ldmx4(smb + off,        a1f[mi][0], a1f[mi][1], a1f[mi][2], a1f[mi][3]);
            ldmx4(smb + 4096 + off, a2f[mi][0], a2f[mi][1], a2f[mi][2], a2f[mi][3]);
        }
        #pragma unroll
        for (int np = 0; np < 2; np++) {
            int row = wn + np * 16 + (lid >> 4) * 8 + (lid & 7);
            int q = ks * 2 + ((lid >> 3) & 1);
            uint32_t off = row * 64 + ((q ^ ((row >> 1) & 3)) << 4);
            ldmx4(smb + 8192  + off, b1f[2*np][0], b1f[2*np][1], b1f[2*np+1][0], b1f[2*np+1][1]);
            ldmx4(smb + 16384 + off, b2f[2*np][0], b2f[2*np][1], b2f[2*np+1][0], b2f[2*np+1][1]);
        }
        #pragma unroll
        for (int mi = 0; mi < 2; mi++)
            #pragma unroll
            for (int ni = 0; ni < 4; ni++)
                imma16832(X[mi][ni], a1f[mi], b1f[ni]);
        #pragma unroll
        for (int mi = 0; mi < 2; mi++)
            #pragma unroll
            for (int ni = 0; ni < 4; ni++)
                imma16832(Y[mi][ni], a1f[mi], b2f[ni]);
        #pragma unroll
        for (int mi = 0; mi < 2; mi++)
            #pragma unroll
            for (int ni = 0; ni < 4; ni++)
                imma16832(Y[mi][ni], a2f[mi], b1f[ni]);
    }

    __syncthreads();   // inputs consumed; reuse smem for epilogue staging

    // qk==0: s[n(64)][f(256)]. qk==1: s[f(256)][n(64)]. 16KB per digit.
    int8_t* s1 = (int8_t*)sm;
    int8_t* s2 = (int8_t*)sm + 16384;

    const int g = lid >> 2, c2 = (lid & 3) * 2;
    #pragma unroll
    for (int mi = 0; mi < 2; mi++) {
        #pragma unroll
        for (int ni = 0; ni < 4; ni++) {
            int col = wn + ni * 8 + c2;
            float b0 = brp[h * RFF + col], b1 = brp[h * RFF + col + 1];
            #pragma unroll
            for (int half = 0; half < 2; half++) {
                int nl = wm + mi * 16 + g + half * 8;
                int e0 = half * 2, e1 = half * 2 + 1;
                float p0 = DEQ_P * ((float)X[mi][ni][e0] + (float)Y[mi][ni][e0] * (1.f/256.f)) + b0;
                float p1 = DEQ_P * ((float)X[mi][ni][e1] + (float)Y[mi][ni][e1] * (1.f/256.f)) + b1;
                float s0, c0, s1v, c1;
                __sincosf(p0, &s0, &c0);
                __sincosf(p1, &s1v, &c1);
                int8_t cq1a, cq2a, cq1b, cq2b, sq1a, sq2a, sq1b, sq2b;
                iq2(c0 * 127.f, cq1a, cq2a); iq2(c1 * 127.f, cq1b, cq2b);
                iq2(s0 * 127.f, sq1a, sq2a); iq2(s1v * 127.f, sq1b, sq2b);
                if (qk == 0) {
                    int base = nl * 256;
                    s1[base + col] = cq1a;       s1[base + col + 1] = cq1b;
                    s2[base + col] = cq2a;       s2[base + col + 1] = cq2b;
                    s1[base + RFF + col] = sq1a; s1[base + RFF + col + 1] = sq1b;
                    s2[base + RFF + col] = sq2a; s2[base + RFF + col + 1] = sq2b;
                } else {
                    s1[col * 64 + nl] = cq1a;         s2[col * 64 + nl] = cq2a;
                    s1[(col+1) * 64 + nl] = cq1b;     s2[(col+1) * 64 + nl] = cq2b;
                    s1[(RFF+col) * 64 + nl] = sq1a;   s2[(RFF+col) * 64 + nl] = sq2a;
                    s1[(RFF+col+1) * 64 + nl] = sq1b; s2[(RFF+col+1) * 64 + nl] = sq2b;
                }
            }
        }
    }
    __syncthreads();

    const int b = m0 >> 13, nseq = m0 & 8191;
    const int bh = b * NHEADS + h;
    if (qk == 0) {
        #pragma unroll
        for (int it = 0; it < 4; it++) {
            int idx = tid + it * 256;           // 0..1023
            int n = idx >> 4, off = (idx & 15) * 16;
            size_t ga = ((size_t)bh * SEQ + nseq + n) * FEAT + off;
            *(uint4*)&g_qfq1[ga] = *(uint4*)&s1[n * 256 + off];
            *(uint4*)&g_qfq2[ga] = *(uint4*)&s2[n * 256 + off];
        }
    } else {
        #pragma unroll
        for (int it = 0; it < 4; it++) {
            int idx = tid + it * 256;           // 0..1023
            int f = idx >> 2, off = (idx & 3) * 16;
            size_t ga = ((size_t)bh * FEAT + f) * SEQ + nseq + off;
            *(uint4*)&g_kfq1[ga] = *(uint4*)&s1[f * 64 + off];
            *(uint4*)&g_kfq2[ga] = *(uint4*)&s2[f * 64 + off];
        }
    }
}

// ---------------- Kv GEMM int8 (split-K 8), M=64 f-rows per CTA, 2 CTAs/SM ----------------
// 8 warps as 4(m,16) x 2(n,48). Stage: A1 4K | A2 4K | B1 6K | B2 6K = 20KB.
#define KV_STG 20480
#define KV_SMEM (2 * KV_STG)

__global__ __launch_bounds__(256, 2) void gemm_kv()
{
    extern __shared__ __align__(128) char sm[];
    const int tid = threadIdx.x, wid = tid >> 5, lid = tid & 31;
    const int ks = blockIdx.x;
    const int bh = blockIdx.y >> 2, m4 = blockIdx.y & 3;
    const int wm = (wid & 3) * 16, wn = (wid >> 2) * 48;
    const uint32_t smb = smem_u32(sm);

    const int8_t* A1 = g_kfq1 + ((size_t)bh * FEAT + m4 * 64) * SEQ + ks * 1024;
    const int8_t* A2 = g_kfq2 + ((size_t)bh * FEAT + m4 * 64) * SEQ + ks * 1024;
    const int8_t* B1 = g_vq1 + (size_t)bh * NPAD * SEQ + ks * 1024;
    const int8_t* B2 = g_vq2 + (size_t)bh * NPAD * SEQ + ks * 1024;

    int X[6][4], Y[6][4];
    #pragma unroll
    for (int j = 0; j < 6; j++)
        #pragma unroll
        for (int e = 0; e < 4; e++) { X[j][e] = 0; Y[j][e] = 0; }

    auto load_stage = [&](int ci, int s) {
        const int k0 = ci * 64;
        const uint32_t sb = smb + s * KV_STG;
        {
            int row = tid >> 2, q = tid & 3;          // A: 64 rows
            uint32_t soff = row * 64 + ((q ^ ((row >> 1) & 3)) << 4);
            cpa16(sb + soff,        A1 + (size_t)row * SEQ + k0 + q * 16);
            cpa16(sb + 4096 + soff, A2 + (size_t)row * SEQ + k0 + q * 16);
        }
        for (int idx = tid; idx < 384; idx += 256) {  // B: 96 rows
            int row = idx >> 2, q = idx & 3;
            uint32_t soff = row * 64 + ((q ^ ((row >> 1) & 3)) << 4);
            cpa16(sb + 8192  + soff, B1 + (size_t)row * SEQ + k0 + q * 16);
            cpa16(sb + 14336 + soff, B2 + (size_t)row * SEQ + k0 + q * 16);
        }
        cpa_commit();
    };

    load_stage(0, 0);
    #pragma unroll 1
    for (int ci = 0; ci < 16; ci++) {
        const int s = ci & 1;
        if (ci < 15) { load_stage(ci + 1, s ^ 1); asm volatile("cp.async.wait_group 1;"); }
        else         asm volatile("cp.async.wait_group 0;");
        __syncthreads();
        const uint32_t sb = smb + s * KV_STG;
        #pragma unroll
        for (int k2 = 0; k2 < 2; k2++) {
            uint32_t a1f[4], a2f[4], b1f[6][2], b2f[6][2];
            {
                int row = wm + (lid & 7) + ((lid >> 3) & 1) * 8;
                int q = k2 * 2 + (lid >> 4);
                uint32_t off = row * 64 + ((q ^ ((row >> 1) & 3)) << 4);
                ldmx4(sb + off,        a1f[0], a1f[1], a1f[2], a1f[3]);
                ldmx4(sb + 4096 + off, a2f[0], a2f[1], a2f[2], a2f[3]);
            }
            #pragma unroll
            for (int np = 0; np < 3; np++) {
                int row = wn + np * 16 + (lid >> 4) * 8 + (lid & 7);
                int q = k2 * 2 + ((lid >> 3) & 1);
                uint32_t off = row * 64 + ((q ^ ((row >> 1) & 3)) << 4);
                ldmx4(sb + 8192  + off, b1f[2*np][0], b1f[2*np][1], b1f[2*np+1][0], b1f[2*np+1][1]);
                ldmx4(sb + 14336 + off, b2f[2*np][0], b2f[2*np][1], b2f[2*np+1][0], b2f[2*np+1][1]);
            }
            #pragma unroll
            for (int ni = 0; ni < 6; ni++)
                imma16832(X[ni], a1f, b1f[ni]);
            #pragma unroll
            for (int ni = 0; ni < 6; ni++)
                imma16832(Y[ni], a1f, b2f[ni]);
            #pragma unroll
            for (int ni = 0; ni < 6; ni++)
                imma16832(Y[ni], a2f, b1f[ni]);
        }
        __syncthreads();
    }

    const int g = lid >> 2, c2 = (lid & 3) * 2;
    #pragma unroll
    for (int ni = 0; ni < 6; ni++) {
        int rl = wm + g;
        int col = wn + ni * 8 + c2;
        float* dp = g_kvp + (((size_t)ks * BH + bh) * FEAT + m4 * 64 + rl) * NPAD + col;
        float2 o0 = { DEQ_KV * ((float)X[ni][0] + (float)Y[ni][0] * (1.f/256.f)),
                      DEQ_KV * ((float)X[ni][1] + (float)Y[ni][1] * (1.f/256.f)) };
        float2 o1 = { DEQ_KV * ((float)X[ni][2] + (float)Y[ni][2] * (1.f/256.f)),
                      DEQ_KV * ((float)X[ni][3] + (float)Y[ni][3] * (1.f/256.f)) };
        *(float2*)dp = o0;
        *(float2*)(dp + 8 * NPAD) = o1;
    }
}

// ---------------- reduce partials + transpose + per-row quantize ----------------
__global__ __launch_bounds__(256) void kv_reduce_q()
{
    int wid = threadIdx.x >> 5, lid = threadIdx.x & 31;
    int r = blockIdx.x * 8 + wid;
    int bh = r / NPAD, d = r - bh * NPAD;
    float v[8];
    float mx = 0.f;
    #pragma unroll
    for (int i = 0; i < 8; i++) {
        int f = lid + 32 * i;
        float s = 0.f;
        #pragma unroll
        for (int ks = 0; ks < 8; ks++)
            s += g_kvp[(((size_t)ks * BH + bh) * FEAT + f) * NPAD + d];
        v[i] = s;
        mx = fmaxf(mx, fabsf(s));
    }
    #pragma unroll
    for (int o = 16; o; o >>= 1) mx = fmaxf(mx, __shfl_xor_sync(0xFFFFFFFFu, mx, o));
    mx = fmaxf(mx, 1e-20f);
    float inv = 127.f / mx;
    if (lid == 0) g_sd[r] = mx / 127.f;
    #pragma unroll
    for (int i = 0; i < 8; i++) {
        int f = lid + 32 * i;
        int8_t q1, q2;
        iq2(v[i] * inv, q1, q2);
        g_dq1[(size_t)r * FEAT + f] = q1;
        g_dq2[(size_t)r * FEAT + f] = q2;
    }
}

// ---------------- out GEMM int8 -> fp32 af ----------------
#define OUT_STG 28672
#define OUT_SMEM (2 * OUT_STG + 512)

__global__ __launch_bounds__(256, 1) void gemm_out()
{
    extern __shared__ __align__(128) char sm[];
    const int tid = threadIdx.x, wid = tid >> 5, lid = tid & 31;
    const int n0 = blockIdx.x * 128;
    const int bh = blockIdx.y;
    const int wm = (wid & 3) * 32, wn = (wid >> 2) * 48;
    const uint32_t smb = smem_u32(sm);
    float* sden = (float*)(sm + 2 * OUT_STG);

    const int8_t* A1 = g_qfq1 + ((size_t)bh * SEQ + n0) * FEAT;
    const int8_t* A2 = g_qfq2 + ((size_t)bh * SEQ + n0) * FEAT;
    const int8_t* B1 = g_dq1 + (size_t)bh * NPAD * FEAT;
    const int8_t* B2 = g_dq2 + (size_t)bh * NPAD * FEAT;

    int X[2][6][4], Y[2][6][4];
    #pragma unroll
    for (int i = 0; i < 2; i++)
        #pragma unroll
        for (int j = 0; j < 6; j++)
            #pragma unroll
            for (int e = 0; e < 4; e++) { X[i][j][e] = 0; Y[i][j][e] = 0; }

    auto load_stage = [&](int ci, int s) {
        const int k0 = ci * 64;
        const uint32_t sb = smb + s * OUT_STG;
        #pragma unroll
        for (int it = 0; it < 2; it++) {
            int idx = tid + it * 256;
            int row = idx >> 2, q = idx & 3;
            uint32_t soff = row * 64 + ((q ^ ((row >> 1) & 3)) << 4);
            cpa16(sb + soff,        A1 + (size_t)row * FEAT + k0 + q * 16);
            cpa16(sb + 8192 + soff, A2 + (size_t)row * FEAT + k0 + q * 16);
        }
        for (int idx = tid; idx < 384; idx += 256) {
            int row = idx >> 2, q = idx & 3;
            uint32_t soff = row * 64 + ((q ^ ((row >> 1) & 3)) << 4);
            cpa16(sb + 16384 + soff, B1 + (size_t)row * FEAT + k0 + q * 16);
            cpa16(sb + 22528 + soff, B2 + (size_t)row * FEAT + k0 + q * 16);
        }
        cpa_commit();
    };

    load_stage(0, 0);
    #pragma unroll 1
    for (int ci = 0; ci < 4; ci++) {
        const int s = ci & 1;
        if (ci < 3) { load_stage(ci + 1, s ^ 1); asm volatile("cp.async.wait_group 1;"); }
        else        asm volatile("cp.async.wait_group 0;");
        __syncthreads();
        const uint32_t sb = smb + s * OUT_STG;
        #pragma unroll
        for (int k2 = 0; k2 < 2; k2++) {
            uint32_t a1f[2][4], a2f[2][4], b1f[6][2], b2f[6][2];
            #pragma unroll
            for (int mi = 0; mi < 2; mi++) {
                int row = wm + mi * 16 + (lid & 7) + ((lid >> 3) & 1) * 8;
                int q = k2 * 2 + (lid >> 4);
                uint32_t off = row * 64 + ((q ^ ((row >> 1) & 3)) << 4);
                ldmx4(sb + off,        a1f[mi][0], a1f[mi][1], a1f[mi][2], a1f[mi][3]);
                ldmx4(sb + 8192 + off, a2f[mi][0], a2f[mi][1], a2f[mi][2], a2f[mi][3]);
            }
            #pragma unroll
            for (int np = 0; np < 3; np++) {
                int row = wn + np * 16 + (lid >> 4) * 8 + (lid & 7);
                int q = k2 * 2 + ((lid >> 3) & 1);
                uint32_t off = row * 64 + ((q ^ ((row >> 1) & 3)) << 4);
                ldmx4(sb + 16384 + off, b1f[2*np][0], b1f[2*np][1], b1f[2*np+1][0], b1f[2*np+1][1]);
                ldmx4(sb + 22528 + off, b2f[2*np][0], b2f[2*np][1], b2f[2*np+1][0], b2f[2*np+1][1]);
            }
            #pragma unroll
            for (int mi = 0; mi < 2; mi++)
                #pragma unroll
                for (int ni = 0; ni < 6; ni++)
                    imma16832(X[mi][ni], a1f[mi], b1f[ni]);
            #pragma unroll
            for (int mi = 0; mi < 2; mi++)
                #pragma unroll
                for (int ni = 0; ni < 6; ni++)
                    imma16832(Y[mi][ni], a1f[mi], b2f[ni]);
            #pragma unroll
            for (int mi = 0; mi < 2; mi++)
                #pragma unroll
                for (int ni = 0; ni < 6; ni++)
                    imma16832(Y[mi][ni], a2f[mi], b1f[ni]);
        }
        __syncthreads();
    }

    const int g = lid >> 2, c2 = (lid & 3) * 2;
    if ((wid >> 2) == 1 && (lid & 3) == 0) {
        float sden_s = SF_QF * g_sd[bh * NPAD + 64];
        #pragma unroll
        for (int mi = 0; mi < 2; mi++) {
            int rl = wm + mi * 16 + g;
            sden[rl]     = sden_s * ((float)X[mi][2][0] + (float)Y[mi][2][0] * (1.f/256.f));
            sden[rl + 8] = sden_s * ((float)X[mi][2][2] + (float)Y[mi][2][2] * (1.f/256.f));
        }
    }
    __syncthreads();

    const int b = bh >> 4, h = bh & 15;
    const int nlim = ((wid >> 2) == 0) ? 6 : 2;
    #pragma unroll
    for (int mi = 0; mi < 2; mi++) {
        int rl = wm + mi * 16 + g;
        float z0 = 1.f / (sden[rl] + 1e-6f);
        float z1 = 1.f / (sden[rl + 8] + 1e-6f);
        size_t rg0 = (size_t)(b * SEQ + n0 + rl) * DIMV + h * 64;
        size_t rg1 = rg0 + 8 * DIMV;
        for (int ni = 0; ni < nlim; ni++) {
            int col = wn + ni * 8 + c2;
            float sb0 = SF_QF * g_sd[bh * NPAD + col];
            float sb1 = SF_QF * g_sd[bh * NPAD + col + 1];
            float r00 = sb0 * ((float)X[mi][ni][0] + (float)Y[mi][ni][0] * (1.f/256.f));
            float r01 = sb1 * ((float)X[mi][ni][1] + (float)Y[mi][ni][1] * (1.f/256.f));
            float r10 = sb0 * ((float)X[mi][ni][2] + (float)Y[mi][ni][2] * (1.f/256.f));
            float r11 = sb1 * ((float)X[mi][ni][3] + (float)Y[mi][ni][3] * (1.f/256.f));
            float2 o0 = { r00 * z0, r01 * z0 };
            float2 o1 = { r10 * z1, r11 * z1 };
            *(float2*)&g_af[rg0 + col] = o0;
            *(float2*)&g_af[rg1 + col] = o1;
        }
    }
}

// ---------------- launch ----------------
extern "C" void kernel_launch(void* const* d_in, const int* in_sizes, int n_in,
                              void* d_out, int out_size)
{
    const float* x  = (const float*)d_in[0];
    const float* Wq = (const float*)d_in[1];
    const float* Wk = (const float*)d_in[2];
    const float* Wv = (const float*)d_in[3];
    const float* Wp = (const float*)d_in[4];
    const float* bp = (const float*)d_in[5];
    const float* Wr = (const float*)d_in[6];
    const float* br = (const float*)d_in[7];
    float* out = (float*)d_out;

    int8_t *xq1, *xq2, *wq1, *wq2, *pq1, *pq2, *aq1, *aq2;
    float *sx, *sw, *sp, *sa, *af;
    cudaGetSymbolAddress((void**)&xq1, g_xq1); cudaGetSymbolAddress((void**)&xq2, g_xq2);
    cudaGetSymbolAddress((void**)&wq1, g_wq1); cudaGetSymbolAddress((void**)&wq2, g_wq2);
    cudaGetSymbolAddress((void**)&pq1, g_pq1); cudaGetSymbolAddress((void**)&pq2, g_pq2);
    cudaGetSymbolAddress((void**)&aq1, g_aq1); cudaGetSymbolAddress((void**)&aq2, g_aq2);
    cudaGetSymbolAddress((void**)&sx, g_sx);   cudaGetSymbolAddress((void**)&sw, g_sw);
    cudaGetSymbolAddress((void**)&sp, g_sp);   cudaGetSymbolAddress((void**)&sa, g_sa);
    cudaGetSymbolAddress((void**)&af, g_af);

    cudaFuncSetAttribute(gemm_i8<0>, cudaFuncAttributeMaxDynamicSharedMemorySize, IGEMM_SMEM);
    cudaFuncSetAttribute(gemm_i8<3>, cudaFuncAttributeMaxDynamicSharedMemorySize, IGEMM_SMEM);
    cudaFuncSetAttribute(proj_feat, cudaFuncAttributeMaxDynamicSharedMemorySize, PROJ_SMEM);
    cudaFuncSetAttribute(gemm_kv,  cudaFuncAttributeMaxDynamicSharedMemorySize, KV_SMEM);
    cudaFuncSetAttribute(gemm_out, cudaFuncAttributeMaxDynamicSharedMemorySize, OUT_SMEM);

    const int WSZ = DIMV * DIMV;

    quant_rows<<<MROWS / 8, 256>>>(x, xq1, xq2, sx, MROWS);
    quant_rows<<<DIMV / 8, 256>>>(Wq, wq1 + 0 * WSZ, wq2 + 0 * WSZ, sw + 0 * DIMV, DIMV);
    quant_rows<<<DIMV / 8, 256>>>(Wk, wq1 + 1 * WSZ, wq2 + 1 * WSZ, sw + 1 * DIMV, DIMV);
    quant_rows<<<DIMV / 8, 256>>>(Wv, wq1 + 2 * WSZ, wq2 + 2 * WSZ, sw + 2 * DIMV, DIMV);
    quant_rows<<<DIMV / 8, 256>>>(Wp, pq1, pq2, sp, DIMV);
    prep_wrt<<<NHEADS, 256>>>(Wr);
    fill_vq<<<BH * 32, 256>>>();

    // merged QKV int8 GEMM: N = 3072, 128x64 tiles, 2 CTAs/SM
    gemm_i8<3><<<dim3(3 * DIMV / 64, MROWS / 128), 256, IGEMM_SMEM>>>(
        xq1, xq2, sx, wq1, wq2, sw, nullptr, nullptr);

    proj_feat<<<dim3(MROWS / 64, 32), 256, PROJ_SMEM>>>(br);
    gemm_kv<<<dim3(8, BH * 4), 256, KV_SMEM>>>();
    kv_reduce_q<<<BH * NPAD / 8, 256>>>();
    gemm_out<<<dim3(SEQ / 128, BH), 256, OUT_SMEM>>>();

    quant_rows<<<MROWS / 8, 256>>>(af, aq1, aq2, sa, MROWS);
    gemm_i8<0><<<dim3(DIMV / 64, MROWS / 128), 256, IGEMM_SMEM>>>(
        aq1, aq2, sa, pq1, pq2, sp, bp, out);
}

// round 16
// speedup vs baseline: 1.1986x; 1.0113x over previous
#include <cuda_runtime.h>
#include <cuda_bf16.h>
#include <math.h>
#include <stdint.h>

#define DIMV 1024
#define NHEADS 16
#define DK 64
#define RFF 128
#define FEAT 256
#define BATCH 2
#define SEQ 8192
#define MROWS 16384
#define BH 32
#define NPAD 96
#define INV_SQRT_R 0.08838834764831845f

// ---------------- scratch (device globals) ----------------
__device__ int8_t g_xq1[MROWS*DIMV], g_xq2[MROWS*DIMV];
__device__ float  g_sx[MROWS];
__device__ int8_t g_wq1[3*DIMV*DIMV], g_wq2[3*DIMV*DIMV];
__device__ float  g_sw[3*DIMV];
__device__ int8_t g_pq1[DIMV*DIMV], g_pq2[DIMV*DIMV];
__device__ float  g_sp[DIMV];
__device__ int8_t g_qq1[MROWS*DIMV], g_qq2[MROWS*DIMV];
__device__ int8_t g_kq1[MROWS*DIMV], g_kq2[MROWS*DIMV];
__device__ int8_t g_wrq1[NHEADS*RFF*DK], g_wrq2[NHEADS*RFF*DK];
__device__ int8_t g_vq1[(size_t)BH*NPAD*SEQ], g_vq2[(size_t)BH*NPAD*SEQ];
__device__ int8_t g_qfq1[(size_t)BH*SEQ*FEAT], g_qfq2[(size_t)BH*SEQ*FEAT];
__device__ int8_t g_kfq1[(size_t)BH*FEAT*SEQ], g_kfq2[(size_t)BH*FEAT*SEQ];
__device__ float g_kvp[8*BH*FEAT*NPAD];
__device__ int8_t g_dq1[(size_t)BH*NPAD*FEAT], g_dq2[(size_t)BH*NPAD*FEAT];
__device__ float  g_sd[BH*NPAD];
__device__ float g_af[MROWS*DIMV];
__device__ int8_t g_aq1[MROWS*DIMV], g_aq2[MROWS*DIMV];
__device__ float  g_sa[MROWS];

#define INV_SV (127.f/8.f)
#define SF_QF (INV_SQRT_R/127.f)
#define DEQ_KV ((INV_SQRT_R/127.f)*(8.f/127.f))
#define INV_SQK (127.f/8.f)
#define DEQ_P ((8.f/127.f)*(1.f/127.f))

// ---------------- helpers ----------------
__device__ __forceinline__ uint32_t smem_u32(const void* p) {
    uint32_t a;
    asm("{ .reg .u64 t; cvta.to.shared.u64 t, %1; cvt.u32.u64 %0, t; }" : "=r"(a) : "l"(p));
    return a;
}
__device__ __forceinline__ void cpa16(uint32_t s, const void* g) {
    asm volatile("cp.async.cg.shared.global [%0], [%1], 16;" :: "r"(s), "l"(g));
}
__device__ __forceinline__ void cpa_commit() { asm volatile("cp.async.commit_group;"); }
__device__ __forceinline__ void ldmx4(uint32_t addr, uint32_t& r0, uint32_t& r1, uint32_t& r2, uint32_t& r3) {
    asm volatile("ldmatrix.sync.aligned.m8n8.x4.shared.b16 {%0,%1,%2,%3}, [%4];"
                 : "=r"(r0), "=r"(r1), "=r"(r2), "=r"(r3) : "r"(addr));
}
__device__ __forceinline__ void imma16832(int* d, const uint32_t* a, const uint32_t* b) {
    asm volatile(
        "mma.sync.aligned.m16n8k32.row.col.s32.s8.s8.s32 "
        "{%0,%1,%2,%3}, {%4,%5,%6,%7}, {%8,%9}, {%0,%1,%2,%3};"
        : "+r"(d[0]), "+r"(d[1]), "+r"(d[2]), "+r"(d[3])
        : "r"(a[0]), "r"(a[1]), "r"(a[2]), "r"(a[3]), "r"(b[0]), "r"(b[1]));
}
__device__ __forceinline__ void iq2(float qv, int8_t& q1, int8_t& q2) {
    float a1 = fminf(fmaxf(rintf(qv), -127.f), 127.f);
    float a2 = fminf(fmaxf(rintf((qv - a1) * 256.f), -127.f), 127.f);
    q1 = (int8_t)a1; q2 = (int8_t)a2;
}

// ---------------- per-row 2-digit int8 quantization ----------------
__global__ __launch_bounds__(256) void quant_rows(
    const float* __restrict__ in, int8_t* __restrict__ q1,
    int8_t* __restrict__ q2, float* __restrict__ sc, int nrows)
{
    int row = blockIdx.x * 8 + (threadIdx.x >> 5);
    if (row >= nrows) return;
    int lid = threadIdx.x & 31;
    const float4* r = (const float4*)(in + (size_t)row * 1024);
    float4 v[8];
    float mx = 0.f;
    #pragma unroll
    for (int i = 0; i < 8; i++) {
        v[i] = r[lid + 32 * i];
        mx = fmaxf(mx, fmaxf(fmaxf(fabsf(v[i].x), fabsf(v[i].y)),
                             fmaxf(fabsf(v[i].z), fabsf(v[i].w))));
    }
    #pragma unroll
    for (int o = 16; o; o >>= 1) mx = fmaxf(mx, __shfl_xor_sync(0xFFFFFFFFu, mx, o));
    mx = fmaxf(mx, 1e-20f);
    float inv = 127.f / mx;
    if (lid == 0) sc[row] = mx / 127.f;
    char4* o1 = (char4*)(q1 + (size_t)row * 1024);
    char4* o2 = (char4*)(q2 + (size_t)row * 1024);
    #pragma unroll
    for (int i = 0; i < 8; i++) {
        float qv[4] = { v[i].x * inv, v[i].y * inv, v[i].z * inv, v[i].w * inv };
        int8_t c1[4], c2[4];
        #pragma unroll
        for (int j = 0; j < 4; j++) iq2(qv[j], c1[j], c2[j]);
        o1[lid + 32 * i] = make_char4(c1[0], c1[1], c1[2], c1[3]);
        o2[lid + 32 * i] = make_char4(c2[0], c2[1], c2[2], c2[3]);
    }
}

// ---------------- WrT prep (int8, fixed scale 1/127) ----------------
__global__ __launch_bounds__(256) void prep_wrt(const float* __restrict__ Wr)
{
    int h = blockIdx.x;
    for (int e = threadIdx.x; e < RFF * DK; e += 256) {
        int r = e >> 6, j = e & 63;
        float v = Wr[(size_t)h * DK * RFF + j * RFF + r];
        int8_t q1, q2;
        iq2(v * 127.f, q1, q2);
        g_wrq1[h * RFF * DK + e] = q1;
        g_wrq2[h * RFF * DK + e] = q2;
    }
}

// ---------------- v padding rows ----------------
__global__ __launch_bounds__(256) void fill_vq()
{
    int bx = blockIdx.x;
    int bh = bx >> 5, dr = 64 + (bx & 31);
    char c1 = (dr == 64) ? 16 : 0;
    char c2 = (dr == 64) ? -32 : 0;
    uint32_t w1 = (uint8_t)c1; w1 |= w1 << 8; w1 |= w1 << 16;
    uint32_t w2 = (uint8_t)c2; w2 |= w2 << 8; w2 |= w2 << 16;
    size_t base = ((size_t)bh * NPAD + dr) * SEQ;
    for (int i = threadIdx.x; i < SEQ / 4; i += 256) {
        ((uint32_t*)(g_vq1 + base))[i] = w1;
        ((uint32_t*)(g_vq2 + base))[i] = w2;
    }
}

// ---------------- int8x2 IMMA GEMM: 128x64 tile, 2 CTAs/SM, 3-stage pipeline ----------------
#define ISTG 24576
#define IGEMM_SMEM (3 * ISTG)

template<int MODE>
__global__ __launch_bounds__(256, 2) void gemm_i8(
    const int8_t* __restrict__ A1, const int8_t* __restrict__ A2, const float* __restrict__ sA,
    const int8_t* __restrict__ B1, const int8_t* __restrict__ B2, const float* __restrict__ sB,
    const float* __restrict__ bias, float* __restrict__ C)
{
    extern __shared__ __align__(128) char sm[];
    const int tid = threadIdx.x, wid = tid >> 5, lid = tid & 31;
    const int m0 = blockIdx.y * 128, n0 = blockIdx.x * 64;
    const int wm = (wid & 3) * 32;
    const int wn = (wid >> 2) * 32;
    const uint32_t smb = smem_u32(sm);

    int X[2][4][4], Y[2][4][4];
    #pragma unroll
    for (int i = 0; i < 2; i++)
        #pragma unroll
        for (int j = 0; j < 4; j++)
            #pragma unroll
            for (int e = 0; e < 4; e++) { X[i][j][e] = 0; Y[i][j][e] = 0; }

    auto load_stage = [&](int ci, int s) {
        const int k0 = ci * 64;
        const uint32_t sb = smb + s * ISTG;
        #pragma unroll
        for (int it = 0; it < 2; it++) {
            int t = tid + it * 256;
            int row = t >> 2, q = t & 3;
            uint32_t soff = row * 64 + ((q ^ ((row >> 1) & 3)) << 4);
            size_t ga = (size_t)(m0 + row) * DIMV + k0 + q * 16;
            cpa16(sb + soff,        A1 + ga);
            cpa16(sb + 8192 + soff, A2 + ga);
        }
        {
            int row = tid >> 2, q = tid & 3;
            uint32_t soff = row * 64 + ((q ^ ((row >> 1) & 3)) << 4);
            size_t gb = (size_t)(n0 + row) * DIMV + k0 + q * 16;
            cpa16(sb + 16384 + soff, B1 + gb);
            cpa16(sb + 20480 + soff, B2 + gb);
        }
        cpa_commit();
    };

    load_stage(0, 0);
    load_stage(1, 1);

    #pragma unroll 1
    for (int ci = 0; ci < 16; ci++) {
        if (ci + 2 < 16) {
            int s2 = ci + 2; s2 -= (s2 / 3) * 3;   // (ci+2) % 3
            load_stage(ci + 2, s2);
            asm volatile("cp.async.wait_group 2;");
        } else if (ci + 1 < 16) {
            asm volatile("cp.async.wait_group 1;");
        } else {
            asm volatile("cp.async.wait_group 0;");
        }
        __syncthreads();

        int sc = ci; sc -= (sc / 3) * 3;           // ci % 3
        const uint32_t sb = smb + sc * ISTG;
        #pragma unroll
        for (int ks = 0; ks < 2; ks++) {
            uint32_t a1f[2][4], a2f[2][4], b1f[4][2], b2f[4][2];
            #pragma unroll
            for (int mi = 0; mi < 2; mi++) {
                int row = wm + mi * 16 + (lid & 7) + ((lid >> 3) & 1) * 8;
                int q = ks * 2 + (lid >> 4);
                uint32_t off = row * 64 + ((q ^ ((row >> 1) & 3)) << 4);
                ldmx4(sb + off,        a1f[mi][0], a1f[mi][1], a1f[mi][2], a1f[mi][3]);
                ldmx4(sb + 8192 + off, a2f[mi][0], a2f[mi][1], a2f[mi][2], a2f[mi][3]);
            }
            #pragma unroll
            for (int np = 0; np < 2; np++) {
                int row = wn + np * 16 + (lid >> 4) * 8 + (lid & 7);
                int q = ks * 2 + ((lid >> 3) & 1);
                uint32_t off = row * 64 + ((q ^ ((row >> 1) & 3)) << 4);
                ldmx4(sb + 16384 + off, b1f[2*np][0], b1f[2*np][1], b1f[2*np+1][0], b1f[2*np+1][1]);
                ldmx4(sb + 20480 + off, b2f[2*np][0], b2f[2*np][1], b2f[2*np+1][0], b2f[2*np+1][1]);
            }
            #pragma unroll
            for (int mi = 0; mi < 2; mi++)
                #pragma unroll
                for (int ni = 0; ni < 4; ni++)
                    imma16832(X[mi][ni], a1f[mi], b1f[ni]);
            #pragma unroll
            for (int mi = 0; mi < 2; mi++)
                #pragma unroll
                for (int ni = 0; ni < 4; ni++)
                    imma16832(Y[mi][ni], a1f[mi], b2f[ni]);
            #pragma unroll
            for (int mi = 0; mi < 2; mi++)
                #pragma unroll
                for (int ni = 0; ni < 4; ni++)
                    imma16832(Y[mi][ni], a2f[mi], b1f[ni]);
        }
        __syncthreads();
    }

    const int g = lid >> 2, c2 = (lid & 3) * 2;
    if (MODE == 0) {
        #pragma unroll
        for (int mi = 0; mi < 2; mi++) {
            int row = m0 + wm + mi * 16 + g;
            float sa0 = sA[row], sa1 = sA[row + 8];
            #pragma unroll
            for (int ni = 0; ni < 4; ni++) {
                int col = n0 + wn + ni * 8 + c2;
                float sb0 = sB[col], sb1 = sB[col + 1];
                float r00 = sa0 * sb0 * ((float)X[mi][ni][0] + (float)Y[mi][ni][0] * (1.f/256.f));
                float r01 = sa0 * sb1 * ((float)X[mi][ni][1] + (float)Y[mi][ni][1] * (1.f/256.f));
                float r10 = sa1 * sb0 * ((float)X[mi][ni][2] + (float)Y[mi][ni][2] * (1.f/256.f));
                float r11 = sa1 * sb1 * ((float)X[mi][ni][3] + (float)Y[mi][ni][3] * (1.f/256.f));
                float b0 = bias ? bias[col] : 0.f;
                float b1 = bias ? bias[col + 1] : 0.f;
                float2 o0 = { r00 + b0, r01 + b1 };
                float2 o1 = { r10 + b0, r11 + b1 };
                *(float2*)&C[(size_t)row * DIMV + col]       = o0;
                *(float2*)&C[(size_t)(row + 8) * DIMV + col] = o1;
            }
        }
    } else {
        int8_t* s1 = (int8_t*)sm;
        int8_t* s2 = (int8_t*)sm + 8192;
        const bool isv = (n0 >= 2048);
        #pragma unroll
        for (int mi = 0; mi < 2; mi++) {
            int rowg = m0 + wm + mi * 16 + g;
            float sa0 = sA[rowg], sa1 = sA[rowg + 8];
            int rl0 = wm + mi * 16 + g, rl1 = rl0 + 8;
            #pragma unroll
            for (int ni = 0; ni < 4; ni++) {
                int cl = wn + ni * 8 + c2;
                float sb0 = sB[n0 + cl], sb1 = sB[n0 + cl + 1];
                float scale = isv ? INV_SV : INV_SQK;
                float r00 = sa0 * sb0 * ((float)X[mi][ni][0] + (float)Y[mi][ni][0] * (1.f/256.f)) * scale;
                float r01 = sa0 * sb1 * ((float)X[mi][ni][1] + (float)Y[mi][ni][1] * (1.f/256.f)) * scale;
                float r10 = sa1 * sb0 * ((float)X[mi][ni][2] + (float)Y[mi][ni][2] * (1.f/256.f)) * scale;
                float r11 = sa1 * sb1 * ((float)X[mi][ni][3] + (float)Y[mi][ni][3] * (1.f/256.f)) * scale;
                int8_t qa1, qa2, qb1, qb2;
                if (!isv) {
                    iq2(r00, qa1, qa2); iq2(r01, qb1, qb2);
                    s1[rl0 * 64 + cl] = qa1; s1[rl0 * 64 + cl + 1] = qb1;
                    s2[rl0 * 64 + cl] = qa2; s2[rl0 * 64 + cl + 1] = qb2;
                    iq2(r10, qa1, qa2); iq2(r11, qb1, qb2);
                    s1[rl1 * 64 + cl] = qa1; s1[rl1 * 64 + cl + 1] = qb1;
                    s2[rl1 * 64 + cl] = qa2; s2[rl1 * 64 + cl + 1] = qb2;
                } else {
                    iq2(r00, qa1, qa2);
                    s1[cl * 128 + rl0] = qa1;       s2[cl * 128 + rl0] = qa2;
                    iq2(r01, qa1, qa2);
                    s1[(cl+1) * 128 + rl0] = qa1;   s2[(cl+1) * 128 + rl0] = qa2;
                    iq2(r10, qa1, qa2);
                    s1[cl * 128 + rl1] = qa1;       s2[cl * 128 + rl1] = qa2;
                    iq2(r11, qa1, qa2);
                    s1[(cl+1) * 128 + rl1] = qa1;   s2[(cl+1) * 128 + rl1] = qa2;
                }
            }
        }
        __syncthreads();
        if (!isv) {
            int8_t* Cq1 = (n0 < 1024) ? g_qq1 : g_kq1;
            int8_t* Cq2 = (n0 < 1024) ? g_qq2 : g_kq2;
            const int cc0 = n0 & 1023;
            #pragma unroll
            for (int it = 0; it < 2; it++) {
                int idx = tid + it * 256;
                int row = idx >> 2, off = (idx & 3) * 16;
                size_t ga = (size_t)(m0 + row) * DIMV + cc0 + off;
                *(uint4*)&Cq1[ga] = *(uint4*)&s1[row * 64 + off];
                *(uint4*)&Cq2[ga] = *(uint4*)&s2[row * 64 + off];
            }
        } else {
            const int b = m0 >> 13, nseq = m0 & 8191;
            #pragma unroll
            for (int it = 0; it < 2; it++) {
                int idx = tid + it * 256;
                int col = idx >> 3, off = (idx & 7) * 16;
                int ccg = (n0 - 2048) + col;
                int hh = ccg >> 6, d0 = ccg & 63;
                size_t ga = (((size_t)(b * NHEADS + hh) * NPAD) + d0) * SEQ + nseq + off;
                *(uint4*)&g_vq1[ga] = *(uint4*)&s1[col * 128 + off];
                *(uint4*)&g_vq2[ga] = *(uint4*)&s2[col * 128 + off];
            }
        }
    }
}

// ---------------- proj + RFF features (int8), M=64 per CTA, 2 CTAs/SM ----------------
#define PROJ_SMEM 32768

__global__ __launch_bounds__(256, 2) void proj_feat(const float* __restrict__ brp)
{
    extern __shared__ __align__(128) char sm[];
    const int tid = threadIdx.x, wid = tid >> 5, lid = tid & 31;
    const int m0 = blockIdx.x * 64;
    const int qk = blockIdx.y >> 4, h = blockIdx.y & 15;
    const int wm = (wid & 1) * 32, wn = (wid >> 1) * 32;
    const uint32_t smb = smem_u32(sm);

    const int8_t* Aq1 = qk ? g_kq1 : g_qq1;
    const int8_t* Aq2 = qk ? g_kq2 : g_qq2;
    const int8_t* Bq1 = g_wrq1 + h * RFF * DK;
    const int8_t* Bq2 = g_wrq2 + h * RFF * DK;

    {
        int row = tid >> 2, q = tid & 3;
        uint32_t soff = row * 64 + ((q ^ ((row >> 1) & 3)) << 4);
        size_t ga = (size_t)(m0 + row) * DIMV + h * DK + q * 16;
        *(uint4*)(sm + soff)        = *(const uint4*)(Aq1 + ga);
        *(uint4*)(sm + 4096 + soff) = *(const uint4*)(Aq2 + ga);
    }
    #pragma unroll
    for (int it = 0; it < 2; it++) {
        int t = tid + it * 256;
        int row = t >> 2, q = t & 3;
        uint32_t soff = row * 64 + ((q ^ ((row >> 1) & 3)) << 4);
        size_t gb = (size_t)row * DK + q * 16;
        *(uint4*)(sm + 8192  + soff) = *(const uint4*)(Bq1 + gb);
        *(uint4*)(sm + 16384 + soff) = *(const uint4*)(Bq2 + gb);
    }
    __syncthreads();

    int X[2][4][4], Y[2][4][4];
    #pragma unroll
    for (int i = 0; i < 2; i++)
        #pragma unroll
        for (int j = 0; j < 4; j++)
            #pragma unroll
            for (int e = 0; e < 4; e++) { X[i][j][e] = 0; Y[i][j][e] = 0; }

    #pragma unroll
    for (int ks = 0; ks < 2; ks++) {
        uint32_t a1f[2][4], a2f[2][4], b1f[4][2], b2f[4][2];
        #pragma unroll
        for (int mi = 0; mi < 2; mi++) {
            int row = wm + mi * 16 + (lid & 7) + ((lid >> 3) & 1) * 8;
            int q = ks * 2 + (lid >> 4);
            uint32_t off = row * 64 + ((q ^ ((row >> 1) & 3)) << 4);
            ldmx4(smb + off,        a1f[mi][0], a1f[mi][1], a1f[mi][2], a1f[mi][3]);
            ldmx4(smb + 4096 + off, a2f[mi][0], a2f[mi][1], a2f[mi][2], a2f[mi][3]);
        }
        #pragma unroll
        for (int np = 0; np < 2; np++) {
            int row = wn + np * 16 + (lid >> 4) * 8 + (lid & 7);
            int q = ks * 2 + ((lid >> 3) & 1);
            uint32_t off = row * 64 + ((q ^ ((row >> 1) & 3)) << 4);
            ldmx4(smb + 8192  + off, b1f[2*np][0], b1f[2*np][1], b1f[2*np+1][0], b1f[2*np+1][1]);
            ldmx4(smb + 16384 + off, b2f[2*np][0], b2f[2*np][1], b2f[2*np+1][0], b2f[2*np+1][1]);
        }
        #pragma unroll
        for (int mi = 0; mi < 2; mi++)
            #pragma unroll
            for (int ni = 0; ni < 4; ni++)
                imma16832(X[mi][ni], a1f[mi], b1f[ni]);
        #pragma unroll
        for (int mi = 0; mi < 2; mi++)
            #pragma unroll
            for (int ni = 0; ni < 4; ni++)
                imma16832(Y[mi][ni], a1f[mi], b2f[ni]);
        #pragma unroll
        for (int mi = 0; mi < 2; mi++)
            #pragma unroll
            for (int ni = 0; ni < 4; ni++)
                imma16832(Y[mi][ni], a2f[mi], b1f[ni]);
    }

    __syncthreads();

    int8_t* s1 = (int8_t*)sm;
    int8_t* s2 = (int8_t*)sm + 16384;

    const int g = lid >> 2, c2 = (lid & 3) * 2;
    #pragma unroll
    for (int mi = 0; mi < 2; mi++) {
        #pragma unroll
        for (int ni = 0; ni < 4; ni++) {
            int col = wn + ni * 8 + c2;
            float b0 = brp[h * RFF + col], b1 = brp[h * RFF + col + 1];
            #pragma unroll
            for (int half = 0; half < 2; half++) {
                int nl = wm + mi * 16 + g + half * 8;
                int e0 = half * 2, e1 = half * 2 + 1;
                float p0 = DEQ_P * ((float)X[mi][ni][e0] + (float)Y[mi][ni][e0] * (1.f/256.f)) + b0;
                float p1 = DEQ_P * ((float)X[mi][ni][e1] + (float)Y[mi][ni][e1] * (1.f/256.f)) + b1;
                float s0, c0, s1v, c1;
                __sincosf(p0, &s0, &c0);
                __sincosf(p1, &s1v, &c1);
                int8_t cq1a, cq2a, cq1b, cq2b, sq1a, sq2a, sq1b, sq2b;
                iq2(c0 * 127.f, cq1a, cq2a); iq2(c1 * 127.f, cq1b, cq2b);
                iq2(s0 * 127.f, sq1a, sq2a); iq2(s1v * 127.f, sq1b, sq2b);
                if (qk == 0) {
                    int base = nl * 256;
                    s1[base + col] = cq1a;       s1[base + col + 1] = cq1b;
                    s2[base + col] = cq2a;       s2[base + col + 1] = cq2b;
                    s1[base + RFF + col] = sq1a; s1[base + RFF + col + 1] = sq1b;
                    s2[base + RFF + col] = sq2a; s2[base + RFF + col + 1] = sq2b;
                } else {
                    s1[col * 64 + nl] = cq1a;         s2[col * 64 + nl] = cq2a;
                    s1[(col+1) * 64 + nl] = cq1b;     s2[(col+1) * 64 + nl] = cq2b;
                    s1[(RFF+col) * 64 + nl] = sq1a;   s2[(RFF+col) * 64 + nl] = sq2a;
                    s1[(RFF+col+1) * 64 + nl] = sq1b; s2[(RFF+col+1) * 64 + nl] = sq2b;
                }
            }
        }
    }
    __syncthreads();

    const int b = m0 >> 13, nseq = m0 & 8191;
    const int bh = b * NHEADS + h;
    if (qk == 0) {
        #pragma unroll
        for (int it = 0; it < 4; it++) {
            int idx = tid + it * 256;
            int n = idx >> 4, off = (idx & 15) * 16;
            size_t ga = ((size_t)bh * SEQ + nseq + n) * FEAT + off;
            *(uint4*)&g_qfq1[ga] = *(uint4*)&s1[n * 256 + off];
            *(uint4*)&g_qfq2[ga] = *(uint4*)&s2[n * 256 + off];
        }
    } else {
        #pragma unroll
        for (int it = 0; it < 4; it++) {
            int idx = tid + it * 256;
            int f = idx >> 2, off = (idx & 3) * 16;
            size_t ga = ((size_t)bh * FEAT + f) * SEQ + nseq + off;
            *(uint4*)&g_kfq1[ga] = *(uint4*)&s1[f * 64 + off];
            *(uint4*)&g_kfq2[ga] = *(uint4*)&s2[f * 64 + off];
        }
    }
}

// ---------------- Kv GEMM int8 (split-K 8), M=64 f-rows per CTA, 2 CTAs/SM ----------------
#define KV_STG 20480
#define KV_SMEM (2 * KV_STG)

__global__ __launch_bounds__(256, 2) void gemm_kv()
{
    extern __shared__ __align__(128) char sm[];
    const int tid = threadIdx.x, wid = tid >> 5, lid = tid & 31;
    const int ks = blockIdx.x;
    const int bh = blockIdx.y >> 2, m4 = blockIdx.y & 3;
    const int wm = (wid & 3) * 16, wn = (wid >> 2) * 48;
    const uint32_t smb = smem_u32(sm);

    const int8_t* A1 = g_kfq1 + ((size_t)bh * FEAT + m4 * 64) * SEQ + ks * 1024;
    const int8_t* A2 = g_kfq2 + ((size_t)bh * FEAT + m4 * 64) * SEQ + ks * 1024;
    const int8_t* B1 = g_vq1 + (size_t)bh * NPAD * SEQ + ks * 1024;
    const int8_t* B2 = g_vq2 + (size_t)bh * NPAD * SEQ + ks * 1024;

    int X[6][4], Y[6][4];
    #pragma unroll
    for (int j = 0; j < 6; j++)
        #pragma unroll
        for (int e = 0; e < 4; e++) { X[j][e] = 0; Y[j][e] = 0; }

    auto load_stage = [&](int ci, int s) {
        const int k0 = ci * 64;
        const uint32_t sb = smb + s * KV_STG;
        {
            int row = tid >> 2, q = tid & 3;
            uint32_t soff = row * 64 + ((q ^ ((row >> 1) & 3)) << 4);
            cpa16(sb + soff,        A1 + (size_t)row * SEQ + k0 + q * 16);
            cpa16(sb + 4096 + soff, A2 + (size_t)row * SEQ + k0 + q * 16);
        }
        for (int idx = tid; idx < 384; idx += 256) {
            int row = idx >> 2, q = idx & 3;
            uint32_t soff = row * 64 + ((q ^ ((row >> 1) & 3)) << 4);
            cpa16(sb + 8192  + soff, B1 + (size_t)row * SEQ + k0 + q * 16);
            cpa16(sb + 14336 + soff, B2 + (size_t)row * SEQ + k0 + q * 16);
        }
        cpa_commit();
    };

    load_stage(0, 0);
    #pragma unroll 1
    for (int ci = 0; ci < 16; ci++) {
        const int s = ci & 1;
        if (ci < 15) { load_stage(ci + 1, s ^ 1); asm volatile("cp.async.wait_group 1;"); }
        else         asm volatile("cp.async.wait_group 0;");
        __syncthreads();
        const uint32_t sb = smb + s * KV_STG;
        #pragma unroll
        for (int k2 = 0; k2 < 2; k2++) {
            uint32_t a1f[4], a2f[4], b1f[6][2], b2f[6][2];
            {
                int row = wm + (lid & 7) + ((lid >> 3) & 1) * 8;
                int q = k2 * 2 + (lid >> 4);
                uint32_t off = row * 64 + ((q ^ ((row >> 1) & 3)) << 4);
                ldmx4(sb + off,        a1f[0], a1f[1], a1f[2], a1f[3]);
                ldmx4(sb + 4096 + off, a2f[0], a2f[1], a2f[2], a2f[3]);
            }
            #pragma unroll
            for (int np = 0; np < 3; np++) {
                int row = wn + np * 16 + (lid >> 4) * 8 + (lid & 7);
                int q = k2 * 2 + ((lid >> 3) & 1);
                uint32_t off = row * 64 + ((q ^ ((row >> 1) & 3)) << 4);
                ldmx4(sb + 8192  + off, b1f[2*np][0], b1f[2*np][1], b1f[2*np+1][0], b1f[2*np+1][1]);
                ldmx4(sb + 14336 + off, b2f[2*np][0], b2f[2*np][1], b2f[2*np+1][0], b2f[2*np+1][1]);
            }
            #pragma unroll
            for (int ni = 0; ni < 6; ni++)
                imma16832(X[ni], a1f, b1f[ni]);
            #pragma unroll
            for (int ni = 0; ni < 6; ni++)
                imma16832(Y[ni], a1f, b2f[ni]);
            #pragma unroll
            for (int ni = 0; ni < 6; ni++)
                imma16832(Y[ni], a2f, b1f[ni]);
        }
        __syncthreads();
    }

    const int g = lid >> 2, c2 = (lid & 3) * 2;
    #pragma unroll
    for (int ni = 0; ni < 6; ni++) {
        int rl = wm + g;
        int col = wn + ni * 8 + c2;
        float* dp = g_kvp + (((size_t)ks * BH + bh) * FEAT + m4 * 64 + rl) * NPAD + col;
        float2 o0 = { DEQ_KV * ((float)X[ni][0] + (float)Y[ni][0] * (1.f/256.f)),
                      DEQ_KV * ((float)X[ni][1] + (float)Y[ni][1] * (1.f/256.f)) };
        float2 o1 = { DEQ_KV * ((float)X[ni][2] + (float)Y[ni][2] * (1.f/256.f)),
                      DEQ_KV * ((float)X[ni][3] + (float)Y[ni][3] * (1.f/256.f)) };
        *(float2*)dp = o0;
        *(float2*)(dp + 8 * NPAD) = o1;
    }
}

// ---------------- reduce partials + transpose + per-row quantize ----------------
__global__ __launch_bounds__(256) void kv_reduce_q()
{
    int wid = threadIdx.x >> 5, lid = threadIdx.x & 31;
    int r = blockIdx.x * 8 + wid;
    int bh = r / NPAD, d = r - bh * NPAD;
    float v[8];
    float mx = 0.f;
    #pragma unroll
    for (int i = 0; i < 8; i++) {
        int f = lid + 32 * i;
        float s = 0.f;
        #pragma unroll
        for (int ks = 0; ks < 8; ks++)
            s += g_kvp[(((size_t)ks * BH + bh) * FEAT + f) * NPAD + d];
        v[i] = s;
        mx = fmaxf(mx, fabsf(s));
    }
    #pragma unroll
    for (int o = 16; o; o >>= 1) mx = fmaxf(mx, __shfl_xor_sync(0xFFFFFFFFu, mx, o));
    mx = fmaxf(mx, 1e-20f);
    float inv = 127.f / mx;
    if (lid == 0) g_sd[r] = mx / 127.f;
    #pragma unroll
    for (int i = 0; i < 8; i++) {
        int f = lid + 32 * i;
        int8_t q1, q2;
        iq2(v[i] * inv, q1, q2);
        g_dq1[(size_t)r * FEAT + f] = q1;
        g_dq2[(size_t)r * FEAT + f] = q2;
    }
}

// ---------------- out GEMM int8 -> fp32 af: M=64 per CTA, 2 CTAs/SM ----------------
// 8 warps as 4(m,16) x 2(n,48). Stage: A1 4K | A2 4K | B1 6K | B2 6K = 20KB.
#define OUT_STG 20480
#define OUT_SMEM (2 * OUT_STG + 512)

__global__ __launch_bounds__(256, 2) void gemm_out()
{
    extern __shared__ __align__(128) char sm[];
    const int tid = threadIdx.x, wid = tid >> 5, lid = tid & 31;
    const int n0 = blockIdx.x * 64;
    const int bh = blockIdx.y;
    const int wm = (wid & 3) * 16, wn = (wid >> 2) * 48;
    const uint32_t smb = smem_u32(sm);
    float* sden = (float*)(sm + 2 * OUT_STG);

    const int8_t* A1 = g_qfq1 + ((size_t)bh * SEQ + n0) * FEAT;
    const int8_t* A2 = g_qfq2 + ((size_t)bh * SEQ + n0) * FEAT;
    const int8_t* B1 = g_dq1 + (size_t)bh * NPAD * FEAT;
    const int8_t* B2 = g_dq2 + (size_t)bh * NPAD * FEAT;

    int X[6][4], Y[6][4];
    #pragma unroll
    for (int j = 0; j < 6; j++)
        #pragma unroll
        for (int e = 0; e < 4; e++) { X[j][e] = 0; Y[j][e] = 0; }

    auto load_stage = [&](int ci, int s) {
        const int k0 = ci * 64;
        const uint32_t sb = smb + s * OUT_STG;
        {
            int row = tid >> 2, q = tid & 3;          // A: 64 rows
            uint32_t soff = row * 64 + ((q ^ ((row >> 1) & 3)) << 4);
            cpa16(sb + soff,        A1 + (size_t)row * FEAT + k0 + q * 16);
            cpa16(sb + 4096 + soff, A2 + (size_t)row * FEAT + k0 + q * 16);
        }
        for (int idx = tid; idx < 384; idx += 256) {  // B: 96 rows
            int row = idx >> 2, q = idx & 3;
            uint32_t soff = row * 64 + ((q ^ ((row >> 1) & 3)) << 4);
            cpa16(sb + 8192  + soff, B1 + (size_t)row * FEAT + k0 + q * 16);
            cpa16(sb + 14336 + soff, B2 + (size_t)row * FEAT + k0 + q * 16);
        }
        cpa_commit();
    };

    load_stage(0, 0);
    #pragma unroll 1
    for (int ci = 0; ci < 4; ci++) {
        const int s = ci & 1;
        if (ci < 3) { load_stage(ci + 1, s ^ 1); asm volatile("cp.async.wait_group 1;"); }
        else        asm volatile("cp.async.wait_group 0;");
        __syncthreads();
        const uint32_t sb = smb + s * OUT_STG;
        #pragma unroll
        for (int k2 = 0; k2 < 2; k2++) {
            uint32_t a1f[4], a2f[4], b1f[6][2], b2f[6][2];
            {
                int row = wm + (lid & 7) + ((lid >> 3) & 1) * 8;
                int q = k2 * 2 + (lid >> 4);
                uint32_t off = row * 64 + ((q ^ ((row >> 1) & 3)) << 4);
                ldmx4(sb + off,        a1f[0], a1f[1], a1f[2], a1f[3]);
                ldmx4(sb + 4096 + off, a2f[0], a2f[1], a2f[2], a2f[3]);
            }
            #pragma unroll
            for (int np = 0; np < 3; np++) {
                int row = wn + np * 16 + (lid >> 4) * 8 + (lid & 7);
                int q = k2 * 2 + ((lid >> 3) & 1);
                uint32_t off = row * 64 + ((q ^ ((row >> 1) & 3)) << 4);
                ldmx4(sb + 8192  + off, b1f[2*np][0], b1f[2*np][1], b1f[2*np+1][0], b1f[2*np+1][1]);
                ldmx4(sb + 14336 + off, b2f[2*np][0], b2f[2*np][1], b2f[2*np+1][0], b2f[2*np+1][1]);
            }
            #pragma unroll
            for (int ni = 0; ni < 6; ni++)
                imma16832(X[ni], a1f, b1f[ni]);
            #pragma unroll
            for (int ni = 0; ni < 6; ni++)
                imma16832(Y[ni], a1f, b2f[ni]);
            #pragma unroll
            for (int ni = 0; ni < 6; ni++)
                imma16832(Y[ni], a2f, b1f[ni]);
        }
        __syncthreads();
    }

    const int g = lid >> 2, c2 = (lid & 3) * 2;
    // denominator: col 64 = wn48 + ni2 + c2==0
    if ((wid >> 2) == 1 && (lid & 3) == 0) {
        float sden_s = SF_QF * g_sd[bh * NPAD + 64];
        int rl = wm + g;
        sden[rl]     = sden_s * ((float)X[2][0] + (float)Y[2][0] * (1.f/256.f));
        sden[rl + 8] = sden_s * ((float)X[2][2] + (float)Y[2][2] * (1.f/256.f));
    }
    __syncthreads();

    const int b = bh >> 4, h = bh & 15;
    const int nlim = ((wid >> 2) == 0) ? 6 : 2;
    {
        int rl = wm + g;
        float z0 = 1.f / (sden[rl] + 1e-6f);
        float z1 = 1.f / (sden[rl + 8] + 1e-6f);
        size_t rg0 = (size_t)(b * SEQ + n0 + rl) * DIMV + h * 64;
        size_t rg1 = rg0 + 8 * DIMV;
        for (int ni = 0; ni < nlim; ni++) {
            int col = wn + ni * 8 + c2;
            float sb0 = SF_QF * g_sd[bh * NPAD + col];
            float sb1 = SF_QF * g_sd[bh * NPAD + col + 1];
            float r00 = sb0 * ((float)X[ni][0] + (float)Y[ni][0] * (1.f/256.f));
            float r01 = sb1 * ((float)X[ni][1] + (float)Y[ni][1] * (1.f/256.f));
            float r10 = sb0 * ((float)X[ni][2] + (float)Y[ni][2] * (1.f/256.f));
            float r11 = sb1 * ((float)X[ni][3] + (float)Y[ni][3] * (1.f/256.f));
            float2 o0 = { r00 * z0, r01 * z0 };
            float2 o1 = { r10 * z1, r11 * z1 };
            *(float2*)&g_af[rg0 + col] = o0;
            *(float2*)&g_af[rg1 + col] = o1;
        }
    }
}

// ---------------- launch ----------------
extern "C" void kernel_launch(void* const* d_in, const int* in_sizes, int n_in,
                              void* d_out, int out_size)
{
    const float* x  = (const float*)d_in[0];
    const float* Wq = (const float*)d_in[1];
    const float* Wk = (const float*)d_in[2];
    const float* Wv = (const float*)d_in[3];
    const float* Wp = (const float*)d_in[4];
    const float* bp = (const float*)d_in[5];
    const float* Wr = (const float*)d_in[6];
    const float* br = (const float*)d_in[7];
    float* out = (float*)d_out;

    int8_t *xq1, *xq2, *wq1, *wq2, *pq1, *pq2, *aq1, *aq2;
    float *sx, *sw, *sp, *sa, *af;
    cudaGetSymbolAddress((void**)&xq1, g_xq1); cudaGetSymbolAddress((void**)&xq2, g_xq2);
    cudaGetSymbolAddress((void**)&wq1, g_wq1); cudaGetSymbolAddress((void**)&wq2, g_wq2);
    cudaGetSymbolAddress((void**)&pq1, g_pq1); cudaGetSymbolAddress((void**)&pq2, g_pq2);
    cudaGetSymbolAddress((void**)&aq1, g_aq1); cudaGetSymbolAddress((void**)&aq2, g_aq2);
    cudaGetSymbolAddress((void**)&sx, g_sx);   cudaGetSymbolAddress((void**)&sw, g_sw);
    cudaGetSymbolAddress((void**)&sp, g_sp);   cudaGetSymbolAddress((void**)&sa, g_sa);
    cudaGetSymbolAddress((void**)&af, g_af);

    cudaFuncSetAttribute(gemm_i8<0>, cudaFuncAttributeMaxDynamicSharedMemorySize, IGEMM_SMEM);
    cudaFuncSetAttribute(gemm_i8<3>, cudaFuncAttributeMaxDynamicSharedMemorySize, IGEMM_SMEM);
    cudaFuncSetAttribute(proj_feat, cudaFuncAttributeMaxDynamicSharedMemorySize, PROJ_SMEM);
    cudaFuncSetAttribute(gemm_kv,  cudaFuncAttributeMaxDynamicSharedMemorySize, KV_SMEM);
    cudaFuncSetAttribute(gemm_out, cudaFuncAttributeMaxDynamicSharedMemorySize, OUT_SMEM);

    const int WSZ = DIMV * DIMV;

    quant_rows<<<MROWS / 8, 256>>>(x, xq1, xq2, sx, MROWS);
    quant_rows<<<DIMV / 8, 256>>>(Wq, wq1 + 0 * WSZ, wq2 + 0 * WSZ, sw + 0 * DIMV, DIMV);
    quant_rows<<<DIMV / 8, 256>>>(Wk, wq1 + 1 * WSZ, wq2 + 1 * WSZ, sw + 1 * DIMV, DIMV);
    quant_rows<<<DIMV / 8, 256>>>(Wv, wq1 + 2 * WSZ, wq2 + 2 * WSZ, sw + 2 * DIMV, DIMV);
    quant_rows<<<DIMV / 8, 256>>>(Wp, pq1, pq2, sp, DIMV);
    prep_wrt<<<NHEADS, 256>>>(Wr);
    fill_vq<<<BH * 32, 256>>>();

    gemm_i8<3><<<dim3(3 * DIMV / 64, MROWS / 128), 256, IGEMM_SMEM>>>(
        xq1, xq2, sx, wq1, wq2, sw, nullptr, nullptr);

    proj_feat<<<dim3(MROWS / 64, 32), 256, PROJ_SMEM>>>(br);
    gemm_kv<<<dim3(8, BH * 4), 256, KV_SMEM>>>();
    kv_reduce_q<<<BH * NPAD / 8, 256>>>();
    gemm_out<<<dim3(SEQ / 64, BH), 256, OUT_SMEM>>>();

    quant_rows<<<MROWS / 8, 256>>>(af, aq1, aq2, sa, MROWS);
    gemm_i8<0><<<dim3(DIMV / 64, MROWS / 128), 256, IGEMM_SMEM>>>(
        aq1, aq2, sa, pq1, pq2, sp, bp, out);
}

// round 17
// speedup vs baseline: 1.2147x; 1.0134x over previous
#include <cuda_runtime.h>
#include <cuda_bf16.h>
#include <math.h>
#include <stdint.h>

#define DIMV 1024
#define NHEADS 16
#define DK 64
#define RFF 128
#define FEAT 256
#define BATCH 2
#define SEQ 8192
#define MROWS 16384
#define BH 32
#define NPAD 96
#define INV_SQRT_R 0.08838834764831845f

// ---------------- scratch (device globals) ----------------
__device__ int8_t g_xq1[MROWS*DIMV], g_xq2[MROWS*DIMV];
__device__ float  g_sx[MROWS];
__device__ int8_t g_wq1[3*DIMV*DIMV], g_wq2[3*DIMV*DIMV];
__device__ float  g_sw[3*DIMV];
__device__ int8_t g_pq1[DIMV*DIMV], g_pq2[DIMV*DIMV];
__device__ float  g_sp[DIMV];
__device__ int8_t g_qq1[MROWS*DIMV], g_qq2[MROWS*DIMV];
__device__ int8_t g_kq1[MROWS*DIMV], g_kq2[MROWS*DIMV];
__device__ int8_t g_wrq1[NHEADS*RFF*DK], g_wrq2[NHEADS*RFF*DK];
__device__ int8_t g_vq1[(size_t)BH*NPAD*SEQ], g_vq2[(size_t)BH*NPAD*SEQ];
__device__ int8_t g_qfq1[(size_t)BH*SEQ*FEAT], g_qfq2[(size_t)BH*SEQ*FEAT];
__device__ int8_t g_kfq1[(size_t)BH*FEAT*SEQ], g_kfq2[(size_t)BH*FEAT*SEQ];
__device__ float g_kvp[8*BH*FEAT*NPAD];
__device__ int8_t g_dq1[(size_t)BH*NPAD*FEAT], g_dq2[(size_t)BH*NPAD*FEAT];
__device__ float  g_sd[BH*NPAD];
__device__ float g_af[MROWS*DIMV];
__device__ int8_t g_aq1[MROWS*DIMV], g_aq2[MROWS*DIMV];
__device__ float  g_sa[MROWS];

#define INV_SV (127.f/8.f)
#define SF_QF (INV_SQRT_R/127.f)
#define DEQ_KV ((INV_SQRT_R/127.f)*(8.f/127.f))
#define INV_SQK (127.f/8.f)
#define DEQ_P ((8.f/127.f)*(1.f/127.f))

// ---------------- helpers ----------------
__device__ __forceinline__ uint32_t smem_u32(const void* p) {
    uint32_t a;
    asm("{ .reg .u64 t; cvta.to.shared.u64 t, %1; cvt.u32.u64 %0, t; }" : "=r"(a) : "l"(p));
    return a;
}
__device__ __forceinline__ void cpa16(uint32_t s, const void* g) {
    asm volatile("cp.async.cg.shared.global [%0], [%1], 16;" :: "r"(s), "l"(g));
}
__device__ __forceinline__ void cpa_commit() { asm volatile("cp.async.commit_group;"); }
__device__ __forceinline__ void ldmx4(uint32_t addr, uint32_t& r0, uint32_t& r1, uint32_t& r2, uint32_t& r3) {
    asm volatile("ldmatrix.sync.aligned.m8n8.x4.shared.b16 {%0,%1,%2,%3}, [%4];"
                 : "=r"(r0), "=r"(r1), "=r"(r2), "=r"(r3) : "r"(addr));
}
__device__ __forceinline__ void imma16832(int* d, const uint32_t* a, const uint32_t* b) {
    asm volatile(
        "mma.sync.aligned.m16n8k32.row.col.s32.s8.s8.s32 "
        "{%0,%1,%2,%3}, {%4,%5,%6,%7}, {%8,%9}, {%0,%1,%2,%3};"
        : "+r"(d[0]), "+r"(d[1]), "+r"(d[2]), "+r"(d[3])
        : "r"(a[0]), "r"(a[1]), "r"(a[2]), "r"(a[3]), "r"(b[0]), "r"(b[1]));
}
__device__ __forceinline__ void iq2(float qv, int8_t& q1, int8_t& q2) {
    float a1 = fminf(fmaxf(rintf(qv), -127.f), 127.f);
    float a2 = fminf(fmaxf(rintf((qv - a1) * 256.f), -127.f), 127.f);
    q1 = (int8_t)a1; q2 = (int8_t)a2;
}

// ---------------- per-row 2-digit int8 quantization core ----------------
__device__ __forceinline__ void quant_row_body(
    const float* __restrict__ in, int8_t* __restrict__ q1,
    int8_t* __restrict__ q2, float* __restrict__ sc, int row, int lid)
{
    const float4* r = (const float4*)(in + (size_t)row * 1024);
    float4 v[8];
    float mx = 0.f;
    #pragma unroll
    for (int i = 0; i < 8; i++) {
        v[i] = r[lid + 32 * i];
        mx = fmaxf(mx, fmaxf(fmaxf(fabsf(v[i].x), fabsf(v[i].y)),
                             fmaxf(fabsf(v[i].z), fabsf(v[i].w))));
    }
    #pragma unroll
    for (int o = 16; o; o >>= 1) mx = fmaxf(mx, __shfl_xor_sync(0xFFFFFFFFu, mx, o));
    mx = fmaxf(mx, 1e-20f);
    float inv = 127.f / mx;
    if (lid == 0) sc[row] = mx / 127.f;
    char4* o1 = (char4*)(q1 + (size_t)row * 1024);
    char4* o2 = (char4*)(q2 + (size_t)row * 1024);
    #pragma unroll
    for (int i = 0; i < 8; i++) {
        float qv[4] = { v[i].x * inv, v[i].y * inv, v[i].z * inv, v[i].w * inv };
        int8_t c1[4], c2[4];
        #pragma unroll
        for (int j = 0; j < 4; j++) iq2(qv[j], c1[j], c2[j]);
        o1[lid + 32 * i] = make_char4(c1[0], c1[1], c1[2], c1[3]);
        o2[lid + 32 * i] = make_char4(c2[0], c2[1], c2[2], c2[3]);
    }
}

__global__ __launch_bounds__(256) void quant_rows(
    const float* __restrict__ in, int8_t* __restrict__ q1,
    int8_t* __restrict__ q2, float* __restrict__ sc, int nrows)
{
    int row = blockIdx.x * 8 + (threadIdx.x >> 5);
    if (row >= nrows) return;
    quant_row_body(in, q1, q2, sc, row, threadIdx.x & 31);
}

// ---------------- merged prep: weights quant + WrT + v padding, one launch ----------------
// grid (1024, 6): y in [0,4) -> weight y quant (128 blocks); y==4 -> prep_wrt (16);
// y==5 -> fill_vq (1024 blocks).
__global__ __launch_bounds__(256) void prep_all(
    const float* __restrict__ Wq, const float* __restrict__ Wk,
    const float* __restrict__ Wv, const float* __restrict__ Wp,
    const float* __restrict__ Wr)
{
    const int task = blockIdx.y;
    const int WSZ = DIMV * DIMV;
    if (task < 4) {
        if (blockIdx.x >= 128) return;
        int row = blockIdx.x * 8 + (threadIdx.x >> 5);
        const float* in = (task == 0) ? Wq : (task == 1) ? Wk : (task == 2) ? Wv : Wp;
        int8_t* q1 = (task < 3) ? (g_wq1 + task * WSZ) : g_pq1;
        int8_t* q2 = (task < 3) ? (g_wq2 + task * WSZ) : g_pq2;
        float* sc  = (task < 3) ? (g_sw + task * DIMV) : g_sp;
        quant_row_body(in, q1, q2, sc, row, threadIdx.x & 31);
    } else if (task == 4) {
        if (blockIdx.x >= NHEADS) return;
        int h = blockIdx.x;
        for (int e = threadIdx.x; e < RFF * DK; e += 256) {
            int r = e >> 6, j = e & 63;
            float v = Wr[(size_t)h * DK * RFF + j * RFF + r];
            int8_t q1, q2;
            iq2(v * 127.f, q1, q2);
            g_wrq1[h * RFF * DK + e] = q1;
            g_wrq2[h * RFF * DK + e] = q2;
        }
    } else {
        int bx = blockIdx.x;
        int bh = bx >> 5, dr = 64 + (bx & 31);
        char c1 = (dr == 64) ? 16 : 0;
        char c2 = (dr == 64) ? -32 : 0;
        uint32_t w1 = (uint8_t)c1; w1 |= w1 << 8; w1 |= w1 << 16;
        uint32_t w2 = (uint8_t)c2; w2 |= w2 << 8; w2 |= w2 << 16;
        size_t base = ((size_t)bh * NPAD + dr) * SEQ;
        for (int i = threadIdx.x; i < SEQ / 4; i += 256) {
            ((uint32_t*)(g_vq1 + base))[i] = w1;
            ((uint32_t*)(g_vq2 + base))[i] = w2;
        }
    }
}

// ---------------- int8x2 IMMA GEMM: 128x64 tile, 2 CTAs/SM, 3-stage pipeline ----------------
#define ISTG 24576
#define IGEMM_SMEM (3 * ISTG)

template<int MODE>
__global__ __launch_bounds__(256, 2) void gemm_i8(
    const int8_t* __restrict__ A1, const int8_t* __restrict__ A2, const float* __restrict__ sA,
    const int8_t* __restrict__ B1, const int8_t* __restrict__ B2, const float* __restrict__ sB,
    const float* __restrict__ bias, float* __restrict__ C)
{
    extern __shared__ __align__(128) char sm[];
    const int tid = threadIdx.x, wid = tid >> 5, lid = tid & 31;
    const int m0 = blockIdx.y * 128, n0 = blockIdx.x * 64;
    const int wm = (wid & 3) * 32;
    const int wn = (wid >> 2) * 32;
    const uint32_t smb = smem_u32(sm);

    int X[2][4][4], Y[2][4][4];
    #pragma unroll
    for (int i = 0; i < 2; i++)
        #pragma unroll
        for (int j = 0; j < 4; j++)
            #pragma unroll
            for (int e = 0; e < 4; e++) { X[i][j][e] = 0; Y[i][j][e] = 0; }

    auto load_stage = [&](int ci, int s) {
        const int k0 = ci * 64;
        const uint32_t sb = smb + s * ISTG;
        #pragma unroll
        for (int it = 0; it < 2; it++) {
            int t = tid + it * 256;
            int row = t >> 2, q = t & 3;
            uint32_t soff = row * 64 + ((q ^ ((row >> 1) & 3)) << 4);
            size_t ga = (size_t)(m0 + row) * DIMV + k0 + q * 16;
            cpa16(sb + soff,        A1 + ga);
            cpa16(sb + 8192 + soff, A2 + ga);
        }
        {
            int row = tid >> 2, q = tid & 3;
            uint32_t soff = row * 64 + ((q ^ ((row >> 1) & 3)) << 4);
            size_t gb = (size_t)(n0 + row) * DIMV + k0 + q * 16;
            cpa16(sb + 16384 + soff, B1 + gb);
            cpa16(sb + 20480 + soff, B2 + gb);
        }
        cpa_commit();
    };

    load_stage(0, 0);
    load_stage(1, 1);

    #pragma unroll 1
    for (int ci = 0; ci < 16; ci++) {
        if (ci + 2 < 16) {
            int s2 = ci + 2; s2 -= (s2 / 3) * 3;
            load_stage(ci + 2, s2);
            asm volatile("cp.async.wait_group 2;");
        } else if (ci + 1 < 16) {
            asm volatile("cp.async.wait_group 1;");
        } else {
            asm volatile("cp.async.wait_group 0;");
        }
        __syncthreads();

        int sc = ci; sc -= (sc / 3) * 3;
        const uint32_t sb = smb + sc * ISTG;
        #pragma unroll
        for (int ks = 0; ks < 2; ks++) {
            uint32_t a1f[2][4], a2f[2][4], b1f[4][2], b2f[4][2];
            #pragma unroll
            for (int mi = 0; mi < 2; mi++) {
                int row = wm + mi * 16 + (lid & 7) + ((lid >> 3) & 1) * 8;
                int q = ks * 2 + (lid >> 4);
                uint32_t off = row * 64 + ((q ^ ((row >> 1) & 3)) << 4);
                ldmx4(sb + off,        a1f[mi][0], a1f[mi][1], a1f[mi][2], a1f[mi][3]);
                ldmx4(sb + 8192 + off, a2f[mi][0], a2f[mi][1], a2f[mi][2], a2f[mi][3]);
            }
            #pragma unroll
            for (int np = 0; np < 2; np++) {
                int row = wn + np * 16 + (lid >> 4) * 8 + (lid & 7);
                int q = ks * 2 + ((lid >> 3) & 1);
                uint32_t off = row * 64 + ((q ^ ((row >> 1) & 3)) << 4);
                ldmx4(sb + 16384 + off, b1f[2*np][0], b1f[2*np][1], b1f[2*np+1][0], b1f[2*np+1][1]);
                ldmx4(sb + 20480 + off, b2f[2*np][0], b2f[2*np][1], b2f[2*np+1][0], b2f[2*np+1][1]);
            }
            #pragma unroll
            for (int mi = 0; mi < 2; mi++)
                #pragma unroll
                for (int ni = 0; ni < 4; ni++)
                    imma16832(X[mi][ni], a1f[mi], b1f[ni]);
            #pragma unroll
            for (int mi = 0; mi < 2; mi++)
                #pragma unroll
                for (int ni = 0; ni < 4; ni++)
                    imma16832(Y[mi][ni], a1f[mi], b2f[ni]);
            #pragma unroll
            for (int mi = 0; mi < 2; mi++)
                #pragma unroll
                for (int ni = 0; ni < 4; ni++)
                    imma16832(Y[mi][ni], a2f[mi], b1f[ni]);
        }
        __syncthreads();
    }

    const int g = lid >> 2, c2 = (lid & 3) * 2;
    if (MODE == 0) {
        #pragma unroll
        for (int mi = 0; mi < 2; mi++) {
            int row = m0 + wm + mi * 16 + g;
            float sa0 = sA[row], sa1 = sA[row + 8];
            #pragma unroll
            for (int ni = 0; ni < 4; ni++) {
                int col = n0 + wn + ni * 8 + c2;
                float sb0 = sB[col], sb1 = sB[col + 1];
                float r00 = sa0 * sb0 * ((float)X[mi][ni][0] + (float)Y[mi][ni][0] * (1.f/256.f));
                float r01 = sa0 * sb1 * ((float)X[mi][ni][1] + (float)Y[mi][ni][1] * (1.f/256.f));
                float r10 = sa1 * sb0 * ((float)X[mi][ni][2] + (float)Y[mi][ni][2] * (1.f/256.f));
                float r11 = sa1 * sb1 * ((float)X[mi][ni][3] + (float)Y[mi][ni][3] * (1.f/256.f));
                float b0 = bias ? bias[col] : 0.f;
                float b1 = bias ? bias[col + 1] : 0.f;
                float2 o0 = { r00 + b0, r01 + b1 };
                float2 o1 = { r10 + b0, r11 + b1 };
                *(float2*)&C[(size_t)row * DIMV + col]       = o0;
                *(float2*)&C[(size_t)(row + 8) * DIMV + col] = o1;
            }
        }
    } else {
        int8_t* s1 = (int8_t*)sm;
        int8_t* s2 = (int8_t*)sm + 8192;
        const bool isv = (n0 >= 2048);
        #pragma unroll
        for (int mi = 0; mi < 2; mi++) {
            int rowg = m0 + wm + mi * 16 + g;
            float sa0 = sA[rowg], sa1 = sA[rowg + 8];
            int rl0 = wm + mi * 16 + g, rl1 = rl0 + 8;
            #pragma unroll
            for (int ni = 0; ni < 4; ni++) {
                int cl = wn + ni * 8 + c2;
                float sb0 = sB[n0 + cl], sb1 = sB[n0 + cl + 1];
                float scale = isv ? INV_SV : INV_SQK;
                float r00 = sa0 * sb0 * ((float)X[mi][ni][0] + (float)Y[mi][ni][0] * (1.f/256.f)) * scale;
                float r01 = sa0 * sb1 * ((float)X[mi][ni][1] + (float)Y[mi][ni][1] * (1.f/256.f)) * scale;
                float r10 = sa1 * sb0 * ((float)X[mi][ni][2] + (float)Y[mi][ni][2] * (1.f/256.f)) * scale;
                float r11 = sa1 * sb1 * ((float)X[mi][ni][3] + (float)Y[mi][ni][3] * (1.f/256.f)) * scale;
                int8_t qa1, qa2, qb1, qb2;
                if (!isv) {
                    iq2(r00, qa1, qa2); iq2(r01, qb1, qb2);
                    s1[rl0 * 64 + cl] = qa1; s1[rl0 * 64 + cl + 1] = qb1;
                    s2[rl0 * 64 + cl] = qa2; s2[rl0 * 64 + cl + 1] = qb2;
                    iq2(r10, qa1, qa2); iq2(r11, qb1, qb2);
                    s1[rl1 * 64 + cl] = qa1; s1[rl1 * 64 + cl + 1] = qb1;
                    s2[rl1 * 64 + cl] = qa2; s2[rl1 * 64 + cl + 1] = qb2;
                } else {
                    iq2(r00, qa1, qa2);
                    s1[cl * 128 + rl0] = qa1;       s2[cl * 128 + rl0] = qa2;
                    iq2(r01, qa1, qa2);
                    s1[(cl+1) * 128 + rl0] = qa1;   s2[(cl+1) * 128 + rl0] = qa2;
                    iq2(r10, qa1, qa2);
                    s1[cl * 128 + rl1] = qa1;       s2[cl * 128 + rl1] = qa2;
                    iq2(r11, qa1, qa2);
                    s1[(cl+1) * 128 + rl1] = qa1;   s2[(cl+1) * 128 + rl1] = qa2;
                }
            }
        }
        __syncthreads();
        if (!isv) {
            int8_t* Cq1 = (n0 < 1024) ? g_qq1 : g_kq1;
            int8_t* Cq2 = (n0 < 1024) ? g_qq2 : g_kq2;
            const int cc0 = n0 & 1023;
            #pragma unroll
            for (int it = 0; it < 2; it++) {
                int idx = tid + it * 256;
                int row = idx >> 2, off = (idx & 3) * 16;
                size_t ga = (size_t)(m0 + row) * DIMV + cc0 + off;
                *(uint4*)&Cq1[ga] = *(uint4*)&s1[row * 64 + off];
                *(uint4*)&Cq2[ga] = *(uint4*)&s2[row * 64 + off];
            }
        } else {
            const int b = m0 >> 13, nseq = m0 & 8191;
            #pragma unroll
            for (int it = 0; it < 2; it++) {
                int idx = tid + it * 256;
                int col = idx >> 3, off = (idx & 7) * 16;
                int ccg = (n0 - 2048) + col;
                int hh = ccg >> 6, d0 = ccg & 63;
                size_t ga = (((size_t)(b * NHEADS + hh) * NPAD) + d0) * SEQ + nseq + off;
                *(uint4*)&g_vq1[ga] = *(uint4*)&s1[col * 128 + off];
                *(uint4*)&g_vq2[ga] = *(uint4*)&s2[col * 128 + off];
            }
        }
    }
}

// ---------------- proj + RFF features (int8), M=64 per CTA, 2 CTAs/SM ----------------
#define PROJ_SMEM 32768

__global__ __launch_bounds__(256, 2) void proj_feat(const float* __restrict__ brp)
{
    extern __shared__ __align__(128) char sm[];
    const int tid = threadIdx.x, wid = tid >> 5, lid = tid & 31;
    const int m0 = blockIdx.x * 64;
    const int qk = blockIdx.y >> 4, h = blockIdx.y & 15;
    const int wm = (wid & 1) * 32, wn = (wid >> 1) * 32;
    const uint32_t smb = smem_u32(sm);

    const int8_t* Aq1 = qk ? g_kq1 : g_qq1;
    const int8_t* Aq2 = qk ? g_kq2 : g_qq2;
    const int8_t* Bq1 = g_wrq1 + h * RFF * DK;
    const int8_t* Bq2 = g_wrq2 + h * RFF * DK;

    {
        int row = tid >> 2, q = tid & 3;
        uint32_t soff = row * 64 + ((q ^ ((row >> 1) & 3)) << 4);
        size_t ga = (size_t)(m0 + row) * DIMV + h * DK + q * 16;
        *(uint4*)(sm + soff)        = *(const uint4*)(Aq1 + ga);
        *(uint4*)(sm + 4096 + soff) = *(const uint4*)(Aq2 + ga);
    }
    #pragma unroll
    for (int it = 0; it < 2; it++) {
        int t = tid + it * 256;
        int row = t >> 2, q = t & 3;
        uint32_t soff = row * 64 + ((q ^ ((row >> 1) & 3)) << 4);
        size_t gb = (size_t)row * DK + q * 16;
        *(uint4*)(sm + 8192  + soff) = *(const uint4*)(Bq1 + gb);
        *(uint4*)(sm + 16384 + soff) = *(const uint4*)(Bq2 + gb);
    }
    __syncthreads();

    int X[2][4][4], Y[2][4][4];
    #pragma unroll
    for (int i = 0; i < 2; i++)
        #pragma unroll
        for (int j = 0; j < 4; j++)
            #pragma unroll
            for (int e = 0; e < 4; e++) { X[i][j][e] = 0; Y[i][j][e] = 0; }

    #pragma unroll
    for (int ks = 0; ks < 2; ks++) {
        uint32_t a1f[2][4], a2f[2][4], b1f[4][2], b2f[4][2];
        #pragma unroll
        for (int mi = 0; mi < 2; mi++) {
            int row = wm + mi * 16 + (lid & 7) + ((lid >> 3) & 1) * 8;
            int q = ks * 2 + (lid >> 4);
            uint32_t off = row * 64 + ((q ^ ((row >> 1) & 3)) << 4);
            ldmx4(smb + off,        a1f[mi][0], a1f[mi][1], a1f[mi][2], a1f[mi][3]);
            ldmx4(smb + 4096 + off, a2f[mi][0], a2f[mi][1], a2f[mi][2], a2f[mi][3]);
        }
        #pragma unroll
        for (int np = 0; np < 2; np++) {
            int row = wn + np * 16 + (lid >> 4) * 8 + (lid & 7);
            int q = ks * 2 + ((lid >> 3) & 1);
            uint32_t off = row * 64 + ((q ^ ((row >> 1) & 3)) << 4);
            ldmx4(smb + 8192  + off, b1f[2*np][0], b1f[2*np][1], b1f[2*np+1][0], b1f[2*np+1][1]);
            ldmx4(smb + 16384 + off, b2f[2*np][0], b2f[2*np][1], b2f[2*np+1][0], b2f[2*np+1][1]);
        }
        #pragma unroll
        for (int mi = 0; mi < 2; mi++)
            #pragma unroll
            for (int ni = 0; ni < 4; ni++)
                imma16832(X[mi][ni], a1f[mi], b1f[ni]);
        #pragma unroll
        for (int mi = 0; mi < 2; mi++)
            #pragma unroll
            for (int ni = 0; ni < 4; ni++)
                imma16832(Y[mi][ni], a1f[mi], b2f[ni]);
        #pragma unroll
        for (int mi = 0; mi < 2; mi++)
            #pragma unroll
            for (int ni = 0; ni < 4; ni++)
                imma16832(Y[mi][ni], a2f[mi], b1f[ni]);
    }

    __syncthreads();

    int8_t* s1 = (int8_t*)sm;
    int8_t* s2 = (int8_t*)sm + 16384;

    const int g = lid >> 2, c2 = (lid & 3) * 2;
    #pragma unroll
    for (int mi = 0; mi < 2; mi++) {
        #pragma unroll
        for (int ni = 0; ni < 4; ni++) {
            int col = wn + ni * 8 + c2;
            float b0 = brp[h * RFF + col], b1 = brp[h * RFF + col + 1];
            #pragma unroll
            for (int half = 0; half < 2; half++) {
                int nl = wm + mi * 16 + g + half * 8;
                int e0 = half * 2, e1 = half * 2 + 1;
                float p0 = DEQ_P * ((float)X[mi][ni][e0] + (float)Y[mi][ni][e0] * (1.f/256.f)) + b0;
                float p1 = DEQ_P * ((float)X[mi][ni][e1] + (float)Y[mi][ni][e1] * (1.f/256.f)) + b1;
                float s0, c0, s1v, c1;
                __sincosf(p0, &s0, &c0);
                __sincosf(p1, &s1v, &c1);
                int8_t cq1a, cq2a, cq1b, cq2b, sq1a, sq2a, sq1b, sq2b;
                iq2(c0 * 127.f, cq1a, cq2a); iq2(c1 * 127.f, cq1b, cq2b);
                iq2(s0 * 127.f, sq1a, sq2a); iq2(s1v * 127.f, sq1b, sq2b);
                if (qk == 0) {
                    int base = nl * 256;
                    s1[base + col] = cq1a;       s1[base + col + 1] = cq1b;
                    s2[base + col] = cq2a;       s2[base + col + 1] = cq2b;
                    s1[base + RFF + col] = sq1a; s1[base + RFF + col + 1] = sq1b;
                    s2[base + RFF + col] = sq2a; s2[base + RFF + col + 1] = sq2b;
                } else {
                    s1[col * 64 + nl] = cq1a;         s2[col * 64 + nl] = cq2a;
                    s1[(col+1) * 64 + nl] = cq1b;     s2[(col+1) * 64 + nl] = cq2b;
                    s1[(RFF+col) * 64 + nl] = sq1a;   s2[(RFF+col) * 64 + nl] = sq2a;
                    s1[(RFF+col+1) * 64 + nl] = sq1b; s2[(RFF+col+1) * 64 + nl] = sq2b;
                }
            }
        }
    }
    __syncthreads();

    const int b = m0 >> 13, nseq = m0 & 8191;
    const int bh = b * NHEADS + h;
    if (qk == 0) {
        #pragma unroll
        for (int it = 0; it < 4; it++) {
            int idx = tid + it * 256;
            int n = idx >> 4, off = (idx & 15) * 16;
            size_t ga = ((size_t)bh * SEQ + nseq + n) * FEAT + off;
            *(uint4*)&g_qfq1[ga] = *(uint4*)&s1[n * 256 + off];
            *(uint4*)&g_qfq2[ga] = *(uint4*)&s2[n * 256 + off];
        }
    } else {
        #pragma unroll
        for (int it = 0; it < 4; it++) {
            int idx = tid + it * 256;
            int f = idx >> 2, off = (idx & 3) * 16;
            size_t ga = ((size_t)bh * FEAT + f) * SEQ + nseq + off;
            *(uint4*)&g_kfq1[ga] = *(uint4*)&s1[f * 64 + off];
            *(uint4*)&g_kfq2[ga] = *(uint4*)&s2[f * 64 + off];
        }
    }
}

// ---------------- Kv GEMM int8 (split-K 8), M=64 f-rows per CTA, 2 CTAs/SM ----------------
#define KV_STG 20480
#define KV_SMEM (2 * KV_STG)

__global__ __launch_bounds__(256, 2) void gemm_kv()
{
    extern __shared__ __align__(128) char sm[];
    const int tid = threadIdx.x, wid = tid >> 5, lid = tid & 31;
    const int ks = blockIdx.x;
    const int bh = blockIdx.y >> 2, m4 = blockIdx.y & 3;
    const int wm = (wid & 3) * 16, wn = (wid >> 2) * 48;
    const uint32_t smb = smem_u32(sm);

    const int8_t* A1 = g_kfq1 + ((size_t)bh * FEAT + m4 * 64) * SEQ + ks * 1024;
    const int8_t* A2 = g_kfq2 + ((size_t)bh * FEAT + m4 * 64) * SEQ + ks * 1024;
    const int8_t* B1 = g_vq1 + (size_t)bh * NPAD * SEQ + ks * 1024;
    const int8_t* B2 = g_vq2 + (size_t)bh * NPAD * SEQ + ks * 1024;

    int X[6][4], Y[6][4];
    #pragma unroll
    for (int j = 0; j < 6; j++)
        #pragma unroll
        for (int e = 0; e < 4; e++) { X[j][e] = 0; Y[j][e] = 0; }

    auto load_stage = [&](int ci, int s) {
        const int k0 = ci * 64;
        const uint32_t sb = smb + s * KV_STG;
        {
            int row = tid >> 2, q = tid & 3;
            uint32_t soff = row * 64 + ((q ^ ((row >> 1) & 3)) << 4);
            cpa16(sb + soff,        A1 + (size_t)row * SEQ + k0 + q * 16);
            cpa16(sb + 4096 + soff, A2 + (size_t)row * SEQ + k0 + q * 16);
        }
        for (int idx = tid; idx < 384; idx += 256) {
            int row = idx >> 2, q = idx & 3;
            uint32_t soff = row * 64 + ((q ^ ((row >> 1) & 3)) << 4);
            cpa16(sb + 8192  + soff, B1 + (size_t)row * SEQ + k0 + q * 16);
            cpa16(sb + 14336 + soff, B2 + (size_t)row * SEQ + k0 + q * 16);
        }
        cpa_commit();
    };

    load_stage(0, 0);
    #pragma unroll 1
    for (int ci = 0; ci < 16; ci++) {
        const int s = ci & 1;
        if (ci < 15) { load_stage(ci + 1, s ^ 1); asm volatile("cp.async.wait_group 1;"); }
        else         asm volatile("cp.async.wait_group 0;");
        __syncthreads();
        const uint32_t sb = smb + s * KV_STG;
        #pragma unroll
        for (int k2 = 0; k2 < 2; k2++) {
            uint32_t a1f[4], a2f[4], b1f[6][2], b2f[6][2];
            {
                int row = wm + (lid & 7) + ((lid >> 3) & 1) * 8;
                int q = k2 * 2 + (lid >> 4);
                uint32_t off = row * 64 + ((q ^ ((row >> 1) & 3)) << 4);
                ldmx4(sb + off,        a1f[0], a1f[1], a1f[2], a1f[3]);
                ldmx4(sb + 4096 + off, a2f[0], a2f[1], a2f[2], a2f[3]);
            }
            #pragma unroll
            for (int np = 0; np < 3; np++) {
                int row = wn + np * 16 + (lid >> 4) * 8 + (lid & 7);
                int q = k2 * 2 + ((lid >> 3) & 1);
                uint32_t off = row * 64 + ((q ^ ((row >> 1) & 3)) << 4);
                ldmx4(sb + 8192  + off, b1f[2*np][0], b1f[2*np][1], b1f[2*np+1][0], b1f[2*np+1][1]);
                ldmx4(sb + 14336 + off, b2f[2*np][0], b2f[2*np][1], b2f[2*np+1][0], b2f[2*np+1][1]);
            }
            #pragma unroll
            for (int ni = 0; ni < 6; ni++)
                imma16832(X[ni], a1f, b1f[ni]);
            #pragma unroll
            for (int ni = 0; ni < 6; ni++)
                imma16832(Y[ni], a1f, b2f[ni]);
            #pragma unroll
            for (int ni = 0; ni < 6; ni++)
                imma16832(Y[ni], a2f, b1f[ni]);
        }
        __syncthreads();
    }

    const int g = lid >> 2, c2 = (lid & 3) * 2;
    #pragma unroll
    for (int ni = 0; ni < 6; ni++) {
        int rl = wm + g;
        int col = wn + ni * 8 + c2;
        float* dp = g_kvp + (((size_t)ks * BH + bh) * FEAT + m4 * 64 + rl) * NPAD + col;
        float2 o0 = { DEQ_KV * ((float)X[ni][0] + (float)Y[ni][0] * (1.f/256.f)),
                      DEQ_KV * ((float)X[ni][1] + (float)Y[ni][1] * (1.f/256.f)) };
        float2 o1 = { DEQ_KV * ((float)X[ni][2] + (float)Y[ni][2] * (1.f/256.f)),
                      DEQ_KV * ((float)X[ni][3] + (float)Y[ni][3] * (1.f/256.f)) };
        *(float2*)dp = o0;
        *(float2*)(dp + 8 * NPAD) = o1;
    }
}

// ---------------- reduce partials + transpose + per-row quantize ----------------
__global__ __launch_bounds__(256) void kv_reduce_q()
{
    int wid = threadIdx.x >> 5, lid = threadIdx.x & 31;
    int r = blockIdx.x * 8 + wid;
    int bh = r / NPAD, d = r - bh * NPAD;
    float v[8];
    float mx = 0.f;
    #pragma unroll
    for (int i = 0; i < 8; i++) {
        int f = lid + 32 * i;
        float s = 0.f;
        #pragma unroll
        for (int ks = 0; ks < 8; ks++)
            s += g_kvp[(((size_t)ks * BH + bh) * FEAT + f) * NPAD + d];
        v[i] = s;
        mx = fmaxf(mx, fabsf(s));
    }
    #pragma unroll
    for (int o = 16; o; o >>= 1) mx = fmaxf(mx, __shfl_xor_sync(0xFFFFFFFFu, mx, o));
    mx = fmaxf(mx, 1e-20f);
    float inv = 127.f / mx;
    if (lid == 0) g_sd[r] = mx / 127.f;
    #pragma unroll
    for (int i = 0; i < 8; i++) {
        int f = lid + 32 * i;
        int8_t q1, q2;
        iq2(v[i] * inv, q1, q2);
        g_dq1[(size_t)r * FEAT + f] = q1;
        g_dq2[(size_t)r * FEAT + f] = q2;
    }
}

// ---------------- out GEMM int8 -> fp32 af: M=64 per CTA, 2 CTAs/SM ----------------
#define OUT_STG 20480
#define OUT_SMEM (2 * OUT_STG + 512)

__global__ __launch_bounds__(256, 2) void gemm_out()
{
    extern __shared__ __align__(128) char sm[];
    const int tid = threadIdx.x, wid = tid >> 5, lid = tid & 31;
    const int n0 = blockIdx.x * 64;
    const int bh = blockIdx.y;
    const int wm = (wid & 3) * 16, wn = (wid >> 2) * 48;
    const uint32_t smb = smem_u32(sm);
    float* sden = (float*)(sm + 2 * OUT_STG);

    const int8_t* A1 = g_qfq1 + ((size_t)bh * SEQ + n0) * FEAT;
    const int8_t* A2 = g_qfq2 + ((size_t)bh * SEQ + n0) * FEAT;
    const int8_t* B1 = g_dq1 + (size_t)bh * NPAD * FEAT;
    const int8_t* B2 = g_dq2 + (size_t)bh * NPAD * FEAT;

    int X[6][4], Y[6][4];
    #pragma unroll
    for (int j = 0; j < 6; j++)
        #pragma unroll
        for (int e = 0; e < 4; e++) { X[j][e] = 0; Y[j][e] = 0; }

    auto load_stage = [&](int ci, int s) {
        const int k0 = ci * 64;
        const uint32_t sb = smb + s * OUT_STG;
        {
            int row = tid >> 2, q = tid & 3;
            uint32_t soff = row * 64 + ((q ^ ((row >> 1) & 3)) << 4);
            cpa16(sb + soff,        A1 + (size_t)row * FEAT + k0 + q * 16);
            cpa16(sb + 4096 + soff, A2 + (size_t)row * FEAT + k0 + q * 16);
        }
        for (int idx = tid; idx < 384; idx += 256) {
            int row = idx >> 2, q = idx & 3;
            uint32_t soff = row * 64 + ((q ^ ((row >> 1) & 3)) << 4);
            cpa16(sb + 8192  + soff, B1 + (size_t)row * FEAT + k0 + q * 16);
            cpa16(sb + 14336 + soff, B2 + (size_t)row * FEAT + k0 + q * 16);
        }
        cpa_commit();
    };

    load_stage(0, 0);
    #pragma unroll 1
    for (int ci = 0; ci < 4; ci++) {
        const int s = ci & 1;
        if (ci < 3) { load_stage(ci + 1, s ^ 1); asm volatile("cp.async.wait_group 1;"); }
        else        asm volatile("cp.async.wait_group 0;");
        __syncthreads();
        const uint32_t sb = smb + s * OUT_STG;
        #pragma unroll
        for (int k2 = 0; k2 < 2; k2++) {
            uint32_t a1f[4], a2f[4], b1f[6][2], b2f[6][2];
            {
                int row = wm + (lid & 7) + ((lid >> 3) & 1) * 8;
                int q = k2 * 2 + (lid >> 4);
                uint32_t off = row * 64 + ((q ^ ((row >> 1) & 3)) << 4);
                ldmx4(sb + off,        a1f[0], a1f[1], a1f[2], a1f[3]);
                ldmx4(sb + 4096 + off, a2f[0], a2f[1], a2f[2], a2f[3]);
            }
            #pragma unroll
            for (int np = 0; np < 3; np++) {
                int row = wn + np * 16 + (lid >> 4) * 8 + (lid & 7);
                int q = k2 * 2 + ((lid >> 3) & 1);
                uint32_t off = row * 64 + ((q ^ ((row >> 1) & 3)) << 4);
                ldmx4(sb + 8192  + off, b1f[2*np][0], b1f[2*np][1], b1f[2*np+1][0], b1f[2*np+1][1]);
                ldmx4(sb + 14336 + off, b2f[2*np][0], b2f[2*np][1], b2f[2*np+1][0], b2f[2*np+1][1]);
            }
            #pragma unroll
            for (int ni = 0; ni < 6; ni++)
                imma16832(X[ni], a1f, b1f[ni]);
            #pragma unroll
            for (int ni = 0; ni < 6; ni++)
                imma16832(Y[ni], a1f, b2f[ni]);
            #pragma unroll
            for (int ni = 0; ni < 6; ni++)
                imma16832(Y[ni], a2f, b1f[ni]);
        }
        __syncthreads();
    }

    const int g = lid >> 2, c2 = (lid & 3) * 2;
    if ((wid >> 2) == 1 && (lid & 3) == 0) {
        float sden_s = SF_QF * g_sd[bh * NPAD + 64];
        int rl = wm + g;
        sden[rl]     = sden_s * ((float)X[2][0] + (float)Y[2][0] * (1.f/256.f));
        sden[rl + 8] = sden_s * ((float)X[2][2] + (float)Y[2][2] * (1.f/256.f));
    }
    __syncthreads();

    const int b = bh >> 4, h = bh & 15;
    const int nlim = ((wid >> 2) == 0) ? 6 : 2;
    {
        int rl = wm + g;
        float z0 = 1.f / (sden[rl] + 1e-6f);
        float z1 = 1.f / (sden[rl + 8] + 1e-6f);
        size_t rg0 = (size_t)(b * SEQ + n0 + rl) * DIMV + h * 64;
        size_t rg1 = rg0 + 8 * DIMV;
        for (int ni = 0; ni < nlim; ni++) {
            int col = wn + ni * 8 + c2;
            float sb0 = SF_QF * g_sd[bh * NPAD + col];
            float sb1 = SF_QF * g_sd[bh * NPAD + col + 1];
            float r00 = sb0 * ((float)X[ni][0] + (float)Y[ni][0] * (1.f/256.f));
            float r01 = sb1 * ((float)X[ni][1] + (float)Y[ni][1] * (1.f/256.f));
            float r10 = sb0 * ((float)X[ni][2] + (float)Y[ni][2] * (1.f/256.f));
            float r11 = sb1 * ((float)X[ni][3] + (float)Y[ni][3] * (1.f/256.f));
            float2 o0 = { r00 * z0, r01 * z0 };
            float2 o1 = { r10 * z1, r11 * z1 };
            *(float2*)&g_af[rg0 + col] = o0;
            *(float2*)&g_af[rg1 + col] = o1;
        }
    }
}

// ---------------- launch ----------------
extern "C" void kernel_launch(void* const* d_in, const int* in_sizes, int n_in,
                              void* d_out, int out_size)
{
    const float* x  = (const float*)d_in[0];
    const float* Wq = (const float*)d_in[1];
    const float* Wk = (const float*)d_in[2];
    const float* Wv = (const float*)d_in[3];
    const float* Wp = (const float*)d_in[4];
    const float* bp = (const float*)d_in[5];
    const float* Wr = (const float*)d_in[6];
    const float* br = (const float*)d_in[7];
    float* out = (float*)d_out;

    int8_t *xq1, *xq2, *wq1, *wq2, *pq1, *pq2, *aq1, *aq2;
    float *sx, *sw, *sp, *sa, *af;
    cudaGetSymbolAddress((void**)&xq1, g_xq1); cudaGetSymbolAddress((void**)&xq2, g_xq2);
    cudaGetSymbolAddress((void**)&wq1, g_wq1); cudaGetSymbolAddress((void**)&wq2, g_wq2);
    cudaGetSymbolAddress((void**)&pq1, g_pq1); cudaGetSymbolAddress((void**)&pq2, g_pq2);
    cudaGetSymbolAddress((void**)&aq1, g_aq1); cudaGetSymbolAddress((void**)&aq2, g_aq2);
    cudaGetSymbolAddress((void**)&sx, g_sx);   cudaGetSymbolAddress((void**)&sw, g_sw);
    cudaGetSymbolAddress((void**)&sp, g_sp);   cudaGetSymbolAddress((void**)&sa, g_sa);
    cudaGetSymbolAddress((void**)&af, g_af);

    cudaFuncSetAttribute(gemm_i8<0>, cudaFuncAttributeMaxDynamicSharedMemorySize, IGEMM_SMEM);
    cudaFuncSetAttribute(gemm_i8<3>, cudaFuncAttributeMaxDynamicSharedMemorySize, IGEMM_SMEM);
    cudaFuncSetAttribute(proj_feat, cudaFuncAttributeMaxDynamicSharedMemorySize, PROJ_SMEM);
    cudaFuncSetAttribute(gemm_kv,  cudaFuncAttributeMaxDynamicSharedMemorySize, KV_SMEM);
    cudaFuncSetAttribute(gemm_out, cudaFuncAttributeMaxDynamicSharedMemorySize, OUT_SMEM);

    // one merged prep launch (weights quant x4 + WrT + v padding) + x quant
    quant_rows<<<MROWS / 8, 256>>>(x, xq1, xq2, sx, MROWS);
    prep_all<<<dim3(1024, 6), 256>>>(Wq, Wk, Wv, Wp, Wr);

    gemm_i8<3><<<dim3(3 * DIMV / 64, MROWS / 128), 256, IGEMM_SMEM>>>(
        xq1, xq2, sx, wq1, wq2, sw, nullptr, nullptr);

    proj_feat<<<dim3(MROWS / 64, 32), 256, PROJ_SMEM>>>(br);
    gemm_kv<<<dim3(8, BH * 4), 256, KV_SMEM>>>();
    kv_reduce_q<<<BH * NPAD / 8, 256>>>();
    gemm_out<<<dim3(SEQ / 64, BH), 256, OUT_SMEM>>>();

    quant_rows<<<MROWS / 8, 256>>>(af, aq1, aq2, sa, MROWS);
    gemm_i8<0><<<dim3(DIMV / 64, MROWS / 128), 256, IGEMM_SMEM>>>(
        aq1, aq2, sa, pq1, pq2, sp, bp, out);
}